// round 6
// baseline (speedup 1.0000x reference)
#include <cuda_runtime.h>
#include <cuda_bf16.h>
#include <float.h>
#include <math.h>
#include <stdint.h>

// Problem constants
#define NB 8
#define NN 256
#define NM 512
#define NE 1024
#define NH 32
#define ND 32
#define NEXT 768   // N + M

#define SCALING_F 0.17677669529663687f  // 32^-0.5

// ---------------- device scratch ----------------
// bf16 split staging: activations for out-GEMM A operands.
//   [0 .. 2M)  : xo rows   [2M .. 8M) : vec rows
static __device__ __nv_bfloat16 g_ah[8192LL*1024];
static __device__ __nv_bfloat16 g_al[8192LL*1024];
static __device__ __nv_bfloat16 g_wh[6LL*1024*1024]; // weights hi
static __device__ __nv_bfloat16 g_wl[6LL*1024*1024];
// projections q,k,v,ve in bf16 hi/lo ([b*n, e] row-major)
static __device__ __nv_bfloat16 g_projh[4LL*2048*1024];
static __device__ __nv_bfloat16 g_projl[4LL*2048*1024];
#define PSZ 2097152
#define VOFF 2097152

// ============================================================================
// helpers
// ============================================================================
__device__ __forceinline__ uint32_t smem_u32(const void* p) {
    uint32_t a;
    asm("{ .reg .u64 t; cvta.to.shared.u64 t, %1; cvt.u32.u64 %0, t; }"
        : "=r"(a) : "l"(p));
    return a;
}
#define CP_ASYNC16(sa, ga) \
    asm volatile("cp.async.cg.shared.global [%0], [%1], 16;\n" :: "r"(sa), "l"(ga))
#define CP_COMMIT() asm volatile("cp.async.commit_group;\n" ::: "memory")
#define CP_WAIT(n)  asm volatile("cp.async.wait_group %0;\n" :: "n"(n) : "memory")

__device__ __forceinline__ void mma16816(float* c, const uint32_t* a, const uint32_t* b) {
    asm volatile(
        "mma.sync.aligned.m16n8k16.row.col.f32.bf16.bf16.f32 "
        "{%0,%1,%2,%3}, {%4,%5,%6,%7}, {%8,%9}, {%0,%1,%2,%3};\n"
        : "+f"(c[0]), "+f"(c[1]), "+f"(c[2]), "+f"(c[3])
        : "r"(a[0]), "r"(a[1]), "r"(a[2]), "r"(a[3]), "r"(b[0]), "r"(b[1]));
}
__device__ __forceinline__ void ldsm4(uint32_t& r0, uint32_t& r1, uint32_t& r2,
                                      uint32_t& r3, uint32_t a) {
    asm volatile("ldmatrix.sync.aligned.m8n8.x4.shared.b16 {%0,%1,%2,%3}, [%4];"
                 : "=r"(r0), "=r"(r1), "=r"(r2), "=r"(r3) : "r"(a));
}
__device__ __forceinline__ void split2(float a, float b, uint32_t& hi, uint32_t& lo) {
    __nv_bfloat16 h0 = __float2bfloat16(a);
    __nv_bfloat16 h1 = __float2bfloat16(b);
    __nv_bfloat16 l0 = __float2bfloat16(a - __bfloat162float(h0));
    __nv_bfloat16 l1 = __float2bfloat16(b - __bfloat162float(h1));
    __nv_bfloat162 H; H.x = h0; H.y = h1;
    __nv_bfloat162 L; L.x = l0; L.y = l1;
    hi = *(uint32_t*)&H;
    lo = *(uint32_t*)&L;
}

// ============================================================================
// converters
// ============================================================================
__global__ __launch_bounds__(256) void cvt_split_x(const float* __restrict__ src,
                                                   __nv_bfloat16* __restrict__ hi,
                                                   __nv_bfloat16* __restrict__ lo)
{
    int i = blockIdx.x * 256 + threadIdx.x;
    int r  = i >> 8;
    int e4 = (i & 255) << 2;
    int b = r >> 8, n = r & 255;
    float4 v = *(const float4*)(src + ((long long)n * NB + b) * NE + e4);
    uint32_t h0, l0, h1, l1;
    split2(v.x, v.y, h0, l0);
    split2(v.z, v.w, h1, l1);
    ((uint2*)hi)[i] = make_uint2(h0, h1);
    ((uint2*)lo)[i] = make_uint2(l0, l1);
}

__global__ __launch_bounds__(256) void cvt_split_w(const float* __restrict__ W0,
                                                   const float* __restrict__ W1,
                                                   const float* __restrict__ W2,
                                                   const float* __restrict__ W3,
                                                   const float* __restrict__ W4,
                                                   const float* __restrict__ W5,
                                                   __nv_bfloat16* __restrict__ hi,
                                                   __nv_bfloat16* __restrict__ lo)
{
    int w = blockIdx.y;
    const float* src = (w == 0) ? W0 : (w == 1) ? W1 : (w == 2) ? W2
                     : (w == 3) ? W3 : (w == 4) ? W4 : W5;
    int i = blockIdx.x * 256 + threadIdx.x;
    float4 v = ((const float4*)src)[i];
    uint32_t h0, l0, h1, l1;
    split2(v.x, v.y, h0, l0);
    split2(v.z, v.w, h1, l1);
    size_t o = ((size_t)w << 18) + i;
    ((uint2*)hi)[o] = make_uint2(h0, h1);
    ((uint2*)lo)[o] = make_uint2(l0, l1);
}

// ============================================================================
// Tensor-core split-precision GEMM (unchanged from round 5)
// ============================================================================
#define TILE_ELE 5120
#define STAGE_ELE 20480
#define GSMEM_BYTES 81920

__global__ __launch_bounds__(256, 2) void gemm_mma(const __nv_bfloat16* __restrict__ Ah,
                                                   const __nv_bfloat16* __restrict__ Al,
                                                   const __nv_bfloat16* __restrict__ Bh,
                                                   const __nv_bfloat16* __restrict__ Bl,
                                                   float* __restrict__ C,
                                                   __nv_bfloat16* __restrict__ Ch,
                                                   __nv_bfloat16* __restrict__ Cl,
                                                   float alpha0, int mode)
{
    extern __shared__ __nv_bfloat16 sm[];

    const int tid  = threadIdx.x;
    const int wid  = tid >> 5;
    const int lane = tid & 31;
    const int g    = lane >> 2;
    const int tig  = lane & 3;
    const int row0 = blockIdx.y << 7;
    const int col0 = blockIdx.x << 7;
    const int z    = blockIdx.z;
    Bh += (size_t)z << 20;
    Bl += (size_t)z << 20;
    if (mode == 0) C += (size_t)z << 21;
    else { Ch += (size_t)z << 21; Cl += (size_t)z << 21; }
    const float alpha = (z == 0) ? alpha0 : 1.0f;
    const int wm = (wid & 1) << 6;
    const int wn = (wid >> 1) << 5;

    float acc[4][4][4];
    #pragma unroll
    for (int i = 0; i < 4; i++)
        #pragma unroll
        for (int j = 0; j < 4; j++)
            #pragma unroll
            for (int q = 0; q < 4; q++) acc[i][j][q] = 0.f;

    const uint32_t smbase = smem_u32(sm);
    const uint32_t a_off = ((wm + (lane & 7) + (((lane >> 3) & 1) << 3)) * 40
                            + ((lane >> 4) << 3)) * 2;
    const uint32_t b_off = ((wn + (lane & 7) + ((lane >> 4) << 3)) * 40
                            + (((lane >> 3) & 1) << 3)) * 2;

    #define LOAD_CHUNK(kc, s)                                                     \
    {                                                                             \
        _Pragma("unroll")                                                         \
        for (int t = 0; t < 8; t++) {                                             \
            int u    = tid + (t << 8);                                            \
            int tile = u >> 9;                                                    \
            int r    = (u >> 2) & 127;                                            \
            int cu   = u & 3;                                                     \
            const __nv_bfloat16* gp;                                              \
            if      (tile == 0) gp = Ah + (size_t)(row0 + r) * 1024;              \
            else if (tile == 1) gp = Al + (size_t)(row0 + r) * 1024;              \
            else if (tile == 2) gp = Bh + (size_t)(col0 + r) * 1024;              \
            else                gp = Bl + (size_t)(col0 + r) * 1024;              \
            gp += (kc) * 32 + cu * 8;                                             \
            uint32_t sa = smbase +                                                \
                (uint32_t)(((s) * STAGE_ELE + tile * TILE_ELE + r * 40 + cu * 8) * 2); \
            CP_ASYNC16(sa, gp);                                                   \
        }                                                                         \
    }

    LOAD_CHUNK(0, 0);
    CP_COMMIT();

    for (int kc = 0; kc < 32; kc++) {
        if (kc + 1 < 32) {
            LOAD_CHUNK(kc + 1, (kc + 1) & 1);
            CP_COMMIT();
            CP_WAIT(1);
        } else {
            CP_WAIT(0);
        }
        __syncthreads();

        const uint32_t so2 = (kc & 1) * (STAGE_ELE * 2);
        const uint32_t abase = smbase + so2 + a_off;
        const uint32_t bbase = smbase + so2 + 2 * TILE_ELE * 2 + b_off;

        #pragma unroll
        for (int kk = 0; kk < 2; kk++) {
            const uint32_t kwb = kk << 5;
            uint32_t ah[4][4], al[4][4], bh[4][2], bl[4][2];
            #pragma unroll
            for (int i = 0; i < 4; i++) {
                ldsm4(ah[i][0], ah[i][1], ah[i][2], ah[i][3],
                      abase + i * 1280 + kwb);
                ldsm4(al[i][0], al[i][1], al[i][2], al[i][3],
                      abase + TILE_ELE * 2 + i * 1280 + kwb);
            }
            #pragma unroll
            for (int jp = 0; jp < 2; jp++) {
                ldsm4(bh[2*jp][0], bh[2*jp][1], bh[2*jp+1][0], bh[2*jp+1][1],
                      bbase + jp * 1280 + kwb);
                ldsm4(bl[2*jp][0], bl[2*jp][1], bl[2*jp+1][0], bl[2*jp+1][1],
                      bbase + TILE_ELE * 2 + jp * 1280 + kwb);
            }
            #pragma unroll
            for (int i = 0; i < 4; i++)
                #pragma unroll
                for (int j = 0; j < 4; j++) {
                    mma16816(acc[i][j], ah[i], bh[j]);
                    mma16816(acc[i][j], ah[i], bl[j]);
                    mma16816(acc[i][j], al[i], bh[j]);
                }
        }
        __syncthreads();
    }

    #pragma unroll
    for (int i = 0; i < 4; i++) {
        int row = row0 + wm + (i << 4) + g;
        #pragma unroll
        for (int j = 0; j < 4; j++) {
            int col = col0 + wn + (j << 3) + (tig << 1);
            float v0 = alpha * acc[i][j][0];
            float v1 = alpha * acc[i][j][1];
            float v2 = alpha * acc[i][j][2];
            float v3 = alpha * acc[i][j][3];
            if (mode == 0) {
                *(float2*)(C + (size_t)row * 1024 + col)       = make_float2(v0, v1);
                *(float2*)(C + (size_t)(row + 8) * 1024 + col) = make_float2(v2, v3);
            } else {
                uint32_t h0, l0, h1, l1;
                split2(v0, v1, h0, l0);
                split2(v2, v3, h1, l1);
                *(uint32_t*)(Ch + (size_t)row * 1024 + col)       = h0;
                *(uint32_t*)(Cl + (size_t)row * 1024 + col)       = l0;
                *(uint32_t*)(Ch + (size_t)(row + 8) * 1024 + col) = h1;
                *(uint32_t*)(Cl + (size_t)(row + 8) * 1024 + col) = l1;
            }
        }
    }
}

// ============================================================================
// FUSED attention: QK^T + bias + mask + softmax + PV/vec, 16-row n-tile.
// Probs live entirely in smem. Grid (16, 32, 8), 256 threads, 2 CTA/SM.
//
// smem element map (bf16 units unless noted):
//   [0, 9216)        : 8 A-mats [Ph,Pl,Pdxh,Pdxl,Pdyh,Pdyl,Pdzh,Pdzl], 16x72 each
//   [9216, 18432)    : B-mats [VEh,VEl,Vh,Vl], 32x72 each (d-major)
//   [18432, 23552)   : K tile hi/lo, 64x40 each
//   [23552, 24832)   : Q tile hi/lo, 16x40 each
//   byte 49664 ..    : logits, 16 x 772 fp32
// ============================================================================
#define LST 772
#define AT_A   1152       // 16*72
#define AT_B   2304       // 32*72
#define AT_SMEM 99072

__global__ __launch_bounds__(256, 2) void attn_fused(
    const float* __restrict__ bias,
    const float* __restrict__ pos,
    const float* __restrict__ epos,
    const int*   __restrict__ oidx,
    const unsigned char* __restrict__ pmask,
    const unsigned char* __restrict__ emask,
    const __nv_bfloat16* __restrict__ qh_g,
    const __nv_bfloat16* __restrict__ ql_g,
    const __nv_bfloat16* __restrict__ kh_g,
    const __nv_bfloat16* __restrict__ kl_g,
    const __nv_bfloat16* __restrict__ vh_g,
    const __nv_bfloat16* __restrict__ vl_g,
    const __nv_bfloat16* __restrict__ veh_g,
    const __nv_bfloat16* __restrict__ vel_g,
    __nv_bfloat16* __restrict__ outh,
    __nv_bfloat16* __restrict__ outl)
{
    extern __shared__ __nv_bfloat16 sp[];
    __nv_bfloat16* Bve_h = sp + 9216;
    __nv_bfloat16* Bve_l = sp + 11520;
    __nv_bfloat16* Bv_h  = sp + 13824;
    __nv_bfloat16* Bv_l  = sp + 16128;
    __nv_bfloat16* skh   = sp + 18432;
    __nv_bfloat16* skl   = sp + 20992;
    __nv_bfloat16* sqh   = sp + 23552;
    __nv_bfloat16* sql   = sp + 24192;
    float* logits = (float*)((char*)sp + 49664);

    const int tid  = threadIdx.x;
    const int wid  = tid >> 5;
    const int lane = tid & 31;
    const int g    = lane >> 2;
    const int tig  = lane & 3;
    const int b    = blockIdx.z;
    const int h    = blockIdx.y;
    const int n0   = blockIdx.x << 4;

    // ---- load Q tile (16 x 32 hi/lo) ----
    if (tid < 64) {
        int r = tid >> 2, c = (tid & 3) << 3;
        size_t off = (size_t)(b * NN + n0 + r) * NE + h * ND + c;
        *(uint4*)(sqh + r * 40 + c) = *(const uint4*)(qh_g + off);
        *(uint4*)(sql + r * 40 + c) = *(const uint4*)(ql_g + off);
    }

    // ======================= PASS 1: QK^T -> logits =======================
    const int wc = wid << 3;   // this warp's 8-col strip within an m-tile
    for (int m0 = 0; m0 < NEXT; m0 += 64) {
        __syncthreads();
        {
            int r = tid >> 2, c = (tid & 3) << 3;
            int m = m0 + r;
            int row = (m < NN) ? m : oidx[b * NM + m - NN];
            size_t off = (size_t)(b * NN + row) * NE + h * ND + c;
            *(uint4*)(skh + r * 40 + c) = *(const uint4*)(kh_g + off);
            *(uint4*)(skl + r * 40 + c) = *(const uint4*)(kl_g + off);
        }
        __syncthreads();

        float acc[4] = {0.f, 0.f, 0.f, 0.f};
        #pragma unroll
        for (int kk = 0; kk < 2; kk++) {
            const int kw = kk << 3;
            uint32_t a_h[4], a_l[4], b_h[2], b_l[2];
            a_h[0] = *(const uint32_t*)(sqh + (g    ) * 40 + ((kw + tig    ) << 1));
            a_h[1] = *(const uint32_t*)(sqh + (g + 8) * 40 + ((kw + tig    ) << 1));
            a_h[2] = *(const uint32_t*)(sqh + (g    ) * 40 + ((kw + tig + 4) << 1));
            a_h[3] = *(const uint32_t*)(sqh + (g + 8) * 40 + ((kw + tig + 4) << 1));
            a_l[0] = *(const uint32_t*)(sql + (g    ) * 40 + ((kw + tig    ) << 1));
            a_l[1] = *(const uint32_t*)(sql + (g + 8) * 40 + ((kw + tig    ) << 1));
            a_l[2] = *(const uint32_t*)(sql + (g    ) * 40 + ((kw + tig + 4) << 1));
            a_l[3] = *(const uint32_t*)(sql + (g + 8) * 40 + ((kw + tig + 4) << 1));
            b_h[0] = *(const uint32_t*)(skh + (wc + g) * 40 + ((kw + tig    ) << 1));
            b_h[1] = *(const uint32_t*)(skh + (wc + g) * 40 + ((kw + tig + 4) << 1));
            b_l[0] = *(const uint32_t*)(skl + (wc + g) * 40 + ((kw + tig    ) << 1));
            b_l[1] = *(const uint32_t*)(skl + (wc + g) * 40 + ((kw + tig + 4) << 1));
            mma16816(acc, a_h, b_h);
            mma16816(acc, a_h, b_l);
            mma16816(acc, a_l, b_h);
        }
        int col = m0 + wc + (tig << 1);
        *(float2*)&logits[(g    ) * LST + col] = make_float2(acc[0], acc[1]);
        *(float2*)&logits[(g + 8) * LST + col] = make_float2(acc[2], acc[3]);
    }
    __syncthreads();

    // ======================= softmax (bias + masks) =======================
    #pragma unroll
    for (int rr = wid << 1; rr < (wid << 1) + 2; rr++) {
        int n = n0 + rr;
        bool pn = pmask[b * NN + n] != 0;
        float* lrow = logits + rr * LST;
        long long goff = (((long long)(b * NH + h)) * NN + n) * NEXT;

        float val[24];
        float mx = -FLT_MAX;
        #pragma unroll
        for (int t = 0; t < 24; t++) {
            int m = lane + (t << 5);
            bool fm = (m < NN) ? (pmask[b * NN + m] != 0)
                               : (emask[b * NM + m - NN] != 0);
            float v = lrow[m] + bias[goff + m];
            if (pn || fm) v = -FLT_MAX;
            val[t] = v;
            mx = fmaxf(mx, v);
        }
        #pragma unroll
        for (int o = 16; o > 0; o >>= 1)
            mx = fmaxf(mx, __shfl_xor_sync(0xffffffffu, mx, o));
        float s = 0.f;
        #pragma unroll
        for (int t = 0; t < 24; t++) {
            val[t] = expf(val[t] - mx);
            s += val[t];
        }
        #pragma unroll
        for (int o = 16; o > 0; o >>= 1)
            s += __shfl_xor_sync(0xffffffffu, s, o);
        float inv = 1.f / s;
        #pragma unroll
        for (int t = 0; t < 24; t++)
            lrow[lane + (t << 5)] = val[t] * inv;
    }

    // ======================= PASS 2: PV + vec =============================
    const int o_out = wid >> 1;     // 0=xo, 1=vx, 2=vy, 3=vz
    const int ch    = wid & 1;      // col half (16 dims)

    const uint32_t spb = smem_u32(sp);
    const uint32_t a_off = (((lane & 7) + (((lane >> 3) & 1) << 3)) * 72
                            + ((lane >> 4) << 3)) * 2;
    const uint32_t b_off = (((ch << 4) + (lane & 7) + ((lane >> 4) << 3)) * 72
                            + (((lane >> 3) & 1) << 3)) * 2;
    const uint32_t Auh = spb + (uint32_t)(2 * o_out * AT_A) * 2 + a_off;
    const uint32_t Aul = Auh + AT_A * 2;
    const uint32_t Buh = spb + (uint32_t)((o_out == 0) ? 9216 : 13824) * 2 + b_off;
    const uint32_t Bul = Buh + AT_B * 2;

    float acc2[2][4];
    #pragma unroll
    for (int j = 0; j < 2; j++)
        #pragma unroll
        for (int q = 0; q < 4; q++) acc2[j][q] = 0.f;

    const int p_n  = tid >> 4;          // 0..15
    const int p_mq = tid & 15;          // 0..15 -> 4 m cols each
    const float pxn = pos[(b * NN + n0 + p_n) * 3 + 0];
    const float pyn = pos[(b * NN + n0 + p_n) * 3 + 1];
    const float pzn = pos[(b * NN + n0 + p_n) * 3 + 2];
    const bool  pnn = pmask[b * NN + n0 + p_n] != 0;

    for (int m0 = 0; m0 < NEXT; m0 += 64) {
        __syncthreads();
        // ---- B mats: V / VE transposed [d][m] ----
        {
            int d  = tid & 31;
            int mq = tid >> 5;
            #pragma unroll
            for (int s = 0; s < 8; s++) {
                int m = (mq << 3) + s;
                int mg = m0 + m;
                int row = (mg < NN) ? mg : oidx[b * NM + mg - NN];
                size_t off = (size_t)(b * NN + row) * NE + h * ND + d;
                Bve_h[d * 72 + m] = veh_g[off];
                Bve_l[d * 72 + m] = vel_g[off];
                Bv_h [d * 72 + m] = vh_g [off];
                Bv_l [d * 72 + m] = vl_g [off];
            }
        }
        // ---- A mats: P, P*dx, P*dy, P*dz (hi/lo) ----
        {
            float4 P4 = *(const float4*)(logits + p_n * LST + m0 + (p_mq << 2));
            float P[4] = {P4.x, P4.y, P4.z, P4.w};
            float pdx[4], pdy[4], pdz[4];
            #pragma unroll
            for (int q = 0; q < 4; q++) {
                int m = m0 + (p_mq << 2) + q;
                float ax, ay, az; bool fm;
                if (m < NN) {
                    const float* pp = pos + (b * NN + m) * 3;
                    ax = pp[0]; ay = pp[1]; az = pp[2];
                    fm = pmask[b * NN + m] != 0;
                } else {
                    const float* pp = epos + (b * NM + m - NN) * 3;
                    ax = pp[0]; ay = pp[1]; az = pp[2];
                    fm = emask[b * NM + m - NN] != 0;
                }
                float dx = pxn - ax, dy = pyn - ay, dz = pzn - az;
                float dist = sqrtf(dx * dx + dy * dy + dz * dz);
                if (pnn || fm) dist = 1e6f;
                float inv = 1.f / (dist + 1.f);
                if (pnn) inv = 0.f;
                pdx[q] = P[q] * dx * inv;
                pdy[q] = P[q] * dy * inv;
                pdz[q] = P[q] * dz * inv;
            }
            int base = p_n * 72 + (p_mq << 2);
            uint32_t hi, lo;
            #pragma unroll
            for (int qp = 0; qp < 2; qp++) {
                split2(P[2*qp], P[2*qp+1], hi, lo);
                *(uint32_t*)(sp + 0 * AT_A + base + 2*qp) = hi;
                *(uint32_t*)(sp + 1 * AT_A + base + 2*qp) = lo;
                split2(pdx[2*qp], pdx[2*qp+1], hi, lo);
                *(uint32_t*)(sp + 2 * AT_A + base + 2*qp) = hi;
                *(uint32_t*)(sp + 3 * AT_A + base + 2*qp) = lo;
                split2(pdy[2*qp], pdy[2*qp+1], hi, lo);
                *(uint32_t*)(sp + 4 * AT_A + base + 2*qp) = hi;
                *(uint32_t*)(sp + 5 * AT_A + base + 2*qp) = lo;
                split2(pdz[2*qp], pdz[2*qp+1], hi, lo);
                *(uint32_t*)(sp + 6 * AT_A + base + 2*qp) = hi;
                *(uint32_t*)(sp + 7 * AT_A + base + 2*qp) = lo;
            }
        }
        __syncthreads();

        // ---- MMAs: A(16x64) x B(64x16-half) ----
        #pragma unroll
        for (int kk = 0; kk < 4; kk++) {
            const uint32_t kwb = kk << 5;
            uint32_t ah[4], al[4], bh[2][2], bl[2][2];
            ldsm4(ah[0], ah[1], ah[2], ah[3], Auh + kwb);
            ldsm4(al[0], al[1], al[2], al[3], Aul + kwb);
            ldsm4(bh[0][0], bh[0][1], bh[1][0], bh[1][1], Buh + kwb);
            ldsm4(bl[0][0], bl[0][1], bl[1][0], bl[1][1], Bul + kwb);
            #pragma unroll
            for (int j = 0; j < 2; j++) {
                mma16816(acc2[j], ah, bh[j]);
                mma16816(acc2[j], ah, bl[j]);
                mma16816(acc2[j], al, bh[j]);
            }
        }
    }

    // ---- epilogue: split to bf16 hi/lo, write to out-GEMM A buffers ----
    #pragma unroll
    for (int j = 0; j < 2; j++) {
        int col = h * ND + (ch << 4) + (j << 3) + (tig << 1);
        int nr0 = n0 + g;
        size_t d0, d1;
        if (o_out == 0) {
            d0 = (size_t)(b * NN + nr0) * NE + col;
            d1 = (size_t)(b * NN + nr0 + 8) * NE + col;
        } else {
            d0 = VOFF + ((size_t)(b * NN + nr0) * 3 + (o_out - 1)) * NE + col;
            d1 = VOFF + ((size_t)(b * NN + nr0 + 8) * 3 + (o_out - 1)) * NE + col;
        }
        uint32_t hi, lo;
        split2(acc2[j][0], acc2[j][1], hi, lo);
        *(uint32_t*)(outh + d0) = hi; *(uint32_t*)(outl + d0) = lo;
        split2(acc2[j][2], acc2[j][3], hi, lo);
        *(uint32_t*)(outh + d1) = hi; *(uint32_t*)(outl + d1) = lo;
    }
}

// ============================================================================
// launch
// ============================================================================
extern "C" void kernel_launch(void* const* d_in, const int* in_sizes, int n_in,
                              void* d_out, int out_size)
{
    const float* x    = (const float*)d_in[0];
    const float* pos  = (const float*)d_in[1];
    const float* epos = (const float*)d_in[2];
    const float* bias = (const float*)d_in[3];
    const unsigned char* pmask = (const unsigned char*)d_in[4];
    const unsigned char* emask = (const unsigned char*)d_in[5];
    const int*   oidx = (const int*)d_in[6];
    const float* Wq   = (const float*)d_in[7];
    const float* Wk   = (const float*)d_in[8];
    const float* Wv   = (const float*)d_in[9];
    const float* Wve  = (const float*)d_in[10];
    const float* Wo   = (const float*)d_in[11];
    const float* Woe  = (const float*)d_in[12];
    float* out = (float*)d_out;

    __nv_bfloat16 *ah, *al, *wh, *wl, *ph, *pl;
    cudaGetSymbolAddress((void**)&ah,  g_ah);
    cudaGetSymbolAddress((void**)&al,  g_al);
    cudaGetSymbolAddress((void**)&wh,  g_wh);
    cudaGetSymbolAddress((void**)&wl,  g_wl);
    cudaGetSymbolAddress((void**)&ph,  g_projh);
    cudaGetSymbolAddress((void**)&pl,  g_projl);

    cudaFuncSetAttribute(gemm_mma,   cudaFuncAttributeMaxDynamicSharedMemorySize, GSMEM_BYTES);
    cudaFuncSetAttribute(attn_fused, cudaFuncAttributeMaxDynamicSharedMemorySize, AT_SMEM);

    const int WSZ = 1024 * 1024;

    // 1) converters
    cvt_split_x<<<2048, 256>>>(x, ah, al);
    cvt_split_w<<<dim3(1024, 6), 256>>>(Wq, Wk, Wv, Wve, Woe, Wo, wh, wl);

    // 2) projections -> bf16 hi/lo (mode 1)
    gemm_mma<<<dim3(8, 16, 4), 256, GSMEM_BYTES>>>(ah, al, wh, wl,
                                                   nullptr, ph, pl, SCALING_F, 1);

    // 3) fused attention (QK + softmax + PV/vec)
    attn_fused<<<dim3(16, 32, 8), 256, AT_SMEM>>>(bias, pos, epos, oidx, pmask, emask,
                                                  ph, pl,                   // q
                                                  ph + PSZ, pl + PSZ,       // k
                                                  ph + 2*PSZ, pl + 2*PSZ,   // v
                                                  ph + 3*PSZ, pl + 3*PSZ,   // ve
                                                  ah, al);

    // 4) output GEMMs
    gemm_mma<<<dim3(8, 16, 1), 256, GSMEM_BYTES>>>(ah, al, wh + 4*WSZ, wl + 4*WSZ,
                                                   out, nullptr, nullptr, 1.0f, 0);
    gemm_mma<<<dim3(8, 48, 1), 256, GSMEM_BYTES>>>(ah + VOFF, al + VOFF,
                                                   wh + 5*WSZ, wl + 5*WSZ,
                                                   out + NB*NN*NE, nullptr, nullptr, 1.0f, 0);
}

// round 7
// speedup vs baseline: 1.1865x; 1.1865x over previous
#include <cuda_runtime.h>
#include <cuda_bf16.h>
#include <float.h>
#include <math.h>
#include <stdint.h>

// Problem constants
#define NB 8
#define NN 256
#define NM 512
#define NE 1024
#define NH 32
#define ND 32
#define NEXT 768   // N + M

#define SCALING_F 0.17677669529663687f  // 32^-0.5

// ---------------- device scratch ----------------
static __device__ float g_attn[(long long)NB*NH*NN*NEXT];   // probs (fp32)
// bf16 split staging: activations for out-GEMM A operands.
//   [0 .. 2M)  : xo rows   [2M .. 8M) : vec rows
static __device__ __nv_bfloat16 g_ah[8192LL*1024];
static __device__ __nv_bfloat16 g_al[8192LL*1024];
static __device__ __nv_bfloat16 g_wh[6LL*1024*1024]; // weights hi
static __device__ __nv_bfloat16 g_wl[6LL*1024*1024];
// projections q,k,v,ve in bf16 hi/lo ([b*n, e] row-major)
static __device__ __nv_bfloat16 g_projh[4LL*2048*1024];
static __device__ __nv_bfloat16 g_projl[4LL*2048*1024];
#define PSZ 2097152
#define VOFF 2097152

// ============================================================================
// helpers
// ============================================================================
__device__ __forceinline__ uint32_t smem_u32(const void* p) {
    uint32_t a;
    asm("{ .reg .u64 t; cvta.to.shared.u64 t, %1; cvt.u32.u64 %0, t; }"
        : "=r"(a) : "l"(p));
    return a;
}
#define CP_ASYNC16(sa, ga) \
    asm volatile("cp.async.cg.shared.global [%0], [%1], 16;\n" :: "r"(sa), "l"(ga))
#define CP_COMMIT() asm volatile("cp.async.commit_group;\n" ::: "memory")
#define CP_WAIT(n)  asm volatile("cp.async.wait_group %0;\n" :: "n"(n) : "memory")

__device__ __forceinline__ void mma16816(float* c, const uint32_t* a, const uint32_t* b) {
    asm volatile(
        "mma.sync.aligned.m16n8k16.row.col.f32.bf16.bf16.f32 "
        "{%0,%1,%2,%3}, {%4,%5,%6,%7}, {%8,%9}, {%0,%1,%2,%3};\n"
        : "+f"(c[0]), "+f"(c[1]), "+f"(c[2]), "+f"(c[3])
        : "r"(a[0]), "r"(a[1]), "r"(a[2]), "r"(a[3]), "r"(b[0]), "r"(b[1]));
}
__device__ __forceinline__ void ldsm4(uint32_t& r0, uint32_t& r1, uint32_t& r2,
                                      uint32_t& r3, uint32_t a) {
    asm volatile("ldmatrix.sync.aligned.m8n8.x4.shared.b16 {%0,%1,%2,%3}, [%4];"
                 : "=r"(r0), "=r"(r1), "=r"(r2), "=r"(r3) : "r"(a));
}
__device__ __forceinline__ void split2(float a, float b, uint32_t& hi, uint32_t& lo) {
    __nv_bfloat16 h0 = __float2bfloat16(a);
    __nv_bfloat16 h1 = __float2bfloat16(b);
    __nv_bfloat16 l0 = __float2bfloat16(a - __bfloat162float(h0));
    __nv_bfloat16 l1 = __float2bfloat16(b - __bfloat162float(h1));
    __nv_bfloat162 H; H.x = h0; H.y = h1;
    __nv_bfloat162 L; L.x = l0; L.y = l1;
    hi = *(uint32_t*)&H;
    lo = *(uint32_t*)&L;
}

// ============================================================================
// converters
// ============================================================================
__global__ __launch_bounds__(256) void cvt_split_x(const float* __restrict__ src,
                                                   __nv_bfloat16* __restrict__ hi,
                                                   __nv_bfloat16* __restrict__ lo)
{
    int i = blockIdx.x * 256 + threadIdx.x;
    int r  = i >> 8;
    int e4 = (i & 255) << 2;
    int b = r >> 8, n = r & 255;
    float4 v = *(const float4*)(src + ((long long)n * NB + b) * NE + e4);
    uint32_t h0, l0, h1, l1;
    split2(v.x, v.y, h0, l0);
    split2(v.z, v.w, h1, l1);
    ((uint2*)hi)[i] = make_uint2(h0, h1);
    ((uint2*)lo)[i] = make_uint2(l0, l1);
}

__global__ __launch_bounds__(256) void cvt_split_w(const float* __restrict__ W0,
                                                   const float* __restrict__ W1,
                                                   const float* __restrict__ W2,
                                                   const float* __restrict__ W3,
                                                   const float* __restrict__ W4,
                                                   const float* __restrict__ W5,
                                                   __nv_bfloat16* __restrict__ hi,
                                                   __nv_bfloat16* __restrict__ lo)
{
    int w = blockIdx.y;
    const float* src = (w == 0) ? W0 : (w == 1) ? W1 : (w == 2) ? W2
                     : (w == 3) ? W3 : (w == 4) ? W4 : W5;
    int i = blockIdx.x * 256 + threadIdx.x;
    float4 v = ((const float4*)src)[i];
    uint32_t h0, l0, h1, l1;
    split2(v.x, v.y, h0, l0);
    split2(v.z, v.w, h1, l1);
    size_t o = ((size_t)w << 18) + i;
    ((uint2*)hi)[o] = make_uint2(h0, h1);
    ((uint2*)lo)[o] = make_uint2(l0, l1);
}

// ============================================================================
// Tensor-core split-precision GEMM: C = alpha * A @ W^T
// ============================================================================
#define TILE_ELE 5120
#define STAGE_ELE 20480
#define GSMEM_BYTES 81920

__global__ __launch_bounds__(256, 2) void gemm_mma(const __nv_bfloat16* __restrict__ Ah,
                                                   const __nv_bfloat16* __restrict__ Al,
                                                   const __nv_bfloat16* __restrict__ Bh,
                                                   const __nv_bfloat16* __restrict__ Bl,
                                                   float* __restrict__ C,
                                                   __nv_bfloat16* __restrict__ Ch,
                                                   __nv_bfloat16* __restrict__ Cl,
                                                   float alpha0, int mode)
{
    extern __shared__ __nv_bfloat16 sm[];

    const int tid  = threadIdx.x;
    const int wid  = tid >> 5;
    const int lane = tid & 31;
    const int g    = lane >> 2;
    const int tig  = lane & 3;
    const int row0 = blockIdx.y << 7;
    const int col0 = blockIdx.x << 7;
    const int z    = blockIdx.z;
    Bh += (size_t)z << 20;
    Bl += (size_t)z << 20;
    if (mode == 0) C += (size_t)z << 21;
    else { Ch += (size_t)z << 21; Cl += (size_t)z << 21; }
    const float alpha = (z == 0) ? alpha0 : 1.0f;
    const int wm = (wid & 1) << 6;
    const int wn = (wid >> 1) << 5;

    float acc[4][4][4];
    #pragma unroll
    for (int i = 0; i < 4; i++)
        #pragma unroll
        for (int j = 0; j < 4; j++)
            #pragma unroll
            for (int q = 0; q < 4; q++) acc[i][j][q] = 0.f;

    const uint32_t smbase = smem_u32(sm);
    const uint32_t a_off = ((wm + (lane & 7) + (((lane >> 3) & 1) << 3)) * 40
                            + ((lane >> 4) << 3)) * 2;
    const uint32_t b_off = ((wn + (lane & 7) + ((lane >> 4) << 3)) * 40
                            + (((lane >> 3) & 1) << 3)) * 2;

    #define LOAD_CHUNK(kc, s)                                                     \
    {                                                                             \
        _Pragma("unroll")                                                         \
        for (int t = 0; t < 8; t++) {                                             \
            int u    = tid + (t << 8);                                            \
            int tile = u >> 9;                                                    \
            int r    = (u >> 2) & 127;                                            \
            int cu   = u & 3;                                                     \
            const __nv_bfloat16* gp;                                              \
            if      (tile == 0) gp = Ah + (size_t)(row0 + r) * 1024;              \
            else if (tile == 1) gp = Al + (size_t)(row0 + r) * 1024;              \
            else if (tile == 2) gp = Bh + (size_t)(col0 + r) * 1024;              \
            else                gp = Bl + (size_t)(col0 + r) * 1024;              \
            gp += (kc) * 32 + cu * 8;                                             \
            uint32_t sa = smbase +                                                \
                (uint32_t)(((s) * STAGE_ELE + tile * TILE_ELE + r * 40 + cu * 8) * 2); \
            CP_ASYNC16(sa, gp);                                                   \
        }                                                                         \
    }

    LOAD_CHUNK(0, 0);
    CP_COMMIT();

    for (int kc = 0; kc < 32; kc++) {
        if (kc + 1 < 32) {
            LOAD_CHUNK(kc + 1, (kc + 1) & 1);
            CP_COMMIT();
            CP_WAIT(1);
        } else {
            CP_WAIT(0);
        }
        __syncthreads();

        const uint32_t so2 = (kc & 1) * (STAGE_ELE * 2);
        const uint32_t abase = smbase + so2 + a_off;
        const uint32_t bbase = smbase + so2 + 2 * TILE_ELE * 2 + b_off;

        #pragma unroll
        for (int kk = 0; kk < 2; kk++) {
            const uint32_t kwb = kk << 5;
            uint32_t ah[4][4], al[4][4], bh[4][2], bl[4][2];
            #pragma unroll
            for (int i = 0; i < 4; i++) {
                ldsm4(ah[i][0], ah[i][1], ah[i][2], ah[i][3],
                      abase + i * 1280 + kwb);
                ldsm4(al[i][0], al[i][1], al[i][2], al[i][3],
                      abase + TILE_ELE * 2 + i * 1280 + kwb);
            }
            #pragma unroll
            for (int jp = 0; jp < 2; jp++) {
                ldsm4(bh[2*jp][0], bh[2*jp][1], bh[2*jp+1][0], bh[2*jp+1][1],
                      bbase + jp * 1280 + kwb);
                ldsm4(bl[2*jp][0], bl[2*jp][1], bl[2*jp+1][0], bl[2*jp+1][1],
                      bbase + TILE_ELE * 2 + jp * 1280 + kwb);
            }
            #pragma unroll
            for (int i = 0; i < 4; i++)
                #pragma unroll
                for (int j = 0; j < 4; j++) {
                    mma16816(acc[i][j], ah[i], bh[j]);
                    mma16816(acc[i][j], ah[i], bl[j]);
                    mma16816(acc[i][j], al[i], bh[j]);
                }
        }
        __syncthreads();
    }

    #pragma unroll
    for (int i = 0; i < 4; i++) {
        int row = row0 + wm + (i << 4) + g;
        #pragma unroll
        for (int j = 0; j < 4; j++) {
            int col = col0 + wn + (j << 3) + (tig << 1);
            float v0 = alpha * acc[i][j][0];
            float v1 = alpha * acc[i][j][1];
            float v2 = alpha * acc[i][j][2];
            float v3 = alpha * acc[i][j][3];
            if (mode == 0) {
                *(float2*)(C + (size_t)row * 1024 + col)       = make_float2(v0, v1);
                *(float2*)(C + (size_t)(row + 8) * 1024 + col) = make_float2(v2, v3);
            } else {
                uint32_t h0, l0, h1, l1;
                split2(v0, v1, h0, l0);
                split2(v2, v3, h1, l1);
                *(uint32_t*)(Ch + (size_t)row * 1024 + col)       = h0;
                *(uint32_t*)(Cl + (size_t)row * 1024 + col)       = l0;
                *(uint32_t*)(Ch + (size_t)(row + 8) * 1024 + col) = h1;
                *(uint32_t*)(Cl + (size_t)(row + 8) * 1024 + col) = l1;
            }
        }
    }
}

// ============================================================================
// Fused QK^T + bias + mask + softmax. 32-row n-tile -> 111.5 KB smem,
// 2 CTAs/SM (occupancy fix vs 64-row version).
// smem: sqh/sql 32x40, skh/skl 64x40 (bf16), logits 32x772 fp32.
// ============================================================================
#define LSTRIDE 772
#define QK_SMEM 114176   // 7680*2 + 32*772*4

__global__ __launch_bounds__(256, 2) void qk_softmax(const float* __restrict__ bias,
                                                  const int*   __restrict__ oidx,
                                                  const unsigned char* __restrict__ pmask,
                                                  const unsigned char* __restrict__ emask,
                                                  const __nv_bfloat16* __restrict__ qh_g,
                                                  const __nv_bfloat16* __restrict__ ql_g,
                                                  const __nv_bfloat16* __restrict__ kh_g,
                                                  const __nv_bfloat16* __restrict__ kl_g)
{
    extern __shared__ char sraw[];
    __nv_bfloat16* sqh = (__nv_bfloat16*)sraw;
    __nv_bfloat16* sql = sqh + 1280;
    __nv_bfloat16* skh = sqh + 2560;
    __nv_bfloat16* skl = sqh + 5120;
    float* logits = (float*)(sraw + 15360);

    const int tid  = threadIdx.x;
    const int wid  = tid >> 5;
    const int lane = tid & 31;
    const int g    = lane >> 2;
    const int tig  = lane & 3;
    const int bh   = blockIdx.y;
    const int b    = bh >> 5;
    const int h    = bh & 31;
    const int n0   = blockIdx.x << 5;   // 32-row tile

    // load q tile (32 x 32, hi/lo)
    if (tid < 128) {
        int r = tid >> 2, c = (tid & 3) << 3;
        size_t off = (size_t)(b * NN + n0 + r) * NE + h * ND + c;
        *(uint4*)(sqh + r * 40 + c) = *(const uint4*)(qh_g + off);
        *(uint4*)(sql + r * 40 + c) = *(const uint4*)(ql_g + off);
    }

    const int wn = (wid & 1) << 4;    // 0/16 row strip
    const int wm = (wid >> 1) << 4;   // 0,16,32,48 col strip

    for (int m0 = 0; m0 < NEXT; m0 += 64) {
        __syncthreads();
        // load k tile 64x32 (gathered)
        {
            int r = tid >> 2, c = (tid & 3) << 3;
            int m = m0 + r;
            int row = (m < NN) ? m : oidx[b * NM + m - NN];
            size_t off = (size_t)(b * NN + row) * NE + h * ND + c;
            *(uint4*)(skh + r * 40 + c) = *(const uint4*)(kh_g + off);
            *(uint4*)(skl + r * 40 + c) = *(const uint4*)(kl_g + off);
        }
        __syncthreads();

        float acc[2][4];
        #pragma unroll
        for (int j = 0; j < 2; j++)
            #pragma unroll
            for (int q = 0; q < 4; q++) acc[j][q] = 0.f;

        #pragma unroll
        for (int kk = 0; kk < 2; kk++) {
            const int kw = kk << 3;
            uint32_t a_h[4], a_l[4], bhf[2][2], blf[2][2];
            {
                int rA = wn + g;
                a_h[0] = *(const uint32_t*)(sqh + (rA    ) * 40 + ((kw + tig    ) << 1));
                a_h[1] = *(const uint32_t*)(sqh + (rA + 8) * 40 + ((kw + tig    ) << 1));
                a_h[2] = *(const uint32_t*)(sqh + (rA    ) * 40 + ((kw + tig + 4) << 1));
                a_h[3] = *(const uint32_t*)(sqh + (rA + 8) * 40 + ((kw + tig + 4) << 1));
                a_l[0] = *(const uint32_t*)(sql + (rA    ) * 40 + ((kw + tig    ) << 1));
                a_l[1] = *(const uint32_t*)(sql + (rA + 8) * 40 + ((kw + tig    ) << 1));
                a_l[2] = *(const uint32_t*)(sql + (rA    ) * 40 + ((kw + tig + 4) << 1));
                a_l[3] = *(const uint32_t*)(sql + (rA + 8) * 40 + ((kw + tig + 4) << 1));
            }
            #pragma unroll
            for (int j = 0; j < 2; j++) {
                int rB = wm + (j << 3) + g;
                bhf[j][0] = *(const uint32_t*)(skh + rB * 40 + ((kw + tig    ) << 1));
                bhf[j][1] = *(const uint32_t*)(skh + rB * 40 + ((kw + tig + 4) << 1));
                blf[j][0] = *(const uint32_t*)(skl + rB * 40 + ((kw + tig    ) << 1));
                blf[j][1] = *(const uint32_t*)(skl + rB * 40 + ((kw + tig + 4) << 1));
            }
            #pragma unroll
            for (int j = 0; j < 2; j++) {
                mma16816(acc[j], a_h, bhf[j]);
                mma16816(acc[j], a_h, blf[j]);
                mma16816(acc[j], a_l, bhf[j]);
            }
        }

        #pragma unroll
        for (int j = 0; j < 2; j++) {
            int col = m0 + wm + (j << 3) + (tig << 1);
            int row = wn + g;
            *(float2*)&logits[row * LSTRIDE + col]       = make_float2(acc[j][0], acc[j][1]);
            *(float2*)&logits[(row + 8) * LSTRIDE + col] = make_float2(acc[j][2], acc[j][3]);
        }
    }
    __syncthreads();

    // softmax: warp handles rows wid, wid+8, wid+16, wid+24
    for (int rr = wid; rr < 32; rr += 8) {
        int n = n0 + rr;
        bool pn = pmask[b * NN + n] != 0;
        const float* lrow = logits + rr * LSTRIDE;
        long long goff = (((long long)(b * NH + h)) * NN + n) * NEXT;

        float val[24];
        float mx = -FLT_MAX;
        #pragma unroll
        for (int t = 0; t < 24; t++) {
            int m = lane + (t << 5);
            bool fm = (m < NN) ? (pmask[b * NN + m] != 0)
                               : (emask[b * NM + m - NN] != 0);
            float v = lrow[m] + bias[goff + m];
            if (pn || fm) v = -FLT_MAX;
            val[t] = v;
            mx = fmaxf(mx, v);
        }
        #pragma unroll
        for (int o = 16; o > 0; o >>= 1)
            mx = fmaxf(mx, __shfl_xor_sync(0xffffffffu, mx, o));
        float s = 0.f;
        #pragma unroll
        for (int t = 0; t < 24; t++) {
            val[t] = expf(val[t] - mx);
            s += val[t];
        }
        #pragma unroll
        for (int o = 16; o > 0; o >>= 1)
            s += __shfl_xor_sync(0xffffffffu, s, o);
        float inv = 1.f / s;
        #pragma unroll
        for (int t = 0; t < 24; t++)
            g_attn[goff + lane + (t << 5)] = val[t] * inv;
    }
}

// ============================================================================
// Fused PV + vec with split-bf16 HMMA + ldmatrix; epilogue writes bf16 hi/lo.
// ============================================================================
#define PV_A    4608
#define PV_VB   36864
#define PV_B    2304
#define PV_SMEM 92160

__global__ __launch_bounds__(256, 2) void pv_mma(const float* __restrict__ pos,
                                                 const float* __restrict__ epos,
                                                 const int*   __restrict__ oidx,
                                                 const unsigned char* __restrict__ pmask,
                                                 const unsigned char* __restrict__ emask,
                                                 const __nv_bfloat16* __restrict__ vh_g,
                                                 const __nv_bfloat16* __restrict__ vl_g,
                                                 const __nv_bfloat16* __restrict__ veh_g,
                                                 const __nv_bfloat16* __restrict__ vel_g,
                                                 __nv_bfloat16* __restrict__ outh,
                                                 __nv_bfloat16* __restrict__ outl)
{
    extern __shared__ __nv_bfloat16 sp[];

    const int tid  = threadIdx.x;
    const int wid  = tid >> 5;
    const int lane = tid & 31;
    const int g    = lane >> 2;
    const int tig  = lane & 3;
    const int b    = blockIdx.z;
    const int h    = blockIdx.y;
    const int n0   = blockIdx.x << 6;

    const int rowblk = (wid & 3) << 4;
    const int pair   = wid >> 2;

    __nv_bfloat16* VEh = sp + PV_VB;
    __nv_bfloat16* VEl = VEh + PV_B;
    __nv_bfloat16* Vh  = VEh + 2 * PV_B;
    __nv_bfloat16* Vl  = VEh + 3 * PV_B;

    const uint32_t spb = smem_u32(sp);
    const uint32_t a_offp = ((rowblk + (lane & 7) + (((lane >> 3) & 1) << 3)) * 72
                             + ((lane >> 4) << 3)) * 2;
    const uint32_t b_offp = (((lane & 7) + ((lane >> 4) << 3)) * 72
                             + (((lane >> 3) & 1) << 3)) * 2;
    const uint32_t A0u = spb + (((pair == 0) ? 0 : 4) * PV_A) * 2 + a_offp;
    const uint32_t A1u = spb + (((pair == 0) ? 2 : 6) * PV_A) * 2 + a_offp;
    const uint32_t Bvb = spb + PV_VB * 2;
    const uint32_t B0u = ((pair == 0) ? Bvb : Bvb + 2 * PV_B * 2) + b_offp;
    const uint32_t B1u = Bvb + 2 * PV_B * 2 + b_offp;

    float acc0[4][4], acc1[4][4];
    #pragma unroll
    for (int j = 0; j < 4; j++)
        #pragma unroll
        for (int q = 0; q < 4; q++) { acc0[j][q] = 0.f; acc1[j][q] = 0.f; }

    const int p_n  = tid >> 2;
    const int p_mb = (tid & 3) << 4;
    const float pxn = pos[(b * NN + n0 + p_n) * 3 + 0];
    const float pyn = pos[(b * NN + n0 + p_n) * 3 + 1];
    const float pzn = pos[(b * NN + n0 + p_n) * 3 + 2];
    const bool  pnn = pmask[b * NN + n0 + p_n] != 0;

    for (int m0 = 0; m0 < NEXT; m0 += 64) {
        __syncthreads();
        // ---- phase 1a: P tile + delta -> 4 scaled A mats (hi/lo) ----
        {
            const float* prow = g_attn +
                (((long long)(b * NH + h)) * NN + n0 + p_n) * NEXT + m0 + p_mb;
            float P[16];
            *(float4*)(P + 0)  = *(const float4*)(prow + 0);
            *(float4*)(P + 4)  = *(const float4*)(prow + 4);
            *(float4*)(P + 8)  = *(const float4*)(prow + 8);
            *(float4*)(P + 12) = *(const float4*)(prow + 12);

            float pdx[16], pdy[16], pdz[16];
            #pragma unroll
            for (int q = 0; q < 16; q++) {
                int m = m0 + p_mb + q;
                float ax, ay, az; bool fm;
                if (m < NN) {
                    const float* pp = pos + (b * NN + m) * 3;
                    ax = pp[0]; ay = pp[1]; az = pp[2];
                    fm = pmask[b * NN + m] != 0;
                } else {
                    const float* pp = epos + (b * NM + m - NN) * 3;
                    ax = pp[0]; ay = pp[1]; az = pp[2];
                    fm = emask[b * NM + m - NN] != 0;
                }
                float dx = pxn - ax, dy = pyn - ay, dz = pzn - az;
                float dist = sqrtf(dx * dx + dy * dy + dz * dz);
                if (pnn || fm) dist = 1e6f;
                float inv = 1.f / (dist + 1.f);
                if (pnn) inv = 0.f;
                float Pv = P[q];
                pdx[q] = Pv * dx * inv;
                pdy[q] = Pv * dy * inv;
                pdz[q] = Pv * dz * inv;
            }
            int base = p_n * 72 + p_mb;
            #pragma unroll
            for (int qp = 0; qp < 8; qp++) {
                uint32_t hi, lo;
                split2(P[2*qp], P[2*qp+1], hi, lo);
                *(uint32_t*)(sp + 0 * PV_A + base + 2*qp) = hi;
                *(uint32_t*)(sp + 1 * PV_A + base + 2*qp) = lo;
                split2(pdx[2*qp], pdx[2*qp+1], hi, lo);
                *(uint32_t*)(sp + 2 * PV_A + base + 2*qp) = hi;
                *(uint32_t*)(sp + 3 * PV_A + base + 2*qp) = lo;
                split2(pdy[2*qp], pdy[2*qp+1], hi, lo);
                *(uint32_t*)(sp + 4 * PV_A + base + 2*qp) = hi;
                *(uint32_t*)(sp + 5 * PV_A + base + 2*qp) = lo;
                split2(pdz[2*qp], pdz[2*qp+1], hi, lo);
                *(uint32_t*)(sp + 6 * PV_A + base + 2*qp) = hi;
                *(uint32_t*)(sp + 7 * PV_A + base + 2*qp) = lo;
            }
        }
        // ---- phase 1b: v / ve tiles transposed into B mats ----
        {
            int d  = tid & 31;
            int mq = tid >> 5;
            #pragma unroll
            for (int s = 0; s < 8; s++) {
                int m = (mq << 3) + s;
                int mg = m0 + m;
                int row = (mg < NN) ? mg : oidx[b * NM + mg - NN];
                size_t off = (size_t)(b * NN + row) * NE + h * ND + d;
                VEh[d * 72 + m] = veh_g[off];
                VEl[d * 72 + m] = vel_g[off];
                Vh [d * 72 + m] = vh_g [off];
                Vl [d * 72 + m] = vl_g [off];
            }
        }
        __syncthreads();

        // ---- phase 2: MMAs (ldmatrix fragments) ----
        #pragma unroll
        for (int o = 0; o < 2; o++) {
            const uint32_t Au = o ? A1u : A0u;
            const uint32_t Bu = o ? B1u : B0u;
            float (*acc)[4] = o ? acc1 : acc0;
            #pragma unroll
            for (int kk = 0; kk < 4; kk++) {
                const uint32_t kwb = kk << 5;
                uint32_t ah[4], al[4], bh[4][2], bl[4][2];
                ldsm4(ah[0], ah[1], ah[2], ah[3], Au + kwb);
                ldsm4(al[0], al[1], al[2], al[3], Au + PV_A * 2 + kwb);
                #pragma unroll
                for (int jp = 0; jp < 2; jp++) {
                    ldsm4(bh[2*jp][0], bh[2*jp][1], bh[2*jp+1][0], bh[2*jp+1][1],
                          Bu + jp * 2304 + kwb);
                    ldsm4(bl[2*jp][0], bl[2*jp][1], bl[2*jp+1][0], bl[2*jp+1][1],
                          Bu + PV_B * 2 + jp * 2304 + kwb);
                }
                #pragma unroll
                for (int j = 0; j < 4; j++) {
                    mma16816(acc[j], ah, bh[j]);
                    mma16816(acc[j], ah, bl[j]);
                    mma16816(acc[j], al, bh[j]);
                }
            }
        }
    }

    // ---- epilogue: split to bf16 hi/lo, write to out-GEMM A buffers ----
    const int r0g = n0 + rowblk + g;
    #pragma unroll
    for (int j = 0; j < 4; j++) {
        int col = h * ND + (j << 3) + (tig << 1);
        uint32_t hi, lo;
        if (pair == 0) {
            size_t ro0 = (size_t)(b * NN + r0g) * NE + col;
            size_t ro1 = (size_t)(b * NN + r0g + 8) * NE + col;
            split2(acc0[j][0], acc0[j][1], hi, lo);
            *(uint32_t*)(outh + ro0) = hi; *(uint32_t*)(outl + ro0) = lo;
            split2(acc0[j][2], acc0[j][3], hi, lo);
            *(uint32_t*)(outh + ro1) = hi; *(uint32_t*)(outl + ro1) = lo;
            size_t vo0 = VOFF + ((size_t)(b * NN + r0g) * 3 + 0) * NE + col;
            size_t vo1 = VOFF + ((size_t)(b * NN + r0g + 8) * 3 + 0) * NE + col;
            split2(acc1[j][0], acc1[j][1], hi, lo);
            *(uint32_t*)(outh + vo0) = hi; *(uint32_t*)(outl + vo0) = lo;
            split2(acc1[j][2], acc1[j][3], hi, lo);
            *(uint32_t*)(outh + vo1) = hi; *(uint32_t*)(outl + vo1) = lo;
        } else {
            size_t vo0 = VOFF + ((size_t)(b * NN + r0g) * 3 + 1) * NE + col;
            size_t vo1 = VOFF + ((size_t)(b * NN + r0g + 8) * 3 + 1) * NE + col;
            split2(acc0[j][0], acc0[j][1], hi, lo);
            *(uint32_t*)(outh + vo0) = hi; *(uint32_t*)(outl + vo0) = lo;
            split2(acc0[j][2], acc0[j][3], hi, lo);
            *(uint32_t*)(outh + vo1) = hi; *(uint32_t*)(outl + vo1) = lo;
            size_t wo0 = VOFF + ((size_t)(b * NN + r0g) * 3 + 2) * NE + col;
            size_t wo1 = VOFF + ((size_t)(b * NN + r0g + 8) * 3 + 2) * NE + col;
            split2(acc1[j][0], acc1[j][1], hi, lo);
            *(uint32_t*)(outh + wo0) = hi; *(uint32_t*)(outl + wo0) = lo;
            split2(acc1[j][2], acc1[j][3], hi, lo);
            *(uint32_t*)(outh + wo1) = hi; *(uint32_t*)(outl + wo1) = lo;
        }
    }
}

// ============================================================================
// launch
// ============================================================================
extern "C" void kernel_launch(void* const* d_in, const int* in_sizes, int n_in,
                              void* d_out, int out_size)
{
    const float* x    = (const float*)d_in[0];
    const float* pos  = (const float*)d_in[1];
    const float* epos = (const float*)d_in[2];
    const float* bias = (const float*)d_in[3];
    const unsigned char* pmask = (const unsigned char*)d_in[4];
    const unsigned char* emask = (const unsigned char*)d_in[5];
    const int*   oidx = (const int*)d_in[6];
    const float* Wq   = (const float*)d_in[7];
    const float* Wk   = (const float*)d_in[8];
    const float* Wv   = (const float*)d_in[9];
    const float* Wve  = (const float*)d_in[10];
    const float* Wo   = (const float*)d_in[11];
    const float* Woe  = (const float*)d_in[12];
    float* out = (float*)d_out;

    __nv_bfloat16 *ah, *al, *wh, *wl, *ph, *pl;
    cudaGetSymbolAddress((void**)&ah,  g_ah);
    cudaGetSymbolAddress((void**)&al,  g_al);
    cudaGetSymbolAddress((void**)&wh,  g_wh);
    cudaGetSymbolAddress((void**)&wl,  g_wl);
    cudaGetSymbolAddress((void**)&ph,  g_projh);
    cudaGetSymbolAddress((void**)&pl,  g_projl);

    cudaFuncSetAttribute(gemm_mma,   cudaFuncAttributeMaxDynamicSharedMemorySize, GSMEM_BYTES);
    cudaFuncSetAttribute(qk_softmax, cudaFuncAttributeMaxDynamicSharedMemorySize, QK_SMEM);
    cudaFuncSetAttribute(pv_mma,     cudaFuncAttributeMaxDynamicSharedMemorySize, PV_SMEM);

    const int WSZ = 1024 * 1024;

    // 1) converters
    cvt_split_x<<<2048, 256>>>(x, ah, al);
    cvt_split_w<<<dim3(1024, 6), 256>>>(Wq, Wk, Wv, Wve, Woe, Wo, wh, wl);

    // 2) projections -> bf16 hi/lo (mode 1)
    gemm_mma<<<dim3(8, 16, 4), 256, GSMEM_BYTES>>>(ah, al, wh, wl,
                                                   nullptr, ph, pl, SCALING_F, 1);

    // 3) fused QK + softmax (32-row tiles, 2 CTA/SM)
    qk_softmax<<<dim3(8, 256), 256, QK_SMEM>>>(bias, oidx, pmask, emask,
                                               ph, pl, ph + PSZ, pl + PSZ);

    // 4) fused PV + vec -> bf16 hi/lo A-buffers for out GEMMs
    pv_mma<<<dim3(4, 32, 8), 256, PV_SMEM>>>(pos, epos, oidx, pmask, emask,
                                             ph + 2*PSZ, pl + 2*PSZ,
                                             ph + 3*PSZ, pl + 3*PSZ,
                                             ah, al);

    // 5) output GEMMs (mode 0): xo @ Woe^T, vec @ Wo^T
    gemm_mma<<<dim3(8, 16, 1), 256, GSMEM_BYTES>>>(ah, al, wh + 4*WSZ, wl + 4*WSZ,
                                                   out, nullptr, nullptr, 1.0f, 0);
    gemm_mma<<<dim3(8, 48, 1), 256, GSMEM_BYTES>>>(ah + VOFF, al + VOFF,
                                                   wh + 5*WSZ, wl + 5*WSZ,
                                                   out + NB*NN*NE, nullptr, nullptr, 1.0f, 0);
}

// round 8
// speedup vs baseline: 1.1898x; 1.0028x over previous
#include <cuda_runtime.h>
#include <cuda_bf16.h>
#include <float.h>
#include <math.h>
#include <stdint.h>

// Problem constants
#define NB 8
#define NN 256
#define NM 512
#define NE 1024
#define NH 32
#define ND 32
#define NEXT 768   // N + M

#define SCALING_F 0.17677669529663687f  // 32^-0.5

// ---------------- device scratch ----------------
static __device__ float g_attn[(long long)NB*NH*NN*NEXT];   // probs (fp32)
// bf16 split staging: [0..2M) xo rows, [2M..8M) vec rows (contiguous for fused out-GEMM)
static __device__ __nv_bfloat16 g_ah[8192LL*1024];
static __device__ __nv_bfloat16 g_al[8192LL*1024];
static __device__ __nv_bfloat16 g_wh[6LL*1024*1024]; // weights hi
static __device__ __nv_bfloat16 g_wl[6LL*1024*1024];
// projections q,k,v,ve in bf16 hi/lo ([b*n, e] row-major)
static __device__ __nv_bfloat16 g_projh[4LL*2048*1024];
static __device__ __nv_bfloat16 g_projl[4LL*2048*1024];
#define PSZ 2097152
#define VOFF 2097152

// ============================================================================
// helpers
// ============================================================================
__device__ __forceinline__ uint32_t smem_u32(const void* p) {
    uint32_t a;
    asm("{ .reg .u64 t; cvta.to.shared.u64 t, %1; cvt.u32.u64 %0, t; }"
        : "=r"(a) : "l"(p));
    return a;
}
#define CP_ASYNC16(sa, ga) \
    asm volatile("cp.async.cg.shared.global [%0], [%1], 16;\n" :: "r"(sa), "l"(ga))
#define CP_COMMIT() asm volatile("cp.async.commit_group;\n" ::: "memory")
#define CP_WAIT(n)  asm volatile("cp.async.wait_group %0;\n" :: "n"(n) : "memory")

__device__ __forceinline__ void mma16816(float* c, const uint32_t* a, const uint32_t* b) {
    asm volatile(
        "mma.sync.aligned.m16n8k16.row.col.f32.bf16.bf16.f32 "
        "{%0,%1,%2,%3}, {%4,%5,%6,%7}, {%8,%9}, {%0,%1,%2,%3};\n"
        : "+f"(c[0]), "+f"(c[1]), "+f"(c[2]), "+f"(c[3])
        : "r"(a[0]), "r"(a[1]), "r"(a[2]), "r"(a[3]), "r"(b[0]), "r"(b[1]));
}
__device__ __forceinline__ void ldsm4(uint32_t& r0, uint32_t& r1, uint32_t& r2,
                                      uint32_t& r3, uint32_t a) {
    asm volatile("ldmatrix.sync.aligned.m8n8.x4.shared.b16 {%0,%1,%2,%3}, [%4];"
                 : "=r"(r0), "=r"(r1), "=r"(r2), "=r"(r3) : "r"(a));
}
__device__ __forceinline__ void split2(float a, float b, uint32_t& hi, uint32_t& lo) {
    __nv_bfloat16 h0 = __float2bfloat16(a);
    __nv_bfloat16 h1 = __float2bfloat16(b);
    __nv_bfloat16 l0 = __float2bfloat16(a - __bfloat162float(h0));
    __nv_bfloat16 l1 = __float2bfloat16(b - __bfloat162float(h1));
    __nv_bfloat162 H; H.x = h0; H.y = h1;
    __nv_bfloat162 L; L.x = l0; L.y = l1;
    hi = *(uint32_t*)&H;
    lo = *(uint32_t*)&L;
}

// ============================================================================
// converters
// ============================================================================
__global__ __launch_bounds__(256) void cvt_split_x(const float* __restrict__ src,
                                                   __nv_bfloat16* __restrict__ hi,
                                                   __nv_bfloat16* __restrict__ lo)
{
    int i = blockIdx.x * 256 + threadIdx.x;
    int r  = i >> 8;
    int e4 = (i & 255) << 2;
    int b = r >> 8, n = r & 255;
    float4 v = *(const float4*)(src + ((long long)n * NB + b) * NE + e4);
    uint32_t h0, l0, h1, l1;
    split2(v.x, v.y, h0, l0);
    split2(v.z, v.w, h1, l1);
    ((uint2*)hi)[i] = make_uint2(h0, h1);
    ((uint2*)lo)[i] = make_uint2(l0, l1);
}

__global__ __launch_bounds__(256) void cvt_split_w(const float* __restrict__ W0,
                                                   const float* __restrict__ W1,
                                                   const float* __restrict__ W2,
                                                   const float* __restrict__ W3,
                                                   const float* __restrict__ W4,
                                                   const float* __restrict__ W5,
                                                   __nv_bfloat16* __restrict__ hi,
                                                   __nv_bfloat16* __restrict__ lo)
{
    int w = blockIdx.y;
    const float* src = (w == 0) ? W0 : (w == 1) ? W1 : (w == 2) ? W2
                     : (w == 3) ? W3 : (w == 4) ? W4 : W5;
    int i = blockIdx.x * 256 + threadIdx.x;
    float4 v = ((const float4*)src)[i];
    uint32_t h0, l0, h1, l1;
    split2(v.x, v.y, h0, l0);
    split2(v.z, v.w, h1, l1);
    size_t o = ((size_t)w << 18) + i;
    ((uint2*)hi)[o] = make_uint2(h0, h1);
    ((uint2*)lo)[o] = make_uint2(l0, l1);
}

// ============================================================================
// Tensor-core split-precision GEMM: C = alpha * A @ W^T
//   mode 0: fp32 to C.  mode 1: bf16 hi/lo to Ch/Cl.
//   blockIdx.y >= ysplit switches weights to Bh2/Bl2 (fused out-GEMM).
//   Single-sync double-buffered cp.async pipeline.
// ============================================================================
#define TILE_ELE 5120
#define STAGE_ELE 20480
#define GSMEM_BYTES 81920

__global__ __launch_bounds__(256, 2) void gemm_mma(const __nv_bfloat16* __restrict__ Ah,
                                                   const __nv_bfloat16* __restrict__ Al,
                                                   const __nv_bfloat16* __restrict__ Bh,
                                                   const __nv_bfloat16* __restrict__ Bl,
                                                   const __nv_bfloat16* __restrict__ Bh2,
                                                   const __nv_bfloat16* __restrict__ Bl2,
                                                   int ysplit,
                                                   float* __restrict__ C,
                                                   __nv_bfloat16* __restrict__ Ch,
                                                   __nv_bfloat16* __restrict__ Cl,
                                                   float alpha0, int mode)
{
    extern __shared__ __nv_bfloat16 sm[];

    const int tid  = threadIdx.x;
    const int wid  = tid >> 5;
    const int lane = tid & 31;
    const int g    = lane >> 2;
    const int tig  = lane & 3;
    const int row0 = blockIdx.y << 7;
    const int col0 = blockIdx.x << 7;
    const int z    = blockIdx.z;
    if ((int)blockIdx.y >= ysplit) { Bh = Bh2; Bl = Bl2; }
    Bh += (size_t)z << 20;
    Bl += (size_t)z << 20;
    if (mode == 0) C += (size_t)z << 21;
    else { Ch += (size_t)z << 21; Cl += (size_t)z << 21; }
    const float alpha = (z == 0) ? alpha0 : 1.0f;
    const int wm = (wid & 1) << 6;
    const int wn = (wid >> 1) << 5;

    float acc[4][4][4];
    #pragma unroll
    for (int i = 0; i < 4; i++)
        #pragma unroll
        for (int j = 0; j < 4; j++)
            #pragma unroll
            for (int q = 0; q < 4; q++) acc[i][j][q] = 0.f;

    const uint32_t smbase = smem_u32(sm);
    const uint32_t a_off = ((wm + (lane & 7) + (((lane >> 3) & 1) << 3)) * 40
                            + ((lane >> 4) << 3)) * 2;
    const uint32_t b_off = ((wn + (lane & 7) + ((lane >> 4) << 3)) * 40
                            + (((lane >> 3) & 1) << 3)) * 2;

    #define LOAD_CHUNK(kc, s)                                                     \
    {                                                                             \
        _Pragma("unroll")                                                         \
        for (int t = 0; t < 8; t++) {                                             \
            int u    = tid + (t << 8);                                            \
            int tile = u >> 9;                                                    \
            int r    = (u >> 2) & 127;                                            \
            int cu   = u & 3;                                                     \
            const __nv_bfloat16* gp;                                              \
            if      (tile == 0) gp = Ah + (size_t)(row0 + r) * 1024;              \
            else if (tile == 1) gp = Al + (size_t)(row0 + r) * 1024;              \
            else if (tile == 2) gp = Bh + (size_t)(col0 + r) * 1024;              \
            else                gp = Bl + (size_t)(col0 + r) * 1024;              \
            gp += (kc) * 32 + cu * 8;                                             \
            uint32_t sa = smbase +                                                \
                (uint32_t)(((s) * STAGE_ELE + tile * TILE_ELE + r * 40 + cu * 8) * 2); \
            CP_ASYNC16(sa, gp);                                                   \
        }                                                                         \
    }

    LOAD_CHUNK(0, 0);
    CP_COMMIT();

    for (int kc = 0; kc < 32; kc++) {
        CP_WAIT(0);
        __syncthreads();
        if (kc + 1 < 32) {
            LOAD_CHUNK(kc + 1, (kc + 1) & 1);
            CP_COMMIT();
        }

        const uint32_t so2 = (kc & 1) * (STAGE_ELE * 2);
        const uint32_t abase = smbase + so2 + a_off;
        const uint32_t bbase = smbase + so2 + 2 * TILE_ELE * 2 + b_off;

        #pragma unroll
        for (int kk = 0; kk < 2; kk++) {
            const uint32_t kwb = kk << 5;
            uint32_t ah[4][4], al[4][4], bh[4][2], bl[4][2];
            #pragma unroll
            for (int i = 0; i < 4; i++) {
                ldsm4(ah[i][0], ah[i][1], ah[i][2], ah[i][3],
                      abase + i * 1280 + kwb);
                ldsm4(al[i][0], al[i][1], al[i][2], al[i][3],
                      abase + TILE_ELE * 2 + i * 1280 + kwb);
            }
            #pragma unroll
            for (int jp = 0; jp < 2; jp++) {
                ldsm4(bh[2*jp][0], bh[2*jp][1], bh[2*jp+1][0], bh[2*jp+1][1],
                      bbase + jp * 1280 + kwb);
                ldsm4(bl[2*jp][0], bl[2*jp][1], bl[2*jp+1][0], bl[2*jp+1][1],
                      bbase + TILE_ELE * 2 + jp * 1280 + kwb);
            }
            #pragma unroll
            for (int i = 0; i < 4; i++)
                #pragma unroll
                for (int j = 0; j < 4; j++) {
                    mma16816(acc[i][j], ah[i], bh[j]);
                    mma16816(acc[i][j], ah[i], bl[j]);
                    mma16816(acc[i][j], al[i], bh[j]);
                }
        }
    }

    #pragma unroll
    for (int i = 0; i < 4; i++) {
        int row = row0 + wm + (i << 4) + g;
        #pragma unroll
        for (int j = 0; j < 4; j++) {
            int col = col0 + wn + (j << 3) + (tig << 1);
            float v0 = alpha * acc[i][j][0];
            float v1 = alpha * acc[i][j][1];
            float v2 = alpha * acc[i][j][2];
            float v3 = alpha * acc[i][j][3];
            if (mode == 0) {
                *(float2*)(C + (size_t)row * 1024 + col)       = make_float2(v0, v1);
                *(float2*)(C + (size_t)(row + 8) * 1024 + col) = make_float2(v2, v3);
            } else {
                uint32_t h0, l0, h1, l1;
                split2(v0, v1, h0, l0);
                split2(v2, v3, h1, l1);
                *(uint32_t*)(Ch + (size_t)row * 1024 + col)       = h0;
                *(uint32_t*)(Cl + (size_t)row * 1024 + col)       = l0;
                *(uint32_t*)(Ch + (size_t)(row + 8) * 1024 + col) = h1;
                *(uint32_t*)(Cl + (size_t)(row + 8) * 1024 + col) = l1;
            }
        }
    }
}

// ============================================================================
// Fused QK^T + bias + mask + softmax. 16-row n-tile -> 60.8 KB smem,
// 3 CTAs/SM. Softmax staged through smem (low reg count).
// ============================================================================
#define LSTRIDE 772
#define QK_SMEM 62208   // 12800 B tiles + 16*772*4 logits

__global__ __launch_bounds__(256, 3) void qk_softmax(const float* __restrict__ bias,
                                                  const int*   __restrict__ oidx,
                                                  const unsigned char* __restrict__ pmask,
                                                  const unsigned char* __restrict__ emask,
                                                  const __nv_bfloat16* __restrict__ qh_g,
                                                  const __nv_bfloat16* __restrict__ ql_g,
                                                  const __nv_bfloat16* __restrict__ kh_g,
                                                  const __nv_bfloat16* __restrict__ kl_g)
{
    extern __shared__ char sraw[];
    __nv_bfloat16* sqh = (__nv_bfloat16*)sraw;   // 16x40
    __nv_bfloat16* sql = sqh + 640;
    __nv_bfloat16* skh = sqh + 1280;             // 64x40
    __nv_bfloat16* skl = sqh + 3840;
    float* logits = (float*)(sraw + 12800);      // 16 x 772

    const int tid  = threadIdx.x;
    const int wid  = tid >> 5;
    const int lane = tid & 31;
    const int g    = lane >> 2;
    const int tig  = lane & 3;
    const int bh   = blockIdx.y;
    const int b    = bh >> 5;
    const int h    = bh & 31;
    const int n0   = blockIdx.x << 4;   // 16-row tile

    // load q tile (16 x 32, hi/lo)
    if (tid < 64) {
        int r = tid >> 2, c = (tid & 3) << 3;
        size_t off = (size_t)(b * NN + n0 + r) * NE + h * ND + c;
        *(uint4*)(sqh + r * 40 + c) = *(const uint4*)(qh_g + off);
        *(uint4*)(sql + r * 40 + c) = *(const uint4*)(ql_g + off);
    }

    const int wc = wid << 3;   // warp's 8-col strip within an m-tile

    for (int m0 = 0; m0 < NEXT; m0 += 64) {
        __syncthreads();
        // load k tile 64x32 (gathered)
        {
            int r = tid >> 2, c = (tid & 3) << 3;
            int m = m0 + r;
            int row = (m < NN) ? m : oidx[b * NM + m - NN];
            size_t off = (size_t)(b * NN + row) * NE + h * ND + c;
            *(uint4*)(skh + r * 40 + c) = *(const uint4*)(kh_g + off);
            *(uint4*)(skl + r * 40 + c) = *(const uint4*)(kl_g + off);
        }
        __syncthreads();

        float acc[4] = {0.f, 0.f, 0.f, 0.f};
        #pragma unroll
        for (int kk = 0; kk < 2; kk++) {
            const int kw = kk << 3;
            uint32_t a_h[4], a_l[4], b_h[2], b_l[2];
            a_h[0] = *(const uint32_t*)(sqh + (g    ) * 40 + ((kw + tig    ) << 1));
            a_h[1] = *(const uint32_t*)(sqh + (g + 8) * 40 + ((kw + tig    ) << 1));
            a_h[2] = *(const uint32_t*)(sqh + (g    ) * 40 + ((kw + tig + 4) << 1));
            a_h[3] = *(const uint32_t*)(sqh + (g + 8) * 40 + ((kw + tig + 4) << 1));
            a_l[0] = *(const uint32_t*)(sql + (g    ) * 40 + ((kw + tig    ) << 1));
            a_l[1] = *(const uint32_t*)(sql + (g + 8) * 40 + ((kw + tig    ) << 1));
            a_l[2] = *(const uint32_t*)(sql + (g    ) * 40 + ((kw + tig + 4) << 1));
            a_l[3] = *(const uint32_t*)(sql + (g + 8) * 40 + ((kw + tig + 4) << 1));
            b_h[0] = *(const uint32_t*)(skh + (wc + g) * 40 + ((kw + tig    ) << 1));
            b_h[1] = *(const uint32_t*)(skh + (wc + g) * 40 + ((kw + tig + 4) << 1));
            b_l[0] = *(const uint32_t*)(skl + (wc + g) * 40 + ((kw + tig    ) << 1));
            b_l[1] = *(const uint32_t*)(skl + (wc + g) * 40 + ((kw + tig + 4) << 1));
            mma16816(acc, a_h, b_h);
            mma16816(acc, a_h, b_l);
            mma16816(acc, a_l, b_h);
        }
        int col = m0 + wc + (tig << 1);
        *(float2*)&logits[(g    ) * LSTRIDE + col] = make_float2(acc[0], acc[1]);
        *(float2*)&logits[(g + 8) * LSTRIDE + col] = make_float2(acc[2], acc[3]);
    }
    __syncthreads();

    // softmax: warp wid handles rows 2*wid, 2*wid+1; staged through smem.
    #pragma unroll
    for (int rw = 0; rw < 2; rw++) {
        int rr = (wid << 1) + rw;
        int n = n0 + rr;
        bool pn = pmask[b * NN + n] != 0;
        float* lrow = logits + rr * LSTRIDE;
        long long goff = (((long long)(b * NH + h)) * NN + n) * NEXT;

        float mx = -FLT_MAX;
        #pragma unroll
        for (int t = 0; t < 24; t++) {
            int m = lane + (t << 5);
            bool fm = (m < NN) ? (pmask[b * NN + m] != 0)
                               : (emask[b * NM + m - NN] != 0);
            float v = lrow[m] + bias[goff + m];
            if (pn || fm) v = -FLT_MAX;
            lrow[m] = v;
            mx = fmaxf(mx, v);
        }
        #pragma unroll
        for (int o = 16; o > 0; o >>= 1)
            mx = fmaxf(mx, __shfl_xor_sync(0xffffffffu, mx, o));

        float s = 0.f;
        #pragma unroll
        for (int t = 0; t < 24; t++) {
            int m = lane + (t << 5);
            float e = expf(lrow[m] - mx);
            s += e;
            lrow[m] = e;
        }
        #pragma unroll
        for (int o = 16; o > 0; o >>= 1)
            s += __shfl_xor_sync(0xffffffffu, s, o);
        float inv = 1.f / s;

        #pragma unroll
        for (int t = 0; t < 24; t++) {
            int m = lane + (t << 5);
            g_attn[goff + m] = lrow[m] * inv;
        }
    }
}

// ============================================================================
// Fused PV + vec with split-bf16 HMMA + ldmatrix (unchanged from round 7).
// ============================================================================
#define PV_A    4608
#define PV_VB   36864
#define PV_B    2304
#define PV_SMEM 92160

__global__ __launch_bounds__(256, 2) void pv_mma(const float* __restrict__ pos,
                                                 const float* __restrict__ epos,
                                                 const int*   __restrict__ oidx,
                                                 const unsigned char* __restrict__ pmask,
                                                 const unsigned char* __restrict__ emask,
                                                 const __nv_bfloat16* __restrict__ vh_g,
                                                 const __nv_bfloat16* __restrict__ vl_g,
                                                 const __nv_bfloat16* __restrict__ veh_g,
                                                 const __nv_bfloat16* __restrict__ vel_g,
                                                 __nv_bfloat16* __restrict__ outh,
                                                 __nv_bfloat16* __restrict__ outl)
{
    extern __shared__ __nv_bfloat16 sp[];

    const int tid  = threadIdx.x;
    const int wid  = tid >> 5;
    const int lane = tid & 31;
    const int g    = lane >> 2;
    const int tig  = lane & 3;
    const int b    = blockIdx.z;
    const int h    = blockIdx.y;
    const int n0   = blockIdx.x << 6;

    const int rowblk = (wid & 3) << 4;
    const int pair   = wid >> 2;

    __nv_bfloat16* VEh = sp + PV_VB;
    __nv_bfloat16* VEl = VEh + PV_B;
    __nv_bfloat16* Vh  = VEh + 2 * PV_B;
    __nv_bfloat16* Vl  = VEh + 3 * PV_B;

    const uint32_t spb = smem_u32(sp);
    const uint32_t a_offp = ((rowblk + (lane & 7) + (((lane >> 3) & 1) << 3)) * 72
                             + ((lane >> 4) << 3)) * 2;
    const uint32_t b_offp = (((lane & 7) + ((lane >> 4) << 3)) * 72
                             + (((lane >> 3) & 1) << 3)) * 2;
    const uint32_t A0u = spb + (((pair == 0) ? 0 : 4) * PV_A) * 2 + a_offp;
    const uint32_t A1u = spb + (((pair == 0) ? 2 : 6) * PV_A) * 2 + a_offp;
    const uint32_t Bvb = spb + PV_VB * 2;
    const uint32_t B0u = ((pair == 0) ? Bvb : Bvb + 2 * PV_B * 2) + b_offp;
    const uint32_t B1u = Bvb + 2 * PV_B * 2 + b_offp;

    float acc0[4][4], acc1[4][4];
    #pragma unroll
    for (int j = 0; j < 4; j++)
        #pragma unroll
        for (int q = 0; q < 4; q++) { acc0[j][q] = 0.f; acc1[j][q] = 0.f; }

    const int p_n  = tid >> 2;
    const int p_mb = (tid & 3) << 4;
    const float pxn = pos[(b * NN + n0 + p_n) * 3 + 0];
    const float pyn = pos[(b * NN + n0 + p_n) * 3 + 1];
    const float pzn = pos[(b * NN + n0 + p_n) * 3 + 2];
    const bool  pnn = pmask[b * NN + n0 + p_n] != 0;

    for (int m0 = 0; m0 < NEXT; m0 += 64) {
        __syncthreads();
        // ---- phase 1a: P tile + delta -> 4 scaled A mats (hi/lo) ----
        {
            const float* prow = g_attn +
                (((long long)(b * NH + h)) * NN + n0 + p_n) * NEXT + m0 + p_mb;
            float P[16];
            *(float4*)(P + 0)  = *(const float4*)(prow + 0);
            *(float4*)(P + 4)  = *(const float4*)(prow + 4);
            *(float4*)(P + 8)  = *(const float4*)(prow + 8);
            *(float4*)(P + 12) = *(const float4*)(prow + 12);

            float pdx[16], pdy[16], pdz[16];
            #pragma unroll
            for (int q = 0; q < 16; q++) {
                int m = m0 + p_mb + q;
                float ax, ay, az; bool fm;
                if (m < NN) {
                    const float* pp = pos + (b * NN + m) * 3;
                    ax = pp[0]; ay = pp[1]; az = pp[2];
                    fm = pmask[b * NN + m] != 0;
                } else {
                    const float* pp = epos + (b * NM + m - NN) * 3;
                    ax = pp[0]; ay = pp[1]; az = pp[2];
                    fm = emask[b * NM + m - NN] != 0;
                }
                float dx = pxn - ax, dy = pyn - ay, dz = pzn - az;
                float dist = sqrtf(dx * dx + dy * dy + dz * dz);
                if (pnn || fm) dist = 1e6f;
                float inv = 1.f / (dist + 1.f);
                if (pnn) inv = 0.f;
                float Pv = P[q];
                pdx[q] = Pv * dx * inv;
                pdy[q] = Pv * dy * inv;
                pdz[q] = Pv * dz * inv;
            }
            int base = p_n * 72 + p_mb;
            #pragma unroll
            for (int qp = 0; qp < 8; qp++) {
                uint32_t hi, lo;
                split2(P[2*qp], P[2*qp+1], hi, lo);
                *(uint32_t*)(sp + 0 * PV_A + base + 2*qp) = hi;
                *(uint32_t*)(sp + 1 * PV_A + base + 2*qp) = lo;
                split2(pdx[2*qp], pdx[2*qp+1], hi, lo);
                *(uint32_t*)(sp + 2 * PV_A + base + 2*qp) = hi;
                *(uint32_t*)(sp + 3 * PV_A + base + 2*qp) = lo;
                split2(pdy[2*qp], pdy[2*qp+1], hi, lo);
                *(uint32_t*)(sp + 4 * PV_A + base + 2*qp) = hi;
                *(uint32_t*)(sp + 5 * PV_A + base + 2*qp) = lo;
                split2(pdz[2*qp], pdz[2*qp+1], hi, lo);
                *(uint32_t*)(sp + 6 * PV_A + base + 2*qp) = hi;
                *(uint32_t*)(sp + 7 * PV_A + base + 2*qp) = lo;
            }
        }
        // ---- phase 1b: v / ve tiles transposed into B mats ----
        {
            int d  = tid & 31;
            int mq = tid >> 5;
            #pragma unroll
            for (int s = 0; s < 8; s++) {
                int m = (mq << 3) + s;
                int mg = m0 + m;
                int row = (mg < NN) ? mg : oidx[b * NM + mg - NN];
                size_t off = (size_t)(b * NN + row) * NE + h * ND + d;
                VEh[d * 72 + m] = veh_g[off];
                VEl[d * 72 + m] = vel_g[off];
                Vh [d * 72 + m] = vh_g [off];
                Vl [d * 72 + m] = vl_g [off];
            }
        }
        __syncthreads();

        // ---- phase 2: MMAs (ldmatrix fragments) ----
        #pragma unroll
        for (int o = 0; o < 2; o++) {
            const uint32_t Au = o ? A1u : A0u;
            const uint32_t Bu = o ? B1u : B0u;
            float (*acc)[4] = o ? acc1 : acc0;
            #pragma unroll
            for (int kk = 0; kk < 4; kk++) {
                const uint32_t kwb = kk << 5;
                uint32_t ah[4], al[4], bh[4][2], bl[4][2];
                ldsm4(ah[0], ah[1], ah[2], ah[3], Au + kwb);
                ldsm4(al[0], al[1], al[2], al[3], Au + PV_A * 2 + kwb);
                #pragma unroll
                for (int jp = 0; jp < 2; jp++) {
                    ldsm4(bh[2*jp][0], bh[2*jp][1], bh[2*jp+1][0], bh[2*jp+1][1],
                          Bu + jp * 2304 + kwb);
                    ldsm4(bl[2*jp][0], bl[2*jp][1], bl[2*jp+1][0], bl[2*jp+1][1],
                          Bu + PV_B * 2 + jp * 2304 + kwb);
                }
                #pragma unroll
                for (int j = 0; j < 4; j++) {
                    mma16816(acc[j], ah, bh[j]);
                    mma16816(acc[j], ah, bl[j]);
                    mma16816(acc[j], al, bh[j]);
                }
            }
        }
    }

    // ---- epilogue: split to bf16 hi/lo, write to out-GEMM A buffers ----
    const int r0g = n0 + rowblk + g;
    #pragma unroll
    for (int j = 0; j < 4; j++) {
        int col = h * ND + (j << 3) + (tig << 1);
        uint32_t hi, lo;
        if (pair == 0) {
            size_t ro0 = (size_t)(b * NN + r0g) * NE + col;
            size_t ro1 = (size_t)(b * NN + r0g + 8) * NE + col;
            split2(acc0[j][0], acc0[j][1], hi, lo);
            *(uint32_t*)(outh + ro0) = hi; *(uint32_t*)(outl + ro0) = lo;
            split2(acc0[j][2], acc0[j][3], hi, lo);
            *(uint32_t*)(outh + ro1) = hi; *(uint32_t*)(outl + ro1) = lo;
            size_t vo0 = VOFF + ((size_t)(b * NN + r0g) * 3 + 0) * NE + col;
            size_t vo1 = VOFF + ((size_t)(b * NN + r0g + 8) * 3 + 0) * NE + col;
            split2(acc1[j][0], acc1[j][1], hi, lo);
            *(uint32_t*)(outh + vo0) = hi; *(uint32_t*)(outl + vo0) = lo;
            split2(acc1[j][2], acc1[j][3], hi, lo);
            *(uint32_t*)(outh + vo1) = hi; *(uint32_t*)(outl + vo1) = lo;
        } else {
            size_t vo0 = VOFF + ((size_t)(b * NN + r0g) * 3 + 1) * NE + col;
            size_t vo1 = VOFF + ((size_t)(b * NN + r0g + 8) * 3 + 1) * NE + col;
            split2(acc0[j][0], acc0[j][1], hi, lo);
            *(uint32_t*)(outh + vo0) = hi; *(uint32_t*)(outl + vo0) = lo;
            split2(acc0[j][2], acc0[j][3], hi, lo);
            *(uint32_t*)(outh + vo1) = hi; *(uint32_t*)(outl + vo1) = lo;
            size_t wo0 = VOFF + ((size_t)(b * NN + r0g) * 3 + 2) * NE + col;
            size_t wo1 = VOFF + ((size_t)(b * NN + r0g + 8) * 3 + 2) * NE + col;
            split2(acc1[j][0], acc1[j][1], hi, lo);
            *(uint32_t*)(outh + wo0) = hi; *(uint32_t*)(outl + wo0) = lo;
            split2(acc1[j][2], acc1[j][3], hi, lo);
            *(uint32_t*)(outh + wo1) = hi; *(uint32_t*)(outl + wo1) = lo;
        }
    }
}

// ============================================================================
// launch
// ============================================================================
extern "C" void kernel_launch(void* const* d_in, const int* in_sizes, int n_in,
                              void* d_out, int out_size)
{
    const float* x    = (const float*)d_in[0];
    const float* pos  = (const float*)d_in[1];
    const float* epos = (const float*)d_in[2];
    const float* bias = (const float*)d_in[3];
    const unsigned char* pmask = (const unsigned char*)d_in[4];
    const unsigned char* emask = (const unsigned char*)d_in[5];
    const int*   oidx = (const int*)d_in[6];
    const float* Wq   = (const float*)d_in[7];
    const float* Wk   = (const float*)d_in[8];
    const float* Wv   = (const float*)d_in[9];
    const float* Wve  = (const float*)d_in[10];
    const float* Wo   = (const float*)d_in[11];
    const float* Woe  = (const float*)d_in[12];
    float* out = (float*)d_out;

    __nv_bfloat16 *ah, *al, *wh, *wl, *ph, *pl;
    cudaGetSymbolAddress((void**)&ah,  g_ah);
    cudaGetSymbolAddress((void**)&al,  g_al);
    cudaGetSymbolAddress((void**)&wh,  g_wh);
    cudaGetSymbolAddress((void**)&wl,  g_wl);
    cudaGetSymbolAddress((void**)&ph,  g_projh);
    cudaGetSymbolAddress((void**)&pl,  g_projl);

    cudaFuncSetAttribute(gemm_mma,   cudaFuncAttributeMaxDynamicSharedMemorySize, GSMEM_BYTES);
    cudaFuncSetAttribute(qk_softmax, cudaFuncAttributeMaxDynamicSharedMemorySize, QK_SMEM);
    cudaFuncSetAttribute(pv_mma,     cudaFuncAttributeMaxDynamicSharedMemorySize, PV_SMEM);

    const int WSZ = 1024 * 1024;

    // 1) converters
    cvt_split_x<<<2048, 256>>>(x, ah, al);
    cvt_split_w<<<dim3(1024, 6), 256>>>(Wq, Wk, Wv, Wve, Woe, Wo, wh, wl);

    // 2) projections -> bf16 hi/lo (mode 1)
    gemm_mma<<<dim3(8, 16, 4), 256, GSMEM_BYTES>>>(ah, al, wh, wl,
                                                   nullptr, nullptr, 1024,
                                                   nullptr, ph, pl, SCALING_F, 1);

    // 3) fused QK + softmax (16-row tiles, 3 CTA/SM)
    qk_softmax<<<dim3(16, 256), 256, QK_SMEM>>>(bias, oidx, pmask, emask,
                                                ph, pl, ph + PSZ, pl + PSZ);

    // 4) fused PV + vec -> bf16 hi/lo A-buffers
    pv_mma<<<dim3(4, 32, 8), 256, PV_SMEM>>>(pos, epos, oidx, pmask, emask,
                                             ph + 2*PSZ, pl + 2*PSZ,
                                             ph + 3*PSZ, pl + 3*PSZ,
                                             ah, al);

    // 5) fused output GEMMs: rows [0,2048) @ Woe^T, rows [2048,8192) @ Wo^T
    gemm_mma<<<dim3(8, 64, 1), 256, GSMEM_BYTES>>>(ah, al,
                                                   wh + 4*WSZ, wl + 4*WSZ,
                                                   wh + 5*WSZ, wl + 5*WSZ, 16,
                                                   out, nullptr, nullptr, 1.0f, 0);
}

// round 9
// speedup vs baseline: 1.3178x; 1.1075x over previous
#include <cuda_runtime.h>
#include <cuda_bf16.h>
#include <float.h>
#include <math.h>
#include <stdint.h>

// Problem constants
#define NB 8
#define NN 256
#define NM 512
#define NE 1024
#define NH 32
#define ND 32
#define NEXT 768   // N + M

#define SCALING_F 0.17677669529663687f  // 32^-0.5

// ---------------- device scratch ----------------
static __device__ float g_attn[(long long)NB*NH*NN*NEXT];   // probs (fp32)
static __device__ float g_delta[(long long)NB*NN*3*NEXT];   // masked delta [b,n,c,m]
// bf16 split staging: [0..2M) xo rows, [2M..8M) vec rows
static __device__ __nv_bfloat16 g_ah[8192LL*1024];
static __device__ __nv_bfloat16 g_al[8192LL*1024];
static __device__ __nv_bfloat16 g_wh[6LL*1024*1024];
static __device__ __nv_bfloat16 g_wl[6LL*1024*1024];
// projections q,k,v,ve in bf16 hi/lo
static __device__ __nv_bfloat16 g_projh[4LL*2048*1024];
static __device__ __nv_bfloat16 g_projl[4LL*2048*1024];
#define PSZ 2097152
#define VOFF 2097152

// ============================================================================
// helpers
// ============================================================================
__device__ __forceinline__ uint32_t smem_u32(const void* p) {
    uint32_t a;
    asm("{ .reg .u64 t; cvta.to.shared.u64 t, %1; cvt.u32.u64 %0, t; }"
        : "=r"(a) : "l"(p));
    return a;
}
#define CP_ASYNC16(sa, ga) \
    asm volatile("cp.async.cg.shared.global [%0], [%1], 16;\n" :: "r"(sa), "l"(ga))
#define CP_COMMIT() asm volatile("cp.async.commit_group;\n" ::: "memory")
#define CP_WAIT(n)  asm volatile("cp.async.wait_group %0;\n" :: "n"(n) : "memory")

__device__ __forceinline__ void mma16816(float* c, const uint32_t* a, const uint32_t* b) {
    asm volatile(
        "mma.sync.aligned.m16n8k16.row.col.f32.bf16.bf16.f32 "
        "{%0,%1,%2,%3}, {%4,%5,%6,%7}, {%8,%9}, {%0,%1,%2,%3};\n"
        : "+f"(c[0]), "+f"(c[1]), "+f"(c[2]), "+f"(c[3])
        : "r"(a[0]), "r"(a[1]), "r"(a[2]), "r"(a[3]), "r"(b[0]), "r"(b[1]));
}
__device__ __forceinline__ void ldsm4(uint32_t& r0, uint32_t& r1, uint32_t& r2,
                                      uint32_t& r3, uint32_t a) {
    asm volatile("ldmatrix.sync.aligned.m8n8.x4.shared.b16 {%0,%1,%2,%3}, [%4];"
                 : "=r"(r0), "=r"(r1), "=r"(r2), "=r"(r3) : "r"(a));
}
__device__ __forceinline__ void split2(float a, float b, uint32_t& hi, uint32_t& lo) {
    __nv_bfloat16 h0 = __float2bfloat16(a);
    __nv_bfloat16 h1 = __float2bfloat16(b);
    __nv_bfloat16 l0 = __float2bfloat16(a - __bfloat162float(h0));
    __nv_bfloat16 l1 = __float2bfloat16(b - __bfloat162float(h1));
    __nv_bfloat162 H; H.x = h0; H.y = h1;
    __nv_bfloat162 L; L.x = l0; L.y = l1;
    hi = *(uint32_t*)&H;
    lo = *(uint32_t*)&L;
}
__device__ __forceinline__ float sqrt_approx(float x) {
    float r;
    asm("sqrt.approx.f32 %0, %1;" : "=f"(r) : "f"(x));
    return r;
}
__device__ __forceinline__ float rcp_approx(float x) {
    float r;
    asm("rcp.approx.f32 %0, %1;" : "=f"(r) : "f"(x));
    return r;
}

// ============================================================================
// converters
// ============================================================================
__global__ __launch_bounds__(256) void cvt_split_x(const float* __restrict__ src,
                                                   __nv_bfloat16* __restrict__ hi,
                                                   __nv_bfloat16* __restrict__ lo)
{
    int i = blockIdx.x * 256 + threadIdx.x;
    int r  = i >> 8;
    int e4 = (i & 255) << 2;
    int b = r >> 8, n = r & 255;
    float4 v = *(const float4*)(src + ((long long)n * NB + b) * NE + e4);
    uint32_t h0, l0, h1, l1;
    split2(v.x, v.y, h0, l0);
    split2(v.z, v.w, h1, l1);
    ((uint2*)hi)[i] = make_uint2(h0, h1);
    ((uint2*)lo)[i] = make_uint2(l0, l1);
}

__global__ __launch_bounds__(256) void cvt_split_w(const float* __restrict__ W0,
                                                   const float* __restrict__ W1,
                                                   const float* __restrict__ W2,
                                                   const float* __restrict__ W3,
                                                   const float* __restrict__ W4,
                                                   const float* __restrict__ W5,
                                                   __nv_bfloat16* __restrict__ hi,
                                                   __nv_bfloat16* __restrict__ lo)
{
    int w = blockIdx.y;
    const float* src = (w == 0) ? W0 : (w == 1) ? W1 : (w == 2) ? W2
                     : (w == 3) ? W3 : (w == 4) ? W4 : W5;
    int i = blockIdx.x * 256 + threadIdx.x;
    float4 v = ((const float4*)src)[i];
    uint32_t h0, l0, h1, l1;
    split2(v.x, v.y, h0, l0);
    split2(v.z, v.w, h1, l1);
    size_t o = ((size_t)w << 18) + i;
    ((uint2*)hi)[o] = make_uint2(h0, h1);
    ((uint2*)lo)[o] = make_uint2(l0, l1);
}

// ============================================================================
// Precompute masked delta [b,n,c,m] (h-independent; computed ONCE).
// ============================================================================
__global__ __launch_bounds__(256) void delta_pre(const float* __restrict__ pos,
                                                 const float* __restrict__ epos,
                                                 const unsigned char* __restrict__ pmask,
                                                 const unsigned char* __restrict__ emask,
                                                 float* __restrict__ delta)
{
    int i = blockIdx.x * 256 + threadIdx.x;   // over NB*NN*NEXT = 1572864
    int m = i % NEXT;
    int n = (i / NEXT) % NN;
    int b = i / (NEXT * NN);

    float pxn = pos[(b * NN + n) * 3 + 0];
    float pyn = pos[(b * NN + n) * 3 + 1];
    float pzn = pos[(b * NN + n) * 3 + 2];
    bool  pn  = pmask[b * NN + n] != 0;

    float ax, ay, az; bool fm;
    if (m < NN) {
        const float* pp = pos + (b * NN + m) * 3;
        ax = pp[0]; ay = pp[1]; az = pp[2];
        fm = pmask[b * NN + m] != 0;
    } else {
        const float* pp = epos + (b * NM + m - NN) * 3;
        ax = pp[0]; ay = pp[1]; az = pp[2];
        fm = emask[b * NM + m - NN] != 0;
    }
    float dx = pxn - ax, dy = pyn - ay, dz = pzn - az;
    float dist = sqrt_approx(dx * dx + dy * dy + dz * dz);
    if (pn || fm) dist = 1e6f;
    float inv = rcp_approx(dist + 1.f);
    if (pn) inv = 0.f;

    size_t base = ((size_t)(b * NN + n) * 3) * NEXT + m;
    delta[base           ] = dx * inv;
    delta[base +     NEXT] = dy * inv;
    delta[base + 2 * NEXT] = dz * inv;
}

// ============================================================================
// Tensor-core split-precision GEMM: C = alpha * A @ W^T
//   mode 0: fp32 to C.  mode 1: bf16 hi/lo to Ch/Cl.
//   blockIdx.y >= ysplit switches weights to Bh2/Bl2 (fused out-GEMM).
// ============================================================================
#define TILE_ELE 5120
#define STAGE_ELE 20480
#define GSMEM_BYTES 81920

__global__ __launch_bounds__(256, 2) void gemm_mma(const __nv_bfloat16* __restrict__ Ah,
                                                   const __nv_bfloat16* __restrict__ Al,
                                                   const __nv_bfloat16* __restrict__ Bh,
                                                   const __nv_bfloat16* __restrict__ Bl,
                                                   const __nv_bfloat16* __restrict__ Bh2,
                                                   const __nv_bfloat16* __restrict__ Bl2,
                                                   int ysplit,
                                                   float* __restrict__ C,
                                                   __nv_bfloat16* __restrict__ Ch,
                                                   __nv_bfloat16* __restrict__ Cl,
                                                   float alpha0, int mode)
{
    extern __shared__ __nv_bfloat16 sm[];

    const int tid  = threadIdx.x;
    const int wid  = tid >> 5;
    const int lane = tid & 31;
    const int g    = lane >> 2;
    const int tig  = lane & 3;
    const int row0 = blockIdx.y << 7;
    const int col0 = blockIdx.x << 7;
    const int z    = blockIdx.z;
    if ((int)blockIdx.y >= ysplit) { Bh = Bh2; Bl = Bl2; }
    Bh += (size_t)z << 20;
    Bl += (size_t)z << 20;
    if (mode == 0) C += (size_t)z << 21;
    else { Ch += (size_t)z << 21; Cl += (size_t)z << 21; }
    const float alpha = (z == 0) ? alpha0 : 1.0f;
    const int wm = (wid & 1) << 6;
    const int wn = (wid >> 1) << 5;

    float acc[4][4][4];
    #pragma unroll
    for (int i = 0; i < 4; i++)
        #pragma unroll
        for (int j = 0; j < 4; j++)
            #pragma unroll
            for (int q = 0; q < 4; q++) acc[i][j][q] = 0.f;

    const uint32_t smbase = smem_u32(sm);
    const uint32_t a_off = ((wm + (lane & 7) + (((lane >> 3) & 1) << 3)) * 40
                            + ((lane >> 4) << 3)) * 2;
    const uint32_t b_off = ((wn + (lane & 7) + ((lane >> 4) << 3)) * 40
                            + (((lane >> 3) & 1) << 3)) * 2;

    #define LOAD_CHUNK(kc, s)                                                     \
    {                                                                             \
        _Pragma("unroll")                                                         \
        for (int t = 0; t < 8; t++) {                                             \
            int u    = tid + (t << 8);                                            \
            int tile = u >> 9;                                                    \
            int r    = (u >> 2) & 127;                                            \
            int cu   = u & 3;                                                     \
            const __nv_bfloat16* gp;                                              \
            if      (tile == 0) gp = Ah + (size_t)(row0 + r) * 1024;              \
            else if (tile == 1) gp = Al + (size_t)(row0 + r) * 1024;              \
            else if (tile == 2) gp = Bh + (size_t)(col0 + r) * 1024;              \
            else                gp = Bl + (size_t)(col0 + r) * 1024;              \
            gp += (kc) * 32 + cu * 8;                                             \
            uint32_t sa = smbase +                                                \
                (uint32_t)(((s) * STAGE_ELE + tile * TILE_ELE + r * 40 + cu * 8) * 2); \
            CP_ASYNC16(sa, gp);                                                   \
        }                                                                         \
    }

    LOAD_CHUNK(0, 0);
    CP_COMMIT();

    for (int kc = 0; kc < 32; kc++) {
        CP_WAIT(0);
        __syncthreads();
        if (kc + 1 < 32) {
            LOAD_CHUNK(kc + 1, (kc + 1) & 1);
            CP_COMMIT();
        }

        const uint32_t so2 = (kc & 1) * (STAGE_ELE * 2);
        const uint32_t abase = smbase + so2 + a_off;
        const uint32_t bbase = smbase + so2 + 2 * TILE_ELE * 2 + b_off;

        #pragma unroll
        for (int kk = 0; kk < 2; kk++) {
            const uint32_t kwb = kk << 5;
            uint32_t ah[4][4], al[4][4], bh[4][2], bl[4][2];
            #pragma unroll
            for (int i = 0; i < 4; i++) {
                ldsm4(ah[i][0], ah[i][1], ah[i][2], ah[i][3],
                      abase + i * 1280 + kwb);
                ldsm4(al[i][0], al[i][1], al[i][2], al[i][3],
                      abase + TILE_ELE * 2 + i * 1280 + kwb);
            }
            #pragma unroll
            for (int jp = 0; jp < 2; jp++) {
                ldsm4(bh[2*jp][0], bh[2*jp][1], bh[2*jp+1][0], bh[2*jp+1][1],
                      bbase + jp * 1280 + kwb);
                ldsm4(bl[2*jp][0], bl[2*jp][1], bl[2*jp+1][0], bl[2*jp+1][1],
                      bbase + TILE_ELE * 2 + jp * 1280 + kwb);
            }
            #pragma unroll
            for (int i = 0; i < 4; i++)
                #pragma unroll
                for (int j = 0; j < 4; j++) {
                    mma16816(acc[i][j], ah[i], bh[j]);
                    mma16816(acc[i][j], ah[i], bl[j]);
                    mma16816(acc[i][j], al[i], bh[j]);
                }
        }
    }

    #pragma unroll
    for (int i = 0; i < 4; i++) {
        int row = row0 + wm + (i << 4) + g;
        #pragma unroll
        for (int j = 0; j < 4; j++) {
            int col = col0 + wn + (j << 3) + (tig << 1);
            float v0 = alpha * acc[i][j][0];
            float v1 = alpha * acc[i][j][1];
            float v2 = alpha * acc[i][j][2];
            float v3 = alpha * acc[i][j][3];
            if (mode == 0) {
                *(float2*)(C + (size_t)row * 1024 + col)       = make_float2(v0, v1);
                *(float2*)(C + (size_t)(row + 8) * 1024 + col) = make_float2(v2, v3);
            } else {
                uint32_t h0, l0, h1, l1;
                split2(v0, v1, h0, l0);
                split2(v2, v3, h1, l1);
                *(uint32_t*)(Ch + (size_t)row * 1024 + col)       = h0;
                *(uint32_t*)(Cl + (size_t)row * 1024 + col)       = l0;
                *(uint32_t*)(Ch + (size_t)(row + 8) * 1024 + col) = h1;
                *(uint32_t*)(Cl + (size_t)(row + 8) * 1024 + col) = l1;
            }
        }
    }
}

// ============================================================================
// Fused QK^T + bias + mask + softmax (Round-7 winner: 32-row tile, 2 CTA/SM,
// register-resident softmax).
// ============================================================================
#define LSTRIDE 772
#define QK_SMEM 114176   // 7680*2 + 32*772*4

__global__ __launch_bounds__(256, 2) void qk_softmax(const float* __restrict__ bias,
                                                  const int*   __restrict__ oidx,
                                                  const unsigned char* __restrict__ pmask,
                                                  const unsigned char* __restrict__ emask,
                                                  const __nv_bfloat16* __restrict__ qh_g,
                                                  const __nv_bfloat16* __restrict__ ql_g,
                                                  const __nv_bfloat16* __restrict__ kh_g,
                                                  const __nv_bfloat16* __restrict__ kl_g)
{
    extern __shared__ char sraw[];
    __nv_bfloat16* sqh = (__nv_bfloat16*)sraw;
    __nv_bfloat16* sql = sqh + 1280;
    __nv_bfloat16* skh = sqh + 2560;
    __nv_bfloat16* skl = sqh + 5120;
    float* logits = (float*)(sraw + 15360);

    const int tid  = threadIdx.x;
    const int wid  = tid >> 5;
    const int lane = tid & 31;
    const int g    = lane >> 2;
    const int tig  = lane & 3;
    const int bh   = blockIdx.y;
    const int b    = bh >> 5;
    const int h    = bh & 31;
    const int n0   = blockIdx.x << 5;

    if (tid < 128) {
        int r = tid >> 2, c = (tid & 3) << 3;
        size_t off = (size_t)(b * NN + n0 + r) * NE + h * ND + c;
        *(uint4*)(sqh + r * 40 + c) = *(const uint4*)(qh_g + off);
        *(uint4*)(sql + r * 40 + c) = *(const uint4*)(ql_g + off);
    }

    const int wn = (wid & 1) << 4;
    const int wm = (wid >> 1) << 4;

    for (int m0 = 0; m0 < NEXT; m0 += 64) {
        __syncthreads();
        {
            int r = tid >> 2, c = (tid & 3) << 3;
            int m = m0 + r;
            int row = (m < NN) ? m : oidx[b * NM + m - NN];
            size_t off = (size_t)(b * NN + row) * NE + h * ND + c;
            *(uint4*)(skh + r * 40 + c) = *(const uint4*)(kh_g + off);
            *(uint4*)(skl + r * 40 + c) = *(const uint4*)(kl_g + off);
        }
        __syncthreads();

        float acc[2][4];
        #pragma unroll
        for (int j = 0; j < 2; j++)
            #pragma unroll
            for (int q = 0; q < 4; q++) acc[j][q] = 0.f;

        #pragma unroll
        for (int kk = 0; kk < 2; kk++) {
            const int kw = kk << 3;
            uint32_t a_h[4], a_l[4], bhf[2][2], blf[2][2];
            {
                int rA = wn + g;
                a_h[0] = *(const uint32_t*)(sqh + (rA    ) * 40 + ((kw + tig    ) << 1));
                a_h[1] = *(const uint32_t*)(sqh + (rA + 8) * 40 + ((kw + tig    ) << 1));
                a_h[2] = *(const uint32_t*)(sqh + (rA    ) * 40 + ((kw + tig + 4) << 1));
                a_h[3] = *(const uint32_t*)(sqh + (rA + 8) * 40 + ((kw + tig + 4) << 1));
                a_l[0] = *(const uint32_t*)(sql + (rA    ) * 40 + ((kw + tig    ) << 1));
                a_l[1] = *(const uint32_t*)(sql + (rA + 8) * 40 + ((kw + tig    ) << 1));
                a_l[2] = *(const uint32_t*)(sql + (rA    ) * 40 + ((kw + tig + 4) << 1));
                a_l[3] = *(const uint32_t*)(sql + (rA + 8) * 40 + ((kw + tig + 4) << 1));
            }
            #pragma unroll
            for (int j = 0; j < 2; j++) {
                int rB = wm + (j << 3) + g;
                bhf[j][0] = *(const uint32_t*)(skh + rB * 40 + ((kw + tig    ) << 1));
                bhf[j][1] = *(const uint32_t*)(skh + rB * 40 + ((kw + tig + 4) << 1));
                blf[j][0] = *(const uint32_t*)(skl + rB * 40 + ((kw + tig    ) << 1));
                blf[j][1] = *(const uint32_t*)(skl + rB * 40 + ((kw + tig + 4) << 1));
            }
            #pragma unroll
            for (int j = 0; j < 2; j++) {
                mma16816(acc[j], a_h, bhf[j]);
                mma16816(acc[j], a_h, blf[j]);
                mma16816(acc[j], a_l, bhf[j]);
            }
        }

        #pragma unroll
        for (int j = 0; j < 2; j++) {
            int col = m0 + wm + (j << 3) + (tig << 1);
            int row = wn + g;
            *(float2*)&logits[row * LSTRIDE + col]       = make_float2(acc[j][0], acc[j][1]);
            *(float2*)&logits[(row + 8) * LSTRIDE + col] = make_float2(acc[j][2], acc[j][3]);
        }
    }
    __syncthreads();

    for (int rr = wid; rr < 32; rr += 8) {
        int n = n0 + rr;
        bool pn = pmask[b * NN + n] != 0;
        const float* lrow = logits + rr * LSTRIDE;
        long long goff = (((long long)(b * NH + h)) * NN + n) * NEXT;

        float val[24];
        float mx = -FLT_MAX;
        #pragma unroll
        for (int t = 0; t < 24; t++) {
            int m = lane + (t << 5);
            bool fm = (m < NN) ? (pmask[b * NN + m] != 0)
                               : (emask[b * NM + m - NN] != 0);
            float v = lrow[m] + bias[goff + m];
            if (pn || fm) v = -FLT_MAX;
            val[t] = v;
            mx = fmaxf(mx, v);
        }
        #pragma unroll
        for (int o = 16; o > 0; o >>= 1)
            mx = fmaxf(mx, __shfl_xor_sync(0xffffffffu, mx, o));
        float s = 0.f;
        #pragma unroll
        for (int t = 0; t < 24; t++) {
            val[t] = expf(val[t] - mx);
            s += val[t];
        }
        #pragma unroll
        for (int o = 16; o > 0; o >>= 1)
            s += __shfl_xor_sync(0xffffffffu, s, o);
        float inv = 1.f / s;
        #pragma unroll
        for (int t = 0; t < 24; t++)
            g_attn[goff + lane + (t << 5)] = val[t] * inv;
    }
}

// ============================================================================
// Fused PV + vec with split-bf16 HMMA + ldmatrix; delta read precomputed.
// ============================================================================
#define PV_A    4608
#define PV_VB   36864
#define PV_B    2304
#define PV_SMEM 92160

__global__ __launch_bounds__(256, 2) void pv_mma(const float* __restrict__ delta,
                                                 const int*   __restrict__ oidx,
                                                 const __nv_bfloat16* __restrict__ vh_g,
                                                 const __nv_bfloat16* __restrict__ vl_g,
                                                 const __nv_bfloat16* __restrict__ veh_g,
                                                 const __nv_bfloat16* __restrict__ vel_g,
                                                 __nv_bfloat16* __restrict__ outh,
                                                 __nv_bfloat16* __restrict__ outl)
{
    extern __shared__ __nv_bfloat16 sp[];

    const int tid  = threadIdx.x;
    const int wid  = tid >> 5;
    const int lane = tid & 31;
    const int g    = lane >> 2;
    const int tig  = lane & 3;
    const int b    = blockIdx.z;
    const int h    = blockIdx.y;
    const int n0   = blockIdx.x << 6;

    const int rowblk = (wid & 3) << 4;
    const int pair   = wid >> 2;

    __nv_bfloat16* VEh = sp + PV_VB;
    __nv_bfloat16* VEl = VEh + PV_B;
    __nv_bfloat16* Vh  = VEh + 2 * PV_B;
    __nv_bfloat16* Vl  = VEh + 3 * PV_B;

    const uint32_t spb = smem_u32(sp);
    const uint32_t a_offp = ((rowblk + (lane & 7) + (((lane >> 3) & 1) << 3)) * 72
                             + ((lane >> 4) << 3)) * 2;
    const uint32_t b_offp = (((lane & 7) + ((lane >> 4) << 3)) * 72
                             + (((lane >> 3) & 1) << 3)) * 2;
    const uint32_t A0u = spb + (((pair == 0) ? 0 : 4) * PV_A) * 2 + a_offp;
    const uint32_t A1u = spb + (((pair == 0) ? 2 : 6) * PV_A) * 2 + a_offp;
    const uint32_t Bvb = spb + PV_VB * 2;
    const uint32_t B0u = ((pair == 0) ? Bvb : Bvb + 2 * PV_B * 2) + b_offp;
    const uint32_t B1u = Bvb + 2 * PV_B * 2 + b_offp;

    float acc0[4][4], acc1[4][4];
    #pragma unroll
    for (int j = 0; j < 4; j++)
        #pragma unroll
        for (int q = 0; q < 4; q++) { acc0[j][q] = 0.f; acc1[j][q] = 0.f; }

    const int p_n  = tid >> 2;
    const int p_mb = (tid & 3) << 4;
    const size_t drow = ((size_t)(b * NN + n0 + p_n) * 3) * NEXT;

    for (int m0 = 0; m0 < NEXT; m0 += 64) {
        __syncthreads();
        // ---- phase 1a: P tile * precomputed delta -> 4 scaled A mats ----
        {
            const float* prow = g_attn +
                (((long long)(b * NH + h)) * NN + n0 + p_n) * NEXT + m0 + p_mb;
            float P[16], dxv[16], dyv[16], dzv[16];
            #pragma unroll
            for (int q4 = 0; q4 < 4; q4++) {
                *(float4*)(P   + q4*4) = *(const float4*)(prow + q4*4);
                *(float4*)(dxv + q4*4) = *(const float4*)(delta + drow            + m0 + p_mb + q4*4);
                *(float4*)(dyv + q4*4) = *(const float4*)(delta + drow +     NEXT + m0 + p_mb + q4*4);
                *(float4*)(dzv + q4*4) = *(const float4*)(delta + drow + 2 * NEXT + m0 + p_mb + q4*4);
            }
            int base = p_n * 72 + p_mb;
            #pragma unroll
            for (int qp = 0; qp < 8; qp++) {
                float p0 = P[2*qp], p1 = P[2*qp+1];
                uint32_t hi, lo;
                split2(p0, p1, hi, lo);
                *(uint32_t*)(sp + 0 * PV_A + base + 2*qp) = hi;
                *(uint32_t*)(sp + 1 * PV_A + base + 2*qp) = lo;
                split2(p0 * dxv[2*qp], p1 * dxv[2*qp+1], hi, lo);
                *(uint32_t*)(sp + 2 * PV_A + base + 2*qp) = hi;
                *(uint32_t*)(sp + 3 * PV_A + base + 2*qp) = lo;
                split2(p0 * dyv[2*qp], p1 * dyv[2*qp+1], hi, lo);
                *(uint32_t*)(sp + 4 * PV_A + base + 2*qp) = hi;
                *(uint32_t*)(sp + 5 * PV_A + base + 2*qp) = lo;
                split2(p0 * dzv[2*qp], p1 * dzv[2*qp+1], hi, lo);
                *(uint32_t*)(sp + 6 * PV_A + base + 2*qp) = hi;
                *(uint32_t*)(sp + 7 * PV_A + base + 2*qp) = lo;
            }
        }
        // ---- phase 1b: v / ve tiles transposed into B mats ----
        {
            int d  = tid & 31;
            int mq = tid >> 5;
            #pragma unroll
            for (int s = 0; s < 8; s++) {
                int m = (mq << 3) + s;
                int mg = m0 + m;
                int row = (mg < NN) ? mg : oidx[b * NM + mg - NN];
                size_t off = (size_t)(b * NN + row) * NE + h * ND + d;
                VEh[d * 72 + m] = veh_g[off];
                VEl[d * 72 + m] = vel_g[off];
                Vh [d * 72 + m] = vh_g [off];
                Vl [d * 72 + m] = vl_g [off];
            }
        }
        __syncthreads();

        // ---- phase 2: MMAs (ldmatrix fragments) ----
        #pragma unroll
        for (int o = 0; o < 2; o++) {
            const uint32_t Au = o ? A1u : A0u;
            const uint32_t Bu = o ? B1u : B0u;
            float (*acc)[4] = o ? acc1 : acc0;
            #pragma unroll
            for (int kk = 0; kk < 4; kk++) {
                const uint32_t kwb = kk << 5;
                uint32_t ah[4], al[4], bh[4][2], bl[4][2];
                ldsm4(ah[0], ah[1], ah[2], ah[3], Au + kwb);
                ldsm4(al[0], al[1], al[2], al[3], Au + PV_A * 2 + kwb);
                #pragma unroll
                for (int jp = 0; jp < 2; jp++) {
                    ldsm4(bh[2*jp][0], bh[2*jp][1], bh[2*jp+1][0], bh[2*jp+1][1],
                          Bu + jp * 2304 + kwb);
                    ldsm4(bl[2*jp][0], bl[2*jp][1], bl[2*jp+1][0], bl[2*jp+1][1],
                          Bu + PV_B * 2 + jp * 2304 + kwb);
                }
                #pragma unroll
                for (int j = 0; j < 4; j++) {
                    mma16816(acc[j], ah, bh[j]);
                    mma16816(acc[j], ah, bl[j]);
                    mma16816(acc[j], al, bh[j]);
                }
            }
        }
    }

    // ---- epilogue: split to bf16 hi/lo, write to out-GEMM A buffers ----
    const int r0g = n0 + rowblk + g;
    #pragma unroll
    for (int j = 0; j < 4; j++) {
        int col = h * ND + (j << 3) + (tig << 1);
        uint32_t hi, lo;
        if (pair == 0) {
            size_t ro0 = (size_t)(b * NN + r0g) * NE + col;
            size_t ro1 = (size_t)(b * NN + r0g + 8) * NE + col;
            split2(acc0[j][0], acc0[j][1], hi, lo);
            *(uint32_t*)(outh + ro0) = hi; *(uint32_t*)(outl + ro0) = lo;
            split2(acc0[j][2], acc0[j][3], hi, lo);
            *(uint32_t*)(outh + ro1) = hi; *(uint32_t*)(outl + ro1) = lo;
            size_t vo0 = VOFF + ((size_t)(b * NN + r0g) * 3 + 0) * NE + col;
            size_t vo1 = VOFF + ((size_t)(b * NN + r0g + 8) * 3 + 0) * NE + col;
            split2(acc1[j][0], acc1[j][1], hi, lo);
            *(uint32_t*)(outh + vo0) = hi; *(uint32_t*)(outl + vo0) = lo;
            split2(acc1[j][2], acc1[j][3], hi, lo);
            *(uint32_t*)(outh + vo1) = hi; *(uint32_t*)(outl + vo1) = lo;
        } else {
            size_t vo0 = VOFF + ((size_t)(b * NN + r0g) * 3 + 1) * NE + col;
            size_t vo1 = VOFF + ((size_t)(b * NN + r0g + 8) * 3 + 1) * NE + col;
            split2(acc0[j][0], acc0[j][1], hi, lo);
            *(uint32_t*)(outh + vo0) = hi; *(uint32_t*)(outl + vo0) = lo;
            split2(acc0[j][2], acc0[j][3], hi, lo);
            *(uint32_t*)(outh + vo1) = hi; *(uint32_t*)(outl + vo1) = lo;
            size_t wo0 = VOFF + ((size_t)(b * NN + r0g) * 3 + 2) * NE + col;
            size_t wo1 = VOFF + ((size_t)(b * NN + r0g + 8) * 3 + 2) * NE + col;
            split2(acc1[j][0], acc1[j][1], hi, lo);
            *(uint32_t*)(outh + wo0) = hi; *(uint32_t*)(outl + wo0) = lo;
            split2(acc1[j][2], acc1[j][3], hi, lo);
            *(uint32_t*)(outh + wo1) = hi; *(uint32_t*)(outl + wo1) = lo;
        }
    }
}

// ============================================================================
// launch
// ============================================================================
extern "C" void kernel_launch(void* const* d_in, const int* in_sizes, int n_in,
                              void* d_out, int out_size)
{
    const float* x    = (const float*)d_in[0];
    const float* pos  = (const float*)d_in[1];
    const float* epos = (const float*)d_in[2];
    const float* bias = (const float*)d_in[3];
    const unsigned char* pmask = (const unsigned char*)d_in[4];
    const unsigned char* emask = (const unsigned char*)d_in[5];
    const int*   oidx = (const int*)d_in[6];
    const float* Wq   = (const float*)d_in[7];
    const float* Wk   = (const float*)d_in[8];
    const float* Wv   = (const float*)d_in[9];
    const float* Wve  = (const float*)d_in[10];
    const float* Wo   = (const float*)d_in[11];
    const float* Woe  = (const float*)d_in[12];
    float* out = (float*)d_out;

    __nv_bfloat16 *ah, *al, *wh, *wl, *ph, *pl;
    float *dlt;
    cudaGetSymbolAddress((void**)&ah,  g_ah);
    cudaGetSymbolAddress((void**)&al,  g_al);
    cudaGetSymbolAddress((void**)&wh,  g_wh);
    cudaGetSymbolAddress((void**)&wl,  g_wl);
    cudaGetSymbolAddress((void**)&ph,  g_projh);
    cudaGetSymbolAddress((void**)&pl,  g_projl);
    cudaGetSymbolAddress((void**)&dlt, g_delta);

    cudaFuncSetAttribute(gemm_mma,   cudaFuncAttributeMaxDynamicSharedMemorySize, GSMEM_BYTES);
    cudaFuncSetAttribute(qk_softmax, cudaFuncAttributeMaxDynamicSharedMemorySize, QK_SMEM);
    cudaFuncSetAttribute(pv_mma,     cudaFuncAttributeMaxDynamicSharedMemorySize, PV_SMEM);

    const int WSZ = 1024 * 1024;

    // 1) converters + delta precompute
    cvt_split_x<<<2048, 256>>>(x, ah, al);
    cvt_split_w<<<dim3(1024, 6), 256>>>(Wq, Wk, Wv, Wve, Woe, Wo, wh, wl);
    delta_pre<<<6144, 256>>>(pos, epos, pmask, emask, dlt);

    // 2) projections -> bf16 hi/lo (mode 1)
    gemm_mma<<<dim3(8, 16, 4), 256, GSMEM_BYTES>>>(ah, al, wh, wl,
                                                   nullptr, nullptr, 1024,
                                                   nullptr, ph, pl, SCALING_F, 1);

    // 3) fused QK + softmax (32-row tiles, 2 CTA/SM)
    qk_softmax<<<dim3(8, 256), 256, QK_SMEM>>>(bias, oidx, pmask, emask,
                                               ph, pl, ph + PSZ, pl + PSZ);

    // 4) fused PV + vec -> bf16 hi/lo A-buffers (delta precomputed)
    pv_mma<<<dim3(4, 32, 8), 256, PV_SMEM>>>(dlt, oidx,
                                             ph + 2*PSZ, pl + 2*PSZ,
                                             ph + 3*PSZ, pl + 3*PSZ,
                                             ah, al);

    // 5) fused output GEMMs: rows [0,2048) @ Woe^T, rows [2048,8192) @ Wo^T
    gemm_mma<<<dim3(8, 64, 1), 256, GSMEM_BYTES>>>(ah, al,
                                                   wh + 4*WSZ, wl + 4*WSZ,
                                                   wh + 5*WSZ, wl + 5*WSZ, 16,
                                                   out, nullptr, nullptr, 1.0f, 0);
}

// round 10
// speedup vs baseline: 1.3227x; 1.0037x over previous
#include <cuda_runtime.h>
#include <cuda_bf16.h>
#include <float.h>
#include <math.h>
#include <stdint.h>

// Problem constants
#define NB 8
#define NN 256
#define NM 512
#define NE 1024
#define NH 32
#define ND 32
#define NEXT 768   // N + M

#define SCALING_F 0.17677669529663687f  // 32^-0.5

// ---------------- device scratch ----------------
static __device__ float g_attn[(long long)NB*NH*NN*NEXT];   // probs (fp32)
static __device__ float g_delta[(long long)NB*NN*3*NEXT];   // masked delta [b,n,c,m]
static __device__ __nv_bfloat16 g_ah[8192LL*1024];
static __device__ __nv_bfloat16 g_al[8192LL*1024];
static __device__ __nv_bfloat16 g_wh[6LL*1024*1024];
static __device__ __nv_bfloat16 g_wl[6LL*1024*1024];
static __device__ __nv_bfloat16 g_projh[4LL*2048*1024];
static __device__ __nv_bfloat16 g_projl[4LL*2048*1024];
#define PSZ 2097152
#define VOFF 2097152

// ============================================================================
// helpers
// ============================================================================
__device__ __forceinline__ uint32_t smem_u32(const void* p) {
    uint32_t a;
    asm("{ .reg .u64 t; cvta.to.shared.u64 t, %1; cvt.u32.u64 %0, t; }"
        : "=r"(a) : "l"(p));
    return a;
}
#define CP_ASYNC16(sa, ga) \
    asm volatile("cp.async.cg.shared.global [%0], [%1], 16;\n" :: "r"(sa), "l"(ga))
#define CP_COMMIT() asm volatile("cp.async.commit_group;\n" ::: "memory")
#define CP_WAIT(n)  asm volatile("cp.async.wait_group %0;\n" :: "n"(n) : "memory")

__device__ __forceinline__ void mma16816(float* c, const uint32_t* a, const uint32_t* b) {
    asm volatile(
        "mma.sync.aligned.m16n8k16.row.col.f32.bf16.bf16.f32 "
        "{%0,%1,%2,%3}, {%4,%5,%6,%7}, {%8,%9}, {%0,%1,%2,%3};\n"
        : "+f"(c[0]), "+f"(c[1]), "+f"(c[2]), "+f"(c[3])
        : "r"(a[0]), "r"(a[1]), "r"(a[2]), "r"(a[3]), "r"(b[0]), "r"(b[1]));
}
__device__ __forceinline__ void ldsm4(uint32_t& r0, uint32_t& r1, uint32_t& r2,
                                      uint32_t& r3, uint32_t a) {
    asm volatile("ldmatrix.sync.aligned.m8n8.x4.shared.b16 {%0,%1,%2,%3}, [%4];"
                 : "=r"(r0), "=r"(r1), "=r"(r2), "=r"(r3) : "r"(a));
}
__device__ __forceinline__ void split2(float a, float b, uint32_t& hi, uint32_t& lo) {
    __nv_bfloat16 h0 = __float2bfloat16(a);
    __nv_bfloat16 h1 = __float2bfloat16(b);
    __nv_bfloat16 l0 = __float2bfloat16(a - __bfloat162float(h0));
    __nv_bfloat16 l1 = __float2bfloat16(b - __bfloat162float(h1));
    __nv_bfloat162 H; H.x = h0; H.y = h1;
    __nv_bfloat162 L; L.x = l0; L.y = l1;
    hi = *(uint32_t*)&H;
    lo = *(uint32_t*)&L;
}
__device__ __forceinline__ float sqrt_approx(float x) {
    float r;
    asm("sqrt.approx.f32 %0, %1;" : "=f"(r) : "f"(x));
    return r;
}
__device__ __forceinline__ float rcp_approx(float x) {
    float r;
    asm("rcp.approx.f32 %0, %1;" : "=f"(r) : "f"(x));
    return r;
}

// ============================================================================
// converters
// ============================================================================
__global__ __launch_bounds__(256) void cvt_split_x(const float* __restrict__ src,
                                                   __nv_bfloat16* __restrict__ hi,
                                                   __nv_bfloat16* __restrict__ lo)
{
    int i = blockIdx.x * 256 + threadIdx.x;
    int r  = i >> 8;
    int e4 = (i & 255) << 2;
    int b = r >> 8, n = r & 255;
    float4 v = *(const float4*)(src + ((long long)n * NB + b) * NE + e4);
    uint32_t h0, l0, h1, l1;
    split2(v.x, v.y, h0, l0);
    split2(v.z, v.w, h1, l1);
    ((uint2*)hi)[i] = make_uint2(h0, h1);
    ((uint2*)lo)[i] = make_uint2(l0, l1);
}

__global__ __launch_bounds__(256) void cvt_split_w(const float* __restrict__ W0,
                                                   const float* __restrict__ W1,
                                                   const float* __restrict__ W2,
                                                   const float* __restrict__ W3,
                                                   const float* __restrict__ W4,
                                                   const float* __restrict__ W5,
                                                   __nv_bfloat16* __restrict__ hi,
                                                   __nv_bfloat16* __restrict__ lo)
{
    int w = blockIdx.y;
    const float* src = (w == 0) ? W0 : (w == 1) ? W1 : (w == 2) ? W2
                     : (w == 3) ? W3 : (w == 4) ? W4 : W5;
    int i = blockIdx.x * 256 + threadIdx.x;
    float4 v = ((const float4*)src)[i];
    uint32_t h0, l0, h1, l1;
    split2(v.x, v.y, h0, l0);
    split2(v.z, v.w, h1, l1);
    size_t o = ((size_t)w << 18) + i;
    ((uint2*)hi)[o] = make_uint2(h0, h1);
    ((uint2*)lo)[o] = make_uint2(l0, l1);
}

// ============================================================================
// Precompute masked delta [b,n,c,m]
// ============================================================================
__global__ __launch_bounds__(256) void delta_pre(const float* __restrict__ pos,
                                                 const float* __restrict__ epos,
                                                 const unsigned char* __restrict__ pmask,
                                                 const unsigned char* __restrict__ emask,
                                                 float* __restrict__ delta)
{
    int i = blockIdx.x * 256 + threadIdx.x;
    int m = i % NEXT;
    int n = (i / NEXT) % NN;
    int b = i / (NEXT * NN);

    float pxn = pos[(b * NN + n) * 3 + 0];
    float pyn = pos[(b * NN + n) * 3 + 1];
    float pzn = pos[(b * NN + n) * 3 + 2];
    bool  pn  = pmask[b * NN + n] != 0;

    float ax, ay, az; bool fm;
    if (m < NN) {
        const float* pp = pos + (b * NN + m) * 3;
        ax = pp[0]; ay = pp[1]; az = pp[2];
        fm = pmask[b * NN + m] != 0;
    } else {
        const float* pp = epos + (b * NM + m - NN) * 3;
        ax = pp[0]; ay = pp[1]; az = pp[2];
        fm = emask[b * NM + m - NN] != 0;
    }
    float dx = pxn - ax, dy = pyn - ay, dz = pzn - az;
    float dist = sqrt_approx(dx * dx + dy * dy + dz * dz);
    if (pn || fm) dist = 1e6f;
    float inv = rcp_approx(dist + 1.f);
    if (pn) inv = 0.f;

    size_t base = ((size_t)(b * NN + n) * 3) * NEXT + m;
    delta[base           ] = dx * inv;
    delta[base +     NEXT] = dy * inv;
    delta[base + 2 * NEXT] = dz * inv;
}

// ============================================================================
// Tensor-core split-precision GEMM (term-outermost MMA ordering for ILP)
// ============================================================================
#define TILE_ELE 5120
#define STAGE_ELE 20480
#define GSMEM_BYTES 81920

__global__ __launch_bounds__(256, 2) void gemm_mma(const __nv_bfloat16* __restrict__ Ah,
                                                   const __nv_bfloat16* __restrict__ Al,
                                                   const __nv_bfloat16* __restrict__ Bh,
                                                   const __nv_bfloat16* __restrict__ Bl,
                                                   const __nv_bfloat16* __restrict__ Bh2,
                                                   const __nv_bfloat16* __restrict__ Bl2,
                                                   int ysplit,
                                                   float* __restrict__ C,
                                                   __nv_bfloat16* __restrict__ Ch,
                                                   __nv_bfloat16* __restrict__ Cl,
                                                   float alpha0, int mode)
{
    extern __shared__ __nv_bfloat16 sm[];

    const int tid  = threadIdx.x;
    const int wid  = tid >> 5;
    const int lane = tid & 31;
    const int g    = lane >> 2;
    const int tig  = lane & 3;
    const int row0 = blockIdx.y << 7;
    const int col0 = blockIdx.x << 7;
    const int z    = blockIdx.z;
    if ((int)blockIdx.y >= ysplit) { Bh = Bh2; Bl = Bl2; }
    Bh += (size_t)z << 20;
    Bl += (size_t)z << 20;
    if (mode == 0) C += (size_t)z << 21;
    else { Ch += (size_t)z << 21; Cl += (size_t)z << 21; }
    const float alpha = (z == 0) ? alpha0 : 1.0f;
    const int wm = (wid & 1) << 6;
    const int wn = (wid >> 1) << 5;

    float acc[4][4][4];
    #pragma unroll
    for (int i = 0; i < 4; i++)
        #pragma unroll
        for (int j = 0; j < 4; j++)
            #pragma unroll
            for (int q = 0; q < 4; q++) acc[i][j][q] = 0.f;

    const uint32_t smbase = smem_u32(sm);
    const uint32_t a_off = ((wm + (lane & 7) + (((lane >> 3) & 1) << 3)) * 40
                            + ((lane >> 4) << 3)) * 2;
    const uint32_t b_off = ((wn + (lane & 7) + ((lane >> 4) << 3)) * 40
                            + (((lane >> 3) & 1) << 3)) * 2;

    #define LOAD_CHUNK(kc, s)                                                     \
    {                                                                             \
        _Pragma("unroll")                                                         \
        for (int t = 0; t < 8; t++) {                                             \
            int u    = tid + (t << 8);                                            \
            int tile = u >> 9;                                                    \
            int r    = (u >> 2) & 127;                                            \
            int cu   = u & 3;                                                     \
            const __nv_bfloat16* gp;                                              \
            if      (tile == 0) gp = Ah + (size_t)(row0 + r) * 1024;              \
            else if (tile == 1) gp = Al + (size_t)(row0 + r) * 1024;              \
            else if (tile == 2) gp = Bh + (size_t)(col0 + r) * 1024;              \
            else                gp = Bl + (size_t)(col0 + r) * 1024;              \
            gp += (kc) * 32 + cu * 8;                                             \
            uint32_t sa = smbase +                                                \
                (uint32_t)(((s) * STAGE_ELE + tile * TILE_ELE + r * 40 + cu * 8) * 2); \
            CP_ASYNC16(sa, gp);                                                   \
        }                                                                         \
    }

    LOAD_CHUNK(0, 0);
    CP_COMMIT();

    for (int kc = 0; kc < 32; kc++) {
        CP_WAIT(0);
        __syncthreads();
        if (kc + 1 < 32) {
            LOAD_CHUNK(kc + 1, (kc + 1) & 1);
            CP_COMMIT();
        }

        const uint32_t so2 = (kc & 1) * (STAGE_ELE * 2);
        const uint32_t abase = smbase + so2 + a_off;
        const uint32_t bbase = smbase + so2 + 2 * TILE_ELE * 2 + b_off;

        #pragma unroll
        for (int kk = 0; kk < 2; kk++) {
            const uint32_t kwb = kk << 5;
            uint32_t ah[4][4], al[4][4], bh[4][2], bl[4][2];
            #pragma unroll
            for (int i = 0; i < 4; i++) {
                ldsm4(ah[i][0], ah[i][1], ah[i][2], ah[i][3],
                      abase + i * 1280 + kwb);
                ldsm4(al[i][0], al[i][1], al[i][2], al[i][3],
                      abase + TILE_ELE * 2 + i * 1280 + kwb);
            }
            #pragma unroll
            for (int jp = 0; jp < 2; jp++) {
                ldsm4(bh[2*jp][0], bh[2*jp][1], bh[2*jp+1][0], bh[2*jp+1][1],
                      bbase + jp * 1280 + kwb);
                ldsm4(bl[2*jp][0], bl[2*jp][1], bl[2*jp+1][0], bl[2*jp+1][1],
                      bbase + TILE_ELE * 2 + jp * 1280 + kwb);
            }
            // term-outermost: 16 independent accumulator chains per term
            #pragma unroll
            for (int i = 0; i < 4; i++)
                #pragma unroll
                for (int j = 0; j < 4; j++)
                    mma16816(acc[i][j], ah[i], bh[j]);
            #pragma unroll
            for (int i = 0; i < 4; i++)
                #pragma unroll
                for (int j = 0; j < 4; j++)
                    mma16816(acc[i][j], ah[i], bl[j]);
            #pragma unroll
            for (int i = 0; i < 4; i++)
                #pragma unroll
                for (int j = 0; j < 4; j++)
                    mma16816(acc[i][j], al[i], bh[j]);
        }
    }

    #pragma unroll
    for (int i = 0; i < 4; i++) {
        int row = row0 + wm + (i << 4) + g;
        #pragma unroll
        for (int j = 0; j < 4; j++) {
            int col = col0 + wn + (j << 3) + (tig << 1);
            float v0 = alpha * acc[i][j][0];
            float v1 = alpha * acc[i][j][1];
            float v2 = alpha * acc[i][j][2];
            float v3 = alpha * acc[i][j][3];
            if (mode == 0) {
                *(float2*)(C + (size_t)row * 1024 + col)       = make_float2(v0, v1);
                *(float2*)(C + (size_t)(row + 8) * 1024 + col) = make_float2(v2, v3);
            } else {
                uint32_t h0, l0, h1, l1;
                split2(v0, v1, h0, l0);
                split2(v2, v3, h1, l1);
                *(uint32_t*)(Ch + (size_t)row * 1024 + col)       = h0;
                *(uint32_t*)(Cl + (size_t)row * 1024 + col)       = l0;
                *(uint32_t*)(Ch + (size_t)(row + 8) * 1024 + col) = h1;
                *(uint32_t*)(Cl + (size_t)(row + 8) * 1024 + col) = l1;
            }
        }
    }
}

// ============================================================================
// Fused QK^T + bias + mask + softmax (32-row tile, term-outermost MMAs)
// ============================================================================
#define LSTRIDE 772
#define QK_SMEM 114176

__global__ __launch_bounds__(256, 2) void qk_softmax(const float* __restrict__ bias,
                                                  const int*   __restrict__ oidx,
                                                  const unsigned char* __restrict__ pmask,
                                                  const unsigned char* __restrict__ emask,
                                                  const __nv_bfloat16* __restrict__ qh_g,
                                                  const __nv_bfloat16* __restrict__ ql_g,
                                                  const __nv_bfloat16* __restrict__ kh_g,
                                                  const __nv_bfloat16* __restrict__ kl_g)
{
    extern __shared__ char sraw[];
    __nv_bfloat16* sqh = (__nv_bfloat16*)sraw;
    __nv_bfloat16* sql = sqh + 1280;
    __nv_bfloat16* skh = sqh + 2560;
    __nv_bfloat16* skl = sqh + 5120;
    float* logits = (float*)(sraw + 15360);

    const int tid  = threadIdx.x;
    const int wid  = tid >> 5;
    const int lane = tid & 31;
    const int g    = lane >> 2;
    const int tig  = lane & 3;
    const int bh   = blockIdx.y;
    const int b    = bh >> 5;
    const int h    = bh & 31;
    const int n0   = blockIdx.x << 5;

    if (tid < 128) {
        int r = tid >> 2, c = (tid & 3) << 3;
        size_t off = (size_t)(b * NN + n0 + r) * NE + h * ND + c;
        *(uint4*)(sqh + r * 40 + c) = *(const uint4*)(qh_g + off);
        *(uint4*)(sql + r * 40 + c) = *(const uint4*)(ql_g + off);
    }

    const int wn = (wid & 1) << 4;
    const int wm = (wid >> 1) << 4;

    for (int m0 = 0; m0 < NEXT; m0 += 64) {
        __syncthreads();
        {
            int r = tid >> 2, c = (tid & 3) << 3;
            int m = m0 + r;
            int row = (m < NN) ? m : oidx[b * NM + m - NN];
            size_t off = (size_t)(b * NN + row) * NE + h * ND + c;
            *(uint4*)(skh + r * 40 + c) = *(const uint4*)(kh_g + off);
            *(uint4*)(skl + r * 40 + c) = *(const uint4*)(kl_g + off);
        }
        __syncthreads();

        float acc[2][4];
        #pragma unroll
        for (int j = 0; j < 2; j++)
            #pragma unroll
            for (int q = 0; q < 4; q++) acc[j][q] = 0.f;

        #pragma unroll
        for (int kk = 0; kk < 2; kk++) {
            const int kw = kk << 3;
            uint32_t a_h[4], a_l[4], bhf[2][2], blf[2][2];
            {
                int rA = wn + g;
                a_h[0] = *(const uint32_t*)(sqh + (rA    ) * 40 + ((kw + tig    ) << 1));
                a_h[1] = *(const uint32_t*)(sqh + (rA + 8) * 40 + ((kw + tig    ) << 1));
                a_h[2] = *(const uint32_t*)(sqh + (rA    ) * 40 + ((kw + tig + 4) << 1));
                a_h[3] = *(const uint32_t*)(sqh + (rA + 8) * 40 + ((kw + tig + 4) << 1));
                a_l[0] = *(const uint32_t*)(sql + (rA    ) * 40 + ((kw + tig    ) << 1));
                a_l[1] = *(const uint32_t*)(sql + (rA + 8) * 40 + ((kw + tig    ) << 1));
                a_l[2] = *(const uint32_t*)(sql + (rA    ) * 40 + ((kw + tig + 4) << 1));
                a_l[3] = *(const uint32_t*)(sql + (rA + 8) * 40 + ((kw + tig + 4) << 1));
            }
            #pragma unroll
            for (int j = 0; j < 2; j++) {
                int rB = wm + (j << 3) + g;
                bhf[j][0] = *(const uint32_t*)(skh + rB * 40 + ((kw + tig    ) << 1));
                bhf[j][1] = *(const uint32_t*)(skh + rB * 40 + ((kw + tig + 4) << 1));
                blf[j][0] = *(const uint32_t*)(skl + rB * 40 + ((kw + tig    ) << 1));
                blf[j][1] = *(const uint32_t*)(skl + rB * 40 + ((kw + tig + 4) << 1));
            }
            // term-outermost
            #pragma unroll
            for (int j = 0; j < 2; j++) mma16816(acc[j], a_h, bhf[j]);
            #pragma unroll
            for (int j = 0; j < 2; j++) mma16816(acc[j], a_h, blf[j]);
            #pragma unroll
            for (int j = 0; j < 2; j++) mma16816(acc[j], a_l, bhf[j]);
        }

        #pragma unroll
        for (int j = 0; j < 2; j++) {
            int col = m0 + wm + (j << 3) + (tig << 1);
            int row = wn + g;
            *(float2*)&logits[row * LSTRIDE + col]       = make_float2(acc[j][0], acc[j][1]);
            *(float2*)&logits[(row + 8) * LSTRIDE + col] = make_float2(acc[j][2], acc[j][3]);
        }
    }
    __syncthreads();

    for (int rr = wid; rr < 32; rr += 8) {
        int n = n0 + rr;
        bool pn = pmask[b * NN + n] != 0;
        const float* lrow = logits + rr * LSTRIDE;
        long long goff = (((long long)(b * NH + h)) * NN + n) * NEXT;

        float val[24];
        float mx = -FLT_MAX;
        #pragma unroll
        for (int t = 0; t < 24; t++) {
            int m = lane + (t << 5);
            bool fm = (m < NN) ? (pmask[b * NN + m] != 0)
                               : (emask[b * NM + m - NN] != 0);
            float v = lrow[m] + bias[goff + m];
            if (pn || fm) v = -FLT_MAX;
            val[t] = v;
            mx = fmaxf(mx, v);
        }
        #pragma unroll
        for (int o = 16; o > 0; o >>= 1)
            mx = fmaxf(mx, __shfl_xor_sync(0xffffffffu, mx, o));
        float s = 0.f;
        #pragma unroll
        for (int t = 0; t < 24; t++) {
            val[t] = expf(val[t] - mx);
            s += val[t];
        }
        #pragma unroll
        for (int o = 16; o > 0; o >>= 1)
            s += __shfl_xor_sync(0xffffffffu, s, o);
        float inv = 1.f / s;
        #pragma unroll
        for (int t = 0; t < 24; t++)
            g_attn[goff + lane + (t << 5)] = val[t] * inv;
    }
}

// ============================================================================
// Fused PV + vec (delta precomputed, term-outermost MMAs)
// ============================================================================
#define PV_A    4608
#define PV_VB   36864
#define PV_B    2304
#define PV_SMEM 92160

__global__ __launch_bounds__(256, 2) void pv_mma(const float* __restrict__ delta,
                                                 const int*   __restrict__ oidx,
                                                 const __nv_bfloat16* __restrict__ vh_g,
                                                 const __nv_bfloat16* __restrict__ vl_g,
                                                 const __nv_bfloat16* __restrict__ veh_g,
                                                 const __nv_bfloat16* __restrict__ vel_g,
                                                 __nv_bfloat16* __restrict__ outh,
                                                 __nv_bfloat16* __restrict__ outl)
{
    extern __shared__ __nv_bfloat16 sp[];

    const int tid  = threadIdx.x;
    const int wid  = tid >> 5;
    const int lane = tid & 31;
    const int g    = lane >> 2;
    const int tig  = lane & 3;
    const int b    = blockIdx.z;
    const int h    = blockIdx.y;
    const int n0   = blockIdx.x << 6;

    const int rowblk = (wid & 3) << 4;
    const int pair   = wid >> 2;

    __nv_bfloat16* VEh = sp + PV_VB;
    __nv_bfloat16* VEl = VEh + PV_B;
    __nv_bfloat16* Vh  = VEh + 2 * PV_B;
    __nv_bfloat16* Vl  = VEh + 3 * PV_B;

    const uint32_t spb = smem_u32(sp);
    const uint32_t a_offp = ((rowblk + (lane & 7) + (((lane >> 3) & 1) << 3)) * 72
                             + ((lane >> 4) << 3)) * 2;
    const uint32_t b_offp = (((lane & 7) + ((lane >> 4) << 3)) * 72
                             + (((lane >> 3) & 1) << 3)) * 2;
    const uint32_t A0u = spb + (((pair == 0) ? 0 : 4) * PV_A) * 2 + a_offp;
    const uint32_t A1u = spb + (((pair == 0) ? 2 : 6) * PV_A) * 2 + a_offp;
    const uint32_t Bvb = spb + PV_VB * 2;
    const uint32_t B0u = ((pair == 0) ? Bvb : Bvb + 2 * PV_B * 2) + b_offp;
    const uint32_t B1u = Bvb + 2 * PV_B * 2 + b_offp;

    float acc0[4][4], acc1[4][4];
    #pragma unroll
    for (int j = 0; j < 4; j++)
        #pragma unroll
        for (int q = 0; q < 4; q++) { acc0[j][q] = 0.f; acc1[j][q] = 0.f; }

    const int p_n  = tid >> 2;
    const int p_mb = (tid & 3) << 4;
    const size_t drow = ((size_t)(b * NN + n0 + p_n) * 3) * NEXT;

    for (int m0 = 0; m0 < NEXT; m0 += 64) {
        __syncthreads();
        // ---- phase 1a: P tile * precomputed delta -> 4 scaled A mats ----
        {
            const float* prow = g_attn +
                (((long long)(b * NH + h)) * NN + n0 + p_n) * NEXT + m0 + p_mb;
            float P[16], dxv[16], dyv[16], dzv[16];
            #pragma unroll
            for (int q4 = 0; q4 < 4; q4++) {
                *(float4*)(P   + q4*4) = *(const float4*)(prow + q4*4);
                *(float4*)(dxv + q4*4) = *(const float4*)(delta + drow            + m0 + p_mb + q4*4);
                *(float4*)(dyv + q4*4) = *(const float4*)(delta + drow +     NEXT + m0 + p_mb + q4*4);
                *(float4*)(dzv + q4*4) = *(const float4*)(delta + drow + 2 * NEXT + m0 + p_mb + q4*4);
            }
            int base = p_n * 72 + p_mb;
            #pragma unroll
            for (int qp = 0; qp < 8; qp++) {
                float p0 = P[2*qp], p1 = P[2*qp+1];
                uint32_t hi, lo;
                split2(p0, p1, hi, lo);
                *(uint32_t*)(sp + 0 * PV_A + base + 2*qp) = hi;
                *(uint32_t*)(sp + 1 * PV_A + base + 2*qp) = lo;
                split2(p0 * dxv[2*qp], p1 * dxv[2*qp+1], hi, lo);
                *(uint32_t*)(sp + 2 * PV_A + base + 2*qp) = hi;
                *(uint32_t*)(sp + 3 * PV_A + base + 2*qp) = lo;
                split2(p0 * dyv[2*qp], p1 * dyv[2*qp+1], hi, lo);
                *(uint32_t*)(sp + 4 * PV_A + base + 2*qp) = hi;
                *(uint32_t*)(sp + 5 * PV_A + base + 2*qp) = lo;
                split2(p0 * dzv[2*qp], p1 * dzv[2*qp+1], hi, lo);
                *(uint32_t*)(sp + 6 * PV_A + base + 2*qp) = hi;
                *(uint32_t*)(sp + 7 * PV_A + base + 2*qp) = lo;
            }
        }
        // ---- phase 1b: v / ve tiles transposed into B mats ----
        {
            int d  = tid & 31;
            int mq = tid >> 5;
            #pragma unroll
            for (int s = 0; s < 8; s++) {
                int m = (mq << 3) + s;
                int mg = m0 + m;
                int row = (mg < NN) ? mg : oidx[b * NM + mg - NN];
                size_t off = (size_t)(b * NN + row) * NE + h * ND + d;
                VEh[d * 72 + m] = veh_g[off];
                VEl[d * 72 + m] = vel_g[off];
                Vh [d * 72 + m] = vh_g [off];
                Vl [d * 72 + m] = vl_g [off];
            }
        }
        __syncthreads();

        // ---- phase 2: MMAs (ldmatrix fragments, term-outermost) ----
        #pragma unroll
        for (int o = 0; o < 2; o++) {
            const uint32_t Au = o ? A1u : A0u;
            const uint32_t Bu = o ? B1u : B0u;
            float (*acc)[4] = o ? acc1 : acc0;
            #pragma unroll
            for (int kk = 0; kk < 4; kk++) {
                const uint32_t kwb = kk << 5;
                uint32_t ah[4], al[4], bh[4][2], bl[4][2];
                ldsm4(ah[0], ah[1], ah[2], ah[3], Au + kwb);
                ldsm4(al[0], al[1], al[2], al[3], Au + PV_A * 2 + kwb);
                #pragma unroll
                for (int jp = 0; jp < 2; jp++) {
                    ldsm4(bh[2*jp][0], bh[2*jp][1], bh[2*jp+1][0], bh[2*jp+1][1],
                          Bu + jp * 2304 + kwb);
                    ldsm4(bl[2*jp][0], bl[2*jp][1], bl[2*jp+1][0], bl[2*jp+1][1],
                          Bu + PV_B * 2 + jp * 2304 + kwb);
                }
                #pragma unroll
                for (int j = 0; j < 4; j++) mma16816(acc[j], ah, bh[j]);
                #pragma unroll
                for (int j = 0; j < 4; j++) mma16816(acc[j], ah, bl[j]);
                #pragma unroll
                for (int j = 0; j < 4; j++) mma16816(acc[j], al, bh[j]);
            }
        }
    }

    // ---- epilogue ----
    const int r0g = n0 + rowblk + g;
    #pragma unroll
    for (int j = 0; j < 4; j++) {
        int col = h * ND + (j << 3) + (tig << 1);
        uint32_t hi, lo;
        if (pair == 0) {
            size_t ro0 = (size_t)(b * NN + r0g) * NE + col;
            size_t ro1 = (size_t)(b * NN + r0g + 8) * NE + col;
            split2(acc0[j][0], acc0[j][1], hi, lo);
            *(uint32_t*)(outh + ro0) = hi; *(uint32_t*)(outl + ro0) = lo;
            split2(acc0[j][2], acc0[j][3], hi, lo);
            *(uint32_t*)(outh + ro1) = hi; *(uint32_t*)(outl + ro1) = lo;
            size_t vo0 = VOFF + ((size_t)(b * NN + r0g) * 3 + 0) * NE + col;
            size_t vo1 = VOFF + ((size_t)(b * NN + r0g + 8) * 3 + 0) * NE + col;
            split2(acc1[j][0], acc1[j][1], hi, lo);
            *(uint32_t*)(outh + vo0) = hi; *(uint32_t*)(outl + vo0) = lo;
            split2(acc1[j][2], acc1[j][3], hi, lo);
            *(uint32_t*)(outh + vo1) = hi; *(uint32_t*)(outl + vo1) = lo;
        } else {
            size_t vo0 = VOFF + ((size_t)(b * NN + r0g) * 3 + 1) * NE + col;
            size_t vo1 = VOFF + ((size_t)(b * NN + r0g + 8) * 3 + 1) * NE + col;
            split2(acc0[j][0], acc0[j][1], hi, lo);
            *(uint32_t*)(outh + vo0) = hi; *(uint32_t*)(outl + vo0) = lo;
            split2(acc0[j][2], acc0[j][3], hi, lo);
            *(uint32_t*)(outh + vo1) = hi; *(uint32_t*)(outl + vo1) = lo;
            size_t wo0 = VOFF + ((size_t)(b * NN + r0g) * 3 + 2) * NE + col;
            size_t wo1 = VOFF + ((size_t)(b * NN + r0g + 8) * 3 + 2) * NE + col;
            split2(acc1[j][0], acc1[j][1], hi, lo);
            *(uint32_t*)(outh + wo0) = hi; *(uint32_t*)(outl + wo0) = lo;
            split2(acc1[j][2], acc1[j][3], hi, lo);
            *(uint32_t*)(outh + wo1) = hi; *(uint32_t*)(outl + wo1) = lo;
        }
    }
}

// ============================================================================
// launch
// ============================================================================
extern "C" void kernel_launch(void* const* d_in, const int* in_sizes, int n_in,
                              void* d_out, int out_size)
{
    const float* x    = (const float*)d_in[0];
    const float* pos  = (const float*)d_in[1];
    const float* epos = (const float*)d_in[2];
    const float* bias = (const float*)d_in[3];
    const unsigned char* pmask = (const unsigned char*)d_in[4];
    const unsigned char* emask = (const unsigned char*)d_in[5];
    const int*   oidx = (const int*)d_in[6];
    const float* Wq   = (const float*)d_in[7];
    const float* Wk   = (const float*)d_in[8];
    const float* Wv   = (const float*)d_in[9];
    const float* Wve  = (const float*)d_in[10];
    const float* Wo   = (const float*)d_in[11];
    const float* Woe  = (const float*)d_in[12];
    float* out = (float*)d_out;

    __nv_bfloat16 *ah, *al, *wh, *wl, *ph, *pl;
    float *dlt;
    cudaGetSymbolAddress((void**)&ah,  g_ah);
    cudaGetSymbolAddress((void**)&al,  g_al);
    cudaGetSymbolAddress((void**)&wh,  g_wh);
    cudaGetSymbolAddress((void**)&wl,  g_wl);
    cudaGetSymbolAddress((void**)&ph,  g_projh);
    cudaGetSymbolAddress((void**)&pl,  g_projl);
    cudaGetSymbolAddress((void**)&dlt, g_delta);

    cudaFuncSetAttribute(gemm_mma,   cudaFuncAttributeMaxDynamicSharedMemorySize, GSMEM_BYTES);
    cudaFuncSetAttribute(qk_softmax, cudaFuncAttributeMaxDynamicSharedMemorySize, QK_SMEM);
    cudaFuncSetAttribute(pv_mma,     cudaFuncAttributeMaxDynamicSharedMemorySize, PV_SMEM);

    const int WSZ = 1024 * 1024;

    // 1) converters + delta precompute
    cvt_split_x<<<2048, 256>>>(x, ah, al);
    cvt_split_w<<<dim3(1024, 6), 256>>>(Wq, Wk, Wv, Wve, Woe, Wo, wh, wl);
    delta_pre<<<6144, 256>>>(pos, epos, pmask, emask, dlt);

    // 2) projections -> bf16 hi/lo (mode 1)
    gemm_mma<<<dim3(8, 16, 4), 256, GSMEM_BYTES>>>(ah, al, wh, wl,
                                                   nullptr, nullptr, 1024,
                                                   nullptr, ph, pl, SCALING_F, 1);

    // 3) fused QK + softmax (32-row tiles, 2 CTA/SM)
    qk_softmax<<<dim3(8, 256), 256, QK_SMEM>>>(bias, oidx, pmask, emask,
                                               ph, pl, ph + PSZ, pl + PSZ);

    // 4) fused PV + vec -> bf16 hi/lo A-buffers (delta precomputed)
    pv_mma<<<dim3(4, 32, 8), 256, PV_SMEM>>>(dlt, oidx,
                                             ph + 2*PSZ, pl + 2*PSZ,
                                             ph + 3*PSZ, pl + 3*PSZ,
                                             ah, al);

    // 5) fused output GEMMs
    gemm_mma<<<dim3(8, 64, 1), 256, GSMEM_BYTES>>>(ah, al,
                                                   wh + 4*WSZ, wl + 4*WSZ,
                                                   wh + 5*WSZ, wl + 5*WSZ, 16,
                                                   out, nullptr, nullptr, 1.0f, 0);
}

// round 11
// speedup vs baseline: 1.3611x; 1.0290x over previous
#include <cuda_runtime.h>
#include <cuda_bf16.h>
#include <float.h>
#include <math.h>
#include <stdint.h>

// Problem constants
#define NB 8
#define NN 256
#define NM 512
#define NE 1024
#define NH 32
#define ND 32
#define NEXT 768   // N + M

#define SCALING_F 0.17677669529663687f  // 32^-0.5

// ---------------- device scratch ----------------
static __device__ float g_attn[(long long)NB*NH*NN*NEXT];   // probs (fp32)
static __device__ float g_delta[(long long)NB*NN*3*NEXT];   // masked delta [b,n,c,m]
static __device__ __nv_bfloat16 g_ah[8192LL*1024];
static __device__ __nv_bfloat16 g_al[8192LL*1024];
static __device__ __nv_bfloat16 g_wh[6LL*1024*1024];
static __device__ __nv_bfloat16 g_wl[6LL*1024*1024];
static __device__ __nv_bfloat16 g_projh[4LL*2048*1024];
static __device__ __nv_bfloat16 g_projl[4LL*2048*1024];
#define PSZ 2097152
#define VOFF 2097152

// ============================================================================
// helpers
// ============================================================================
__device__ __forceinline__ uint32_t smem_u32(const void* p) {
    uint32_t a;
    asm("{ .reg .u64 t; cvta.to.shared.u64 t, %1; cvt.u32.u64 %0, t; }"
        : "=r"(a) : "l"(p));
    return a;
}
#define CP_ASYNC16(sa, ga) \
    asm volatile("cp.async.cg.shared.global [%0], [%1], 16;\n" :: "r"(sa), "l"(ga))
#define CP_COMMIT() asm volatile("cp.async.commit_group;\n" ::: "memory")
#define CP_WAIT(n)  asm volatile("cp.async.wait_group %0;\n" :: "n"(n) : "memory")

__device__ __forceinline__ void mma16816(float* c, const uint32_t* a, const uint32_t* b) {
    asm volatile(
        "mma.sync.aligned.m16n8k16.row.col.f32.bf16.bf16.f32 "
        "{%0,%1,%2,%3}, {%4,%5,%6,%7}, {%8,%9}, {%0,%1,%2,%3};\n"
        : "+f"(c[0]), "+f"(c[1]), "+f"(c[2]), "+f"(c[3])
        : "r"(a[0]), "r"(a[1]), "r"(a[2]), "r"(a[3]), "r"(b[0]), "r"(b[1]));
}
__device__ __forceinline__ void ldsm4(uint32_t& r0, uint32_t& r1, uint32_t& r2,
                                      uint32_t& r3, uint32_t a) {
    asm volatile("ldmatrix.sync.aligned.m8n8.x4.shared.b16 {%0,%1,%2,%3}, [%4];"
                 : "=r"(r0), "=r"(r1), "=r"(r2), "=r"(r3) : "r"(a));
}
// fast split: packed bf16x2 cvt (round-to-nearest-even, bit-identical to
// __float2bfloat16); hi word = {lo16: bf16(a), hi16: bf16(b)}
__device__ __forceinline__ void split2(float a, float b, uint32_t& hi, uint32_t& lo) {
    asm("cvt.rn.bf16x2.f32 %0, %1, %2;" : "=r"(hi) : "f"(b), "f"(a));
    float ha = __uint_as_float(hi << 16);
    float hb = __uint_as_float(hi & 0xffff0000u);
    asm("cvt.rn.bf16x2.f32 %0, %1, %2;" : "=r"(lo) : "f"(b - hb), "f"(a - ha));
}
__device__ __forceinline__ float sqrt_approx(float x) {
    float r;
    asm("sqrt.approx.f32 %0, %1;" : "=f"(r) : "f"(x));
    return r;
}
__device__ __forceinline__ float rcp_approx(float x) {
    float r;
    asm("rcp.approx.f32 %0, %1;" : "=f"(r) : "f"(x));
    return r;
}

// ============================================================================
// converters
// ============================================================================
__global__ __launch_bounds__(256) void cvt_split_x(const float* __restrict__ src,
                                                   __nv_bfloat16* __restrict__ hi,
                                                   __nv_bfloat16* __restrict__ lo)
{
    int i = blockIdx.x * 256 + threadIdx.x;
    int r  = i >> 8;
    int e4 = (i & 255) << 2;
    int b = r >> 8, n = r & 255;
    float4 v = *(const float4*)(src + ((long long)n * NB + b) * NE + e4);
    uint32_t h0, l0, h1, l1;
    split2(v.x, v.y, h0, l0);
    split2(v.z, v.w, h1, l1);
    ((uint2*)hi)[i] = make_uint2(h0, h1);
    ((uint2*)lo)[i] = make_uint2(l0, l1);
}

__global__ __launch_bounds__(256) void cvt_split_w(const float* __restrict__ W0,
                                                   const float* __restrict__ W1,
                                                   const float* __restrict__ W2,
                                                   const float* __restrict__ W3,
                                                   const float* __restrict__ W4,
                                                   const float* __restrict__ W5,
                                                   __nv_bfloat16* __restrict__ hi,
                                                   __nv_bfloat16* __restrict__ lo)
{
    int w = blockIdx.y;
    const float* src = (w == 0) ? W0 : (w == 1) ? W1 : (w == 2) ? W2
                     : (w == 3) ? W3 : (w == 4) ? W4 : W5;
    int i = blockIdx.x * 256 + threadIdx.x;
    float4 v = ((const float4*)src)[i];
    uint32_t h0, l0, h1, l1;
    split2(v.x, v.y, h0, l0);
    split2(v.z, v.w, h1, l1);
    size_t o = ((size_t)w << 18) + i;
    ((uint2*)hi)[o] = make_uint2(h0, h1);
    ((uint2*)lo)[o] = make_uint2(l0, l1);
}

// ============================================================================
// Precompute masked delta [b,n,c,m]
// ============================================================================
__global__ __launch_bounds__(256) void delta_pre(const float* __restrict__ pos,
                                                 const float* __restrict__ epos,
                                                 const unsigned char* __restrict__ pmask,
                                                 const unsigned char* __restrict__ emask,
                                                 float* __restrict__ delta)
{
    int i = blockIdx.x * 256 + threadIdx.x;
    int m = i % NEXT;
    int n = (i / NEXT) % NN;
    int b = i / (NEXT * NN);

    float pxn = pos[(b * NN + n) * 3 + 0];
    float pyn = pos[(b * NN + n) * 3 + 1];
    float pzn = pos[(b * NN + n) * 3 + 2];
    bool  pn  = pmask[b * NN + n] != 0;

    float ax, ay, az; bool fm;
    if (m < NN) {
        const float* pp = pos + (b * NN + m) * 3;
        ax = pp[0]; ay = pp[1]; az = pp[2];
        fm = pmask[b * NN + m] != 0;
    } else {
        const float* pp = epos + (b * NM + m - NN) * 3;
        ax = pp[0]; ay = pp[1]; az = pp[2];
        fm = emask[b * NM + m - NN] != 0;
    }
    float dx = pxn - ax, dy = pyn - ay, dz = pzn - az;
    float dist = sqrt_approx(dx * dx + dy * dy + dz * dz);
    if (pn || fm) dist = 1e6f;
    float inv = rcp_approx(dist + 1.f);
    if (pn) inv = 0.f;

    size_t base = ((size_t)(b * NN + n) * 3) * NEXT + m;
    delta[base           ] = dx * inv;
    delta[base +     NEXT] = dy * inv;
    delta[base + 2 * NEXT] = dz * inv;
}

// ============================================================================
// Tensor-core split-precision GEMM
// ============================================================================
#define TILE_ELE 5120
#define STAGE_ELE 20480
#define GSMEM_BYTES 81920

__global__ __launch_bounds__(256, 2) void gemm_mma(const __nv_bfloat16* __restrict__ Ah,
                                                   const __nv_bfloat16* __restrict__ Al,
                                                   const __nv_bfloat16* __restrict__ Bh,
                                                   const __nv_bfloat16* __restrict__ Bl,
                                                   const __nv_bfloat16* __restrict__ Bh2,
                                                   const __nv_bfloat16* __restrict__ Bl2,
                                                   int ysplit,
                                                   float* __restrict__ C,
                                                   __nv_bfloat16* __restrict__ Ch,
                                                   __nv_bfloat16* __restrict__ Cl,
                                                   float alpha0, int mode)
{
    extern __shared__ __nv_bfloat16 sm[];

    const int tid  = threadIdx.x;
    const int wid  = tid >> 5;
    const int lane = tid & 31;
    const int g    = lane >> 2;
    const int tig  = lane & 3;
    const int row0 = blockIdx.y << 7;
    const int col0 = blockIdx.x << 7;
    const int z    = blockIdx.z;
    if ((int)blockIdx.y >= ysplit) { Bh = Bh2; Bl = Bl2; }
    Bh += (size_t)z << 20;
    Bl += (size_t)z << 20;
    if (mode == 0) C += (size_t)z << 21;
    else { Ch += (size_t)z << 21; Cl += (size_t)z << 21; }
    const float alpha = (z == 0) ? alpha0 : 1.0f;
    const int wm = (wid & 1) << 6;
    const int wn = (wid >> 1) << 5;

    float acc[4][4][4];
    #pragma unroll
    for (int i = 0; i < 4; i++)
        #pragma unroll
        for (int j = 0; j < 4; j++)
            #pragma unroll
            for (int q = 0; q < 4; q++) acc[i][j][q] = 0.f;

    const uint32_t smbase = smem_u32(sm);
    const uint32_t a_off = ((wm + (lane & 7) + (((lane >> 3) & 1) << 3)) * 40
                            + ((lane >> 4) << 3)) * 2;
    const uint32_t b_off = ((wn + (lane & 7) + ((lane >> 4) << 3)) * 40
                            + (((lane >> 3) & 1) << 3)) * 2;

    #define LOAD_CHUNK(kc, s)                                                     \
    {                                                                             \
        _Pragma("unroll")                                                         \
        for (int t = 0; t < 8; t++) {                                             \
            int u    = tid + (t << 8);                                            \
            int tile = u >> 9;                                                    \
            int r    = (u >> 2) & 127;                                            \
            int cu   = u & 3;                                                     \
            const __nv_bfloat16* gp;                                              \
            if      (tile == 0) gp = Ah + (size_t)(row0 + r) * 1024;              \
            else if (tile == 1) gp = Al + (size_t)(row0 + r) * 1024;              \
            else if (tile == 2) gp = Bh + (size_t)(col0 + r) * 1024;              \
            else                gp = Bl + (size_t)(col0 + r) * 1024;              \
            gp += (kc) * 32 + cu * 8;                                             \
            uint32_t sa = smbase +                                                \
                (uint32_t)(((s) * STAGE_ELE + tile * TILE_ELE + r * 40 + cu * 8) * 2); \
            CP_ASYNC16(sa, gp);                                                   \
        }                                                                         \
    }

    LOAD_CHUNK(0, 0);
    CP_COMMIT();

    for (int kc = 0; kc < 32; kc++) {
        CP_WAIT(0);
        __syncthreads();
        if (kc + 1 < 32) {
            LOAD_CHUNK(kc + 1, (kc + 1) & 1);
            CP_COMMIT();
        }

        const uint32_t so2 = (kc & 1) * (STAGE_ELE * 2);
        const uint32_t abase = smbase + so2 + a_off;
        const uint32_t bbase = smbase + so2 + 2 * TILE_ELE * 2 + b_off;

        #pragma unroll
        for (int kk = 0; kk < 2; kk++) {
            const uint32_t kwb = kk << 5;
            uint32_t ah[4][4], al[4][4], bh[4][2], bl[4][2];
            #pragma unroll
            for (int i = 0; i < 4; i++) {
                ldsm4(ah[i][0], ah[i][1], ah[i][2], ah[i][3],
                      abase + i * 1280 + kwb);
                ldsm4(al[i][0], al[i][1], al[i][2], al[i][3],
                      abase + TILE_ELE * 2 + i * 1280 + kwb);
            }
            #pragma unroll
            for (int jp = 0; jp < 2; jp++) {
                ldsm4(bh[2*jp][0], bh[2*jp][1], bh[2*jp+1][0], bh[2*jp+1][1],
                      bbase + jp * 1280 + kwb);
                ldsm4(bl[2*jp][0], bl[2*jp][1], bl[2*jp+1][0], bl[2*jp+1][1],
                      bbase + TILE_ELE * 2 + jp * 1280 + kwb);
            }
            #pragma unroll
            for (int i = 0; i < 4; i++)
                #pragma unroll
                for (int j = 0; j < 4; j++)
                    mma16816(acc[i][j], ah[i], bh[j]);
            #pragma unroll
            for (int i = 0; i < 4; i++)
                #pragma unroll
                for (int j = 0; j < 4; j++)
                    mma16816(acc[i][j], ah[i], bl[j]);
            #pragma unroll
            for (int i = 0; i < 4; i++)
                #pragma unroll
                for (int j = 0; j < 4; j++)
                    mma16816(acc[i][j], al[i], bh[j]);
        }
    }

    #pragma unroll
    for (int i = 0; i < 4; i++) {
        int row = row0 + wm + (i << 4) + g;
        #pragma unroll
        for (int j = 0; j < 4; j++) {
            int col = col0 + wn + (j << 3) + (tig << 1);
            float v0 = alpha * acc[i][j][0];
            float v1 = alpha * acc[i][j][1];
            float v2 = alpha * acc[i][j][2];
            float v3 = alpha * acc[i][j][3];
            if (mode == 0) {
                *(float2*)(C + (size_t)row * 1024 + col)       = make_float2(v0, v1);
                *(float2*)(C + (size_t)(row + 8) * 1024 + col) = make_float2(v2, v3);
            } else {
                uint32_t h0, l0, h1, l1;
                split2(v0, v1, h0, l0);
                split2(v2, v3, h1, l1);
                *(uint32_t*)(Ch + (size_t)row * 1024 + col)       = h0;
                *(uint32_t*)(Cl + (size_t)row * 1024 + col)       = l0;
                *(uint32_t*)(Ch + (size_t)(row + 8) * 1024 + col) = h1;
                *(uint32_t*)(Cl + (size_t)(row + 8) * 1024 + col) = l1;
            }
        }
    }
}

// ============================================================================
// Fused QK^T + bias + mask + softmax (32-row tile, 2 CTA/SM, __expf)
// ============================================================================
#define LSTRIDE 772
#define QK_SMEM 114176

__global__ __launch_bounds__(256, 2) void qk_softmax(const float* __restrict__ bias,
                                                  const int*   __restrict__ oidx,
                                                  const unsigned char* __restrict__ pmask,
                                                  const unsigned char* __restrict__ emask,
                                                  const __nv_bfloat16* __restrict__ qh_g,
                                                  const __nv_bfloat16* __restrict__ ql_g,
                                                  const __nv_bfloat16* __restrict__ kh_g,
                                                  const __nv_bfloat16* __restrict__ kl_g)
{
    extern __shared__ char sraw[];
    __nv_bfloat16* sqh = (__nv_bfloat16*)sraw;
    __nv_bfloat16* sql = sqh + 1280;
    __nv_bfloat16* skh = sqh + 2560;
    __nv_bfloat16* skl = sqh + 5120;
    float* logits = (float*)(sraw + 15360);

    const int tid  = threadIdx.x;
    const int wid  = tid >> 5;
    const int lane = tid & 31;
    const int g    = lane >> 2;
    const int tig  = lane & 3;
    const int bh   = blockIdx.y;
    const int b    = bh >> 5;
    const int h    = bh & 31;
    const int n0   = blockIdx.x << 5;

    if (tid < 128) {
        int r = tid >> 2, c = (tid & 3) << 3;
        size_t off = (size_t)(b * NN + n0 + r) * NE + h * ND + c;
        *(uint4*)(sqh + r * 40 + c) = *(const uint4*)(qh_g + off);
        *(uint4*)(sql + r * 40 + c) = *(const uint4*)(ql_g + off);
    }

    const int wn = (wid & 1) << 4;
    const int wm = (wid >> 1) << 4;

    for (int m0 = 0; m0 < NEXT; m0 += 64) {
        __syncthreads();
        {
            int r = tid >> 2, c = (tid & 3) << 3;
            int m = m0 + r;
            int row = (m < NN) ? m : oidx[b * NM + m - NN];
            size_t off = (size_t)(b * NN + row) * NE + h * ND + c;
            *(uint4*)(skh + r * 40 + c) = *(const uint4*)(kh_g + off);
            *(uint4*)(skl + r * 40 + c) = *(const uint4*)(kl_g + off);
        }
        __syncthreads();

        float acc[2][4];
        #pragma unroll
        for (int j = 0; j < 2; j++)
            #pragma unroll
            for (int q = 0; q < 4; q++) acc[j][q] = 0.f;

        #pragma unroll
        for (int kk = 0; kk < 2; kk++) {
            const int kw = kk << 3;
            uint32_t a_h[4], a_l[4], bhf[2][2], blf[2][2];
            {
                int rA = wn + g;
                a_h[0] = *(const uint32_t*)(sqh + (rA    ) * 40 + ((kw + tig    ) << 1));
                a_h[1] = *(const uint32_t*)(sqh + (rA + 8) * 40 + ((kw + tig    ) << 1));
                a_h[2] = *(const uint32_t*)(sqh + (rA    ) * 40 + ((kw + tig + 4) << 1));
                a_h[3] = *(const uint32_t*)(sqh + (rA + 8) * 40 + ((kw + tig + 4) << 1));
                a_l[0] = *(const uint32_t*)(sql + (rA    ) * 40 + ((kw + tig    ) << 1));
                a_l[1] = *(const uint32_t*)(sql + (rA + 8) * 40 + ((kw + tig    ) << 1));
                a_l[2] = *(const uint32_t*)(sql + (rA    ) * 40 + ((kw + tig + 4) << 1));
                a_l[3] = *(const uint32_t*)(sql + (rA + 8) * 40 + ((kw + tig + 4) << 1));
            }
            #pragma unroll
            for (int j = 0; j < 2; j++) {
                int rB = wm + (j << 3) + g;
                bhf[j][0] = *(const uint32_t*)(skh + rB * 40 + ((kw + tig    ) << 1));
                bhf[j][1] = *(const uint32_t*)(skh + rB * 40 + ((kw + tig + 4) << 1));
                blf[j][0] = *(const uint32_t*)(skl + rB * 40 + ((kw + tig    ) << 1));
                blf[j][1] = *(const uint32_t*)(skl + rB * 40 + ((kw + tig + 4) << 1));
            }
            #pragma unroll
            for (int j = 0; j < 2; j++) mma16816(acc[j], a_h, bhf[j]);
            #pragma unroll
            for (int j = 0; j < 2; j++) mma16816(acc[j], a_h, blf[j]);
            #pragma unroll
            for (int j = 0; j < 2; j++) mma16816(acc[j], a_l, bhf[j]);
        }

        #pragma unroll
        for (int j = 0; j < 2; j++) {
            int col = m0 + wm + (j << 3) + (tig << 1);
            int row = wn + g;
            *(float2*)&logits[row * LSTRIDE + col]       = make_float2(acc[j][0], acc[j][1]);
            *(float2*)&logits[(row + 8) * LSTRIDE + col] = make_float2(acc[j][2], acc[j][3]);
        }
    }
    __syncthreads();

    for (int rr = wid; rr < 32; rr += 8) {
        int n = n0 + rr;
        bool pn = pmask[b * NN + n] != 0;
        const float* lrow = logits + rr * LSTRIDE;
        long long goff = (((long long)(b * NH + h)) * NN + n) * NEXT;

        float val[24];
        float mx = -FLT_MAX;
        #pragma unroll
        for (int t = 0; t < 24; t++) {
            int m = lane + (t << 5);
            bool fm = (m < NN) ? (pmask[b * NN + m] != 0)
                               : (emask[b * NM + m - NN] != 0);
            float v = lrow[m] + bias[goff + m];
            if (pn || fm) v = -FLT_MAX;
            val[t] = v;
            mx = fmaxf(mx, v);
        }
        #pragma unroll
        for (int o = 16; o > 0; o >>= 1)
            mx = fmaxf(mx, __shfl_xor_sync(0xffffffffu, mx, o));
        float s = 0.f;
        #pragma unroll
        for (int t = 0; t < 24; t++) {
            val[t] = __expf(val[t] - mx);
            s += val[t];
        }
        #pragma unroll
        for (int o = 16; o > 0; o >>= 1)
            s += __shfl_xor_sync(0xffffffffu, s, o);
        float inv = 1.f / s;
        #pragma unroll
        for (int t = 0; t < 24; t++)
            g_attn[goff + lane + (t << 5)] = val[t] * inv;
    }
}

// ============================================================================
// Fused PV + vec (delta precomputed, vectorized V/VE gather, fast split2)
// ============================================================================
#define PV_A    4608
#define PV_VB   36864
#define PV_B    2304
#define PV_SMEM 92160

__global__ __launch_bounds__(256, 2) void pv_mma(const float* __restrict__ delta,
                                                 const int*   __restrict__ oidx,
                                                 const __nv_bfloat16* __restrict__ vh_g,
                                                 const __nv_bfloat16* __restrict__ vl_g,
                                                 const __nv_bfloat16* __restrict__ veh_g,
                                                 const __nv_bfloat16* __restrict__ vel_g,
                                                 __nv_bfloat16* __restrict__ outh,
                                                 __nv_bfloat16* __restrict__ outl)
{
    extern __shared__ __nv_bfloat16 sp[];

    const int tid  = threadIdx.x;
    const int wid  = tid >> 5;
    const int lane = tid & 31;
    const int g    = lane >> 2;
    const int tig  = lane & 3;
    const int b    = blockIdx.z;
    const int h    = blockIdx.y;
    const int n0   = blockIdx.x << 6;

    const int rowblk = (wid & 3) << 4;
    const int pair   = wid >> 2;

    __nv_bfloat16* VEh = sp + PV_VB;
    __nv_bfloat16* VEl = VEh + PV_B;
    __nv_bfloat16* Vh  = VEh + 2 * PV_B;
    __nv_bfloat16* Vl  = VEh + 3 * PV_B;

    const uint32_t spb = smem_u32(sp);
    const uint32_t a_offp = ((rowblk + (lane & 7) + (((lane >> 3) & 1) << 3)) * 72
                             + ((lane >> 4) << 3)) * 2;
    const uint32_t b_offp = (((lane & 7) + ((lane >> 4) << 3)) * 72
                             + (((lane >> 3) & 1) << 3)) * 2;
    const uint32_t A0u = spb + (((pair == 0) ? 0 : 4) * PV_A) * 2 + a_offp;
    const uint32_t A1u = spb + (((pair == 0) ? 2 : 6) * PV_A) * 2 + a_offp;
    const uint32_t Bvb = spb + PV_VB * 2;
    const uint32_t B0u = ((pair == 0) ? Bvb : Bvb + 2 * PV_B * 2) + b_offp;
    const uint32_t B1u = Bvb + 2 * PV_B * 2 + b_offp;

    float acc0[4][4], acc1[4][4];
    #pragma unroll
    for (int j = 0; j < 4; j++)
        #pragma unroll
        for (int q = 0; q < 4; q++) { acc0[j][q] = 0.f; acc1[j][q] = 0.f; }

    const int p_n  = tid >> 2;
    const int p_mb = (tid & 3) << 4;
    const size_t drow = ((size_t)(b * NN + n0 + p_n) * 3) * NEXT;

    for (int m0 = 0; m0 < NEXT; m0 += 64) {
        __syncthreads();
        // ---- phase 1a: P tile * precomputed delta -> 4 scaled A mats ----
        {
            const float* prow = g_attn +
                (((long long)(b * NH + h)) * NN + n0 + p_n) * NEXT + m0 + p_mb;
            float P[16], dxv[16], dyv[16], dzv[16];
            #pragma unroll
            for (int q4 = 0; q4 < 4; q4++) {
                *(float4*)(P   + q4*4) = *(const float4*)(prow + q4*4);
                *(float4*)(dxv + q4*4) = *(const float4*)(delta + drow            + m0 + p_mb + q4*4);
                *(float4*)(dyv + q4*4) = *(const float4*)(delta + drow +     NEXT + m0 + p_mb + q4*4);
                *(float4*)(dzv + q4*4) = *(const float4*)(delta + drow + 2 * NEXT + m0 + p_mb + q4*4);
            }
            int base = p_n * 72 + p_mb;
            #pragma unroll
            for (int qp = 0; qp < 8; qp++) {
                float p0 = P[2*qp], p1 = P[2*qp+1];
                uint32_t hi, lo;
                split2(p0, p1, hi, lo);
                *(uint32_t*)(sp + 0 * PV_A + base + 2*qp) = hi;
                *(uint32_t*)(sp + 1 * PV_A + base + 2*qp) = lo;
                split2(p0 * dxv[2*qp], p1 * dxv[2*qp+1], hi, lo);
                *(uint32_t*)(sp + 2 * PV_A + base + 2*qp) = hi;
                *(uint32_t*)(sp + 3 * PV_A + base + 2*qp) = lo;
                split2(p0 * dyv[2*qp], p1 * dyv[2*qp+1], hi, lo);
                *(uint32_t*)(sp + 4 * PV_A + base + 2*qp) = hi;
                *(uint32_t*)(sp + 5 * PV_A + base + 2*qp) = lo;
                split2(p0 * dzv[2*qp], p1 * dzv[2*qp+1], hi, lo);
                *(uint32_t*)(sp + 6 * PV_A + base + 2*qp) = hi;
                *(uint32_t*)(sp + 7 * PV_A + base + 2*qp) = lo;
            }
        }
        // ---- phase 1b: v / ve tiles (vectorized 16B gather loads) ----
        {
            #pragma unroll
            for (int t = 0; t < 4; t++) {
                int u    = tid + (t << 8);
                int m    = u & 63;
                int rest = u >> 6;       // constant within a warp
                int dq   = rest & 3;
                int mat  = rest >> 2;
                int mg   = m0 + m;
                int row  = (mg < NN) ? mg : oidx[b * NM + mg - NN];
                const __nv_bfloat16* gsrc = (mat == 0) ? veh_g
                                          : (mat == 1) ? vel_g
                                          : (mat == 2) ? vh_g : vl_g;
                __nv_bfloat16* dst = (mat == 0) ? VEh
                                   : (mat == 1) ? VEl
                                   : (mat == 2) ? Vh : Vl;
                uint4 v = *(const uint4*)(gsrc + (size_t)(b * NN + row) * NE
                                          + h * ND + (dq << 3));
                __nv_bfloat16 tmp[8];
                *(uint4*)tmp = v;
                #pragma unroll
                for (int s = 0; s < 8; s++)
                    dst[((dq << 3) + s) * 72 + m] = tmp[s];
            }
        }
        __syncthreads();

        // ---- phase 2: MMAs ----
        #pragma unroll
        for (int o = 0; o < 2; o++) {
            const uint32_t Au = o ? A1u : A0u;
            const uint32_t Bu = o ? B1u : B0u;
            float (*acc)[4] = o ? acc1 : acc0;
            #pragma unroll
            for (int kk = 0; kk < 4; kk++) {
                const uint32_t kwb = kk << 5;
                uint32_t ah[4], al[4], bh[4][2], bl[4][2];
                ldsm4(ah[0], ah[1], ah[2], ah[3], Au + kwb);
                ldsm4(al[0], al[1], al[2], al[3], Au + PV_A * 2 + kwb);
                #pragma unroll
                for (int jp = 0; jp < 2; jp++) {
                    ldsm4(bh[2*jp][0], bh[2*jp][1], bh[2*jp+1][0], bh[2*jp+1][1],
                          Bu + jp * 2304 + kwb);
                    ldsm4(bl[2*jp][0], bl[2*jp][1], bl[2*jp+1][0], bl[2*jp+1][1],
                          Bu + PV_B * 2 + jp * 2304 + kwb);
                }
                #pragma unroll
                for (int j = 0; j < 4; j++) mma16816(acc[j], ah, bh[j]);
                #pragma unroll
                for (int j = 0; j < 4; j++) mma16816(acc[j], ah, bl[j]);
                #pragma unroll
                for (int j = 0; j < 4; j++) mma16816(acc[j], al, bh[j]);
            }
        }
    }

    // ---- epilogue ----
    const int r0g = n0 + rowblk + g;
    #pragma unroll
    for (int j = 0; j < 4; j++) {
        int col = h * ND + (j << 3) + (tig << 1);
        uint32_t hi, lo;
        if (pair == 0) {
            size_t ro0 = (size_t)(b * NN + r0g) * NE + col;
            size_t ro1 = (size_t)(b * NN + r0g + 8) * NE + col;
            split2(acc0[j][0], acc0[j][1], hi, lo);
            *(uint32_t*)(outh + ro0) = hi; *(uint32_t*)(outl + ro0) = lo;
            split2(acc0[j][2], acc0[j][3], hi, lo);
            *(uint32_t*)(outh + ro1) = hi; *(uint32_t*)(outl + ro1) = lo;
            size_t vo0 = VOFF + ((size_t)(b * NN + r0g) * 3 + 0) * NE + col;
            size_t vo1 = VOFF + ((size_t)(b * NN + r0g + 8) * 3 + 0) * NE + col;
            split2(acc1[j][0], acc1[j][1], hi, lo);
            *(uint32_t*)(outh + vo0) = hi; *(uint32_t*)(outl + vo0) = lo;
            split2(acc1[j][2], acc1[j][3], hi, lo);
            *(uint32_t*)(outh + vo1) = hi; *(uint32_t*)(outl + vo1) = lo;
        } else {
            size_t vo0 = VOFF + ((size_t)(b * NN + r0g) * 3 + 1) * NE + col;
            size_t vo1 = VOFF + ((size_t)(b * NN + r0g + 8) * 3 + 1) * NE + col;
            split2(acc0[j][0], acc0[j][1], hi, lo);
            *(uint32_t*)(outh + vo0) = hi; *(uint32_t*)(outl + vo0) = lo;
            split2(acc0[j][2], acc0[j][3], hi, lo);
            *(uint32_t*)(outh + vo1) = hi; *(uint32_t*)(outl + vo1) = lo;
            size_t wo0 = VOFF + ((size_t)(b * NN + r0g) * 3 + 2) * NE + col;
            size_t wo1 = VOFF + ((size_t)(b * NN + r0g + 8) * 3 + 2) * NE + col;
            split2(acc1[j][0], acc1[j][1], hi, lo);
            *(uint32_t*)(outh + wo0) = hi; *(uint32_t*)(outl + wo0) = lo;
            split2(acc1[j][2], acc1[j][3], hi, lo);
            *(uint32_t*)(outh + wo1) = hi; *(uint32_t*)(outl + wo1) = lo;
        }
    }
}

// ============================================================================
// launch
// ============================================================================
extern "C" void kernel_launch(void* const* d_in, const int* in_sizes, int n_in,
                              void* d_out, int out_size)
{
    const float* x    = (const float*)d_in[0];
    const float* pos  = (const float*)d_in[1];
    const float* epos = (const float*)d_in[2];
    const float* bias = (const float*)d_in[3];
    const unsigned char* pmask = (const unsigned char*)d_in[4];
    const unsigned char* emask = (const unsigned char*)d_in[5];
    const int*   oidx = (const int*)d_in[6];
    const float* Wq   = (const float*)d_in[7];
    const float* Wk   = (const float*)d_in[8];
    const float* Wv   = (const float*)d_in[9];
    const float* Wve  = (const float*)d_in[10];
    const float* Wo   = (const float*)d_in[11];
    const float* Woe  = (const float*)d_in[12];
    float* out = (float*)d_out;

    __nv_bfloat16 *ah, *al, *wh, *wl, *ph, *pl;
    float *dlt;
    cudaGetSymbolAddress((void**)&ah,  g_ah);
    cudaGetSymbolAddress((void**)&al,  g_al);
    cudaGetSymbolAddress((void**)&wh,  g_wh);
    cudaGetSymbolAddress((void**)&wl,  g_wl);
    cudaGetSymbolAddress((void**)&ph,  g_projh);
    cudaGetSymbolAddress((void**)&pl,  g_projl);
    cudaGetSymbolAddress((void**)&dlt, g_delta);

    cudaFuncSetAttribute(gemm_mma,   cudaFuncAttributeMaxDynamicSharedMemorySize, GSMEM_BYTES);
    cudaFuncSetAttribute(qk_softmax, cudaFuncAttributeMaxDynamicSharedMemorySize, QK_SMEM);
    cudaFuncSetAttribute(pv_mma,     cudaFuncAttributeMaxDynamicSharedMemorySize, PV_SMEM);

    const int WSZ = 1024 * 1024;

    // 1) converters + delta precompute
    cvt_split_x<<<2048, 256>>>(x, ah, al);
    cvt_split_w<<<dim3(1024, 6), 256>>>(Wq, Wk, Wv, Wve, Woe, Wo, wh, wl);
    delta_pre<<<6144, 256>>>(pos, epos, pmask, emask, dlt);

    // 2) projections -> bf16 hi/lo (mode 1)
    gemm_mma<<<dim3(8, 16, 4), 256, GSMEM_BYTES>>>(ah, al, wh, wl,
                                                   nullptr, nullptr, 1024,
                                                   nullptr, ph, pl, SCALING_F, 1);

    // 3) fused QK + softmax
    qk_softmax<<<dim3(8, 256), 256, QK_SMEM>>>(bias, oidx, pmask, emask,
                                               ph, pl, ph + PSZ, pl + PSZ);

    // 4) fused PV + vec
    pv_mma<<<dim3(4, 32, 8), 256, PV_SMEM>>>(dlt, oidx,
                                             ph + 2*PSZ, pl + 2*PSZ,
                                             ph + 3*PSZ, pl + 3*PSZ,
                                             ah, al);

    // 5) fused output GEMMs
    gemm_mma<<<dim3(8, 64, 1), 256, GSMEM_BYTES>>>(ah, al,
                                                   wh + 4*WSZ, wl + 4*WSZ,
                                                   wh + 5*WSZ, wl + 5*WSZ, 16,
                                                   out, nullptr, nullptr, 1.0f, 0);
}

// round 12
// speedup vs baseline: 1.3778x; 1.0123x over previous
#include <cuda_runtime.h>
#include <cuda_bf16.h>
#include <float.h>
#include <math.h>
#include <stdint.h>

// Problem constants
#define NB 8
#define NN 256
#define NM 512
#define NE 1024
#define NH 32
#define ND 32
#define NEXT 768   // N + M

#define SCALING_F 0.17677669529663687f  // 32^-0.5

// ---------------- device scratch ----------------
static __device__ float g_attn[(long long)NB*NH*NN*NEXT];   // probs (fp32)
static __device__ float g_delta[(long long)NB*NN*3*NEXT];   // masked delta [b,n,c,m]
static __device__ __nv_bfloat16 g_ah[8192LL*1024];
static __device__ __nv_bfloat16 g_al[8192LL*1024];
static __device__ __nv_bfloat16 g_wh[6LL*1024*1024];
static __device__ __nv_bfloat16 g_wl[6LL*1024*1024];
static __device__ __nv_bfloat16 g_projh[4LL*2048*1024];
static __device__ __nv_bfloat16 g_projl[4LL*2048*1024];
#define PSZ 2097152
#define VOFF 2097152

// ============================================================================
// helpers
// ============================================================================
__device__ __forceinline__ uint32_t smem_u32(const void* p) {
    uint32_t a;
    asm("{ .reg .u64 t; cvta.to.shared.u64 t, %1; cvt.u32.u64 %0, t; }"
        : "=r"(a) : "l"(p));
    return a;
}
#define CP_ASYNC16(sa, ga) \
    asm volatile("cp.async.cg.shared.global [%0], [%1], 16;\n" :: "r"(sa), "l"(ga))
#define CP_COMMIT() asm volatile("cp.async.commit_group;\n" ::: "memory")
#define CP_WAIT(n)  asm volatile("cp.async.wait_group %0;\n" :: "n"(n) : "memory")

__device__ __forceinline__ void mma16816(float* c, const uint32_t* a, const uint32_t* b) {
    asm volatile(
        "mma.sync.aligned.m16n8k16.row.col.f32.bf16.bf16.f32 "
        "{%0,%1,%2,%3}, {%4,%5,%6,%7}, {%8,%9}, {%0,%1,%2,%3};\n"
        : "+f"(c[0]), "+f"(c[1]), "+f"(c[2]), "+f"(c[3])
        : "r"(a[0]), "r"(a[1]), "r"(a[2]), "r"(a[3]), "r"(b[0]), "r"(b[1]));
}
__device__ __forceinline__ void ldsm4(uint32_t& r0, uint32_t& r1, uint32_t& r2,
                                      uint32_t& r3, uint32_t a) {
    asm volatile("ldmatrix.sync.aligned.m8n8.x4.shared.b16 {%0,%1,%2,%3}, [%4];"
                 : "=r"(r0), "=r"(r1), "=r"(r2), "=r"(r3) : "r"(a));
}
// fast split (bit-identical rn rounding)
__device__ __forceinline__ void split2(float a, float b, uint32_t& hi, uint32_t& lo) {
    asm("cvt.rn.bf16x2.f32 %0, %1, %2;" : "=r"(hi) : "f"(b), "f"(a));
    float ha = __uint_as_float(hi << 16);
    float hb = __uint_as_float(hi & 0xffff0000u);
    asm("cvt.rn.bf16x2.f32 %0, %1, %2;" : "=r"(lo) : "f"(b - hb), "f"(a - ha));
}
__device__ __forceinline__ float sqrt_approx(float x) {
    float r;
    asm("sqrt.approx.f32 %0, %1;" : "=f"(r) : "f"(x));
    return r;
}
__device__ __forceinline__ float rcp_approx(float x) {
    float r;
    asm("rcp.approx.f32 %0, %1;" : "=f"(r) : "f"(x));
    return r;
}

// ============================================================================
// converters
// ============================================================================
__global__ __launch_bounds__(256) void cvt_split_x(const float* __restrict__ src,
                                                   __nv_bfloat16* __restrict__ hi,
                                                   __nv_bfloat16* __restrict__ lo)
{
    int i = blockIdx.x * 256 + threadIdx.x;
    int r  = i >> 8;
    int e4 = (i & 255) << 2;
    int b = r >> 8, n = r & 255;
    float4 v = *(const float4*)(src + ((long long)n * NB + b) * NE + e4);
    uint32_t h0, l0, h1, l1;
    split2(v.x, v.y, h0, l0);
    split2(v.z, v.w, h1, l1);
    ((uint2*)hi)[i] = make_uint2(h0, h1);
    ((uint2*)lo)[i] = make_uint2(l0, l1);
}

__global__ __launch_bounds__(256) void cvt_split_w(const float* __restrict__ W0,
                                                   const float* __restrict__ W1,
                                                   const float* __restrict__ W2,
                                                   const float* __restrict__ W3,
                                                   const float* __restrict__ W4,
                                                   const float* __restrict__ W5,
                                                   __nv_bfloat16* __restrict__ hi,
                                                   __nv_bfloat16* __restrict__ lo)
{
    int w = blockIdx.y;
    const float* src = (w == 0) ? W0 : (w == 1) ? W1 : (w == 2) ? W2
                     : (w == 3) ? W3 : (w == 4) ? W4 : W5;
    int i = blockIdx.x * 256 + threadIdx.x;
    float4 v = ((const float4*)src)[i];
    uint32_t h0, l0, h1, l1;
    split2(v.x, v.y, h0, l0);
    split2(v.z, v.w, h1, l1);
    size_t o = ((size_t)w << 18) + i;
    ((uint2*)hi)[o] = make_uint2(h0, h1);
    ((uint2*)lo)[o] = make_uint2(l0, l1);
}

// ============================================================================
// Precompute masked delta [b,n,c,m]
// ============================================================================
__global__ __launch_bounds__(256) void delta_pre(const float* __restrict__ pos,
                                                 const float* __restrict__ epos,
                                                 const unsigned char* __restrict__ pmask,
                                                 const unsigned char* __restrict__ emask,
                                                 float* __restrict__ delta)
{
    int i = blockIdx.x * 256 + threadIdx.x;
    int m = i % NEXT;
    int n = (i / NEXT) % NN;
    int b = i / (NEXT * NN);

    float pxn = pos[(b * NN + n) * 3 + 0];
    float pyn = pos[(b * NN + n) * 3 + 1];
    float pzn = pos[(b * NN + n) * 3 + 2];
    bool  pn  = pmask[b * NN + n] != 0;

    float ax, ay, az; bool fm;
    if (m < NN) {
        const float* pp = pos + (b * NN + m) * 3;
        ax = pp[0]; ay = pp[1]; az = pp[2];
        fm = pmask[b * NN + m] != 0;
    } else {
        const float* pp = epos + (b * NM + m - NN) * 3;
        ax = pp[0]; ay = pp[1]; az = pp[2];
        fm = emask[b * NM + m - NN] != 0;
    }
    float dx = pxn - ax, dy = pyn - ay, dz = pzn - az;
    float dist = sqrt_approx(dx * dx + dy * dy + dz * dz);
    if (pn || fm) dist = 1e6f;
    float inv = rcp_approx(dist + 1.f);
    if (pn) inv = 0.f;

    size_t base = ((size_t)(b * NN + n) * 3) * NEXT + m;
    delta[base           ] = dx * inv;
    delta[base +     NEXT] = dy * inv;
    delta[base + 2 * NEXT] = dz * inv;
}

// ============================================================================
// Tensor-core split-precision GEMM, 64x128 CTA tile, 3 CTAs/SM.
//   A: rows (64 per CTA), B/W: cols (128 per CTA). K = 1024, chunk 32.
//   smem/stage: Ah(64x40) Al(64x40) Bh(128x40) Bl(128x40) = 15360 ele.
// ============================================================================
#define T64_A    2560          // 64*40
#define T64_B    5120          // 128*40
#define STG64    15360         // elements per stage
#define GSMEM_BYTES 61440      // 2 stages * 15360 * 2B

__global__ __launch_bounds__(256, 3) void gemm_mma(const __nv_bfloat16* __restrict__ Ah,
                                                   const __nv_bfloat16* __restrict__ Al,
                                                   const __nv_bfloat16* __restrict__ Bh,
                                                   const __nv_bfloat16* __restrict__ Bl,
                                                   const __nv_bfloat16* __restrict__ Bh2,
                                                   const __nv_bfloat16* __restrict__ Bl2,
                                                   int ysplit,
                                                   float* __restrict__ C,
                                                   __nv_bfloat16* __restrict__ Ch,
                                                   __nv_bfloat16* __restrict__ Cl,
                                                   float alpha0, int mode)
{
    extern __shared__ __nv_bfloat16 sm[];

    const int tid  = threadIdx.x;
    const int wid  = tid >> 5;
    const int lane = tid & 31;
    const int g    = lane >> 2;
    const int tig  = lane & 3;
    const int row0 = blockIdx.y << 6;      // 64-row tile
    const int col0 = blockIdx.x << 7;      // 128-col tile
    const int z    = blockIdx.z;
    if ((int)blockIdx.y >= ysplit) { Bh = Bh2; Bl = Bl2; }
    Bh += (size_t)z << 20;
    Bl += (size_t)z << 20;
    if (mode == 0) C += (size_t)z << 21;
    else { Ch += (size_t)z << 21; Cl += (size_t)z << 21; }
    const float alpha = (z == 0) ? alpha0 : 1.0f;
    const int wm = (wid & 1) << 5;         // 0 / 32
    const int wn = (wid >> 1) << 5;        // 0..96

    float acc[2][4][4];
    #pragma unroll
    for (int i = 0; i < 2; i++)
        #pragma unroll
        for (int j = 0; j < 4; j++)
            #pragma unroll
            for (int q = 0; q < 4; q++) acc[i][j][q] = 0.f;

    const uint32_t smbase = smem_u32(sm);
    const uint32_t a_off = ((wm + (lane & 7) + (((lane >> 3) & 1) << 3)) * 40
                            + ((lane >> 4) << 3)) * 2;
    const uint32_t b_off = ((wn + (lane & 7) + ((lane >> 4) << 3)) * 40
                            + (((lane >> 3) & 1) << 3)) * 2;

    // 384 rows x 4 16B-chunks = 1536 cp.async; 256 threads x 6
    #define LOAD_CHUNK(kc, s)                                                     \
    {                                                                             \
        _Pragma("unroll")                                                         \
        for (int t = 0; t < 6; t++) {                                             \
            int u  = tid + (t << 8);                                              \
            int r  = u >> 2;              /* 0..383 */                            \
            int cu = u & 3;                                                       \
            const __nv_bfloat16* gp;                                              \
            uint32_t selem;                                                       \
            if (r < 64)       { gp = Ah + (size_t)(row0 + r) * 1024;              \
                                selem = r * 40; }                                 \
            else if (r < 128) { gp = Al + (size_t)(row0 + r - 64) * 1024;         \
                                selem = T64_A + (r - 64) * 40; }                  \
            else if (r < 256) { gp = Bh + (size_t)(col0 + r - 128) * 1024;        \
                                selem = 2 * T64_A + (r - 128) * 40; }             \
            else              { gp = Bl + (size_t)(col0 + r - 256) * 1024;        \
                                selem = 2 * T64_A + T64_B + (r - 256) * 40; }     \
            gp += (kc) * 32 + cu * 8;                                             \
            uint32_t sa = smbase + ((s) * STG64 + selem + cu * 8) * 2;            \
            CP_ASYNC16(sa, gp);                                                   \
        }                                                                         \
    }

    LOAD_CHUNK(0, 0);
    CP_COMMIT();

    for (int kc = 0; kc < 32; kc++) {
        CP_WAIT(0);
        __syncthreads();
        if (kc + 1 < 32) {
            LOAD_CHUNK(kc + 1, (kc + 1) & 1);
            CP_COMMIT();
        }

        const uint32_t so2 = (kc & 1) * (STG64 * 2);
        const uint32_t abase = smbase + so2 + a_off;
        const uint32_t bbase = smbase + so2 + 2 * T64_A * 2 + b_off;

        #pragma unroll
        for (int kk = 0; kk < 2; kk++) {
            const uint32_t kwb = kk << 5;
            uint32_t ah[2][4], al[2][4], bh[4][2], bl[4][2];
            #pragma unroll
            for (int i = 0; i < 2; i++) {
                ldsm4(ah[i][0], ah[i][1], ah[i][2], ah[i][3],
                      abase + i * 1280 + kwb);
                ldsm4(al[i][0], al[i][1], al[i][2], al[i][3],
                      abase + T64_A * 2 + i * 1280 + kwb);
            }
            #pragma unroll
            for (int jp = 0; jp < 2; jp++) {
                ldsm4(bh[2*jp][0], bh[2*jp][1], bh[2*jp+1][0], bh[2*jp+1][1],
                      bbase + jp * 1280 + kwb);
                ldsm4(bl[2*jp][0], bl[2*jp][1], bl[2*jp+1][0], bl[2*jp+1][1],
                      bbase + T64_B * 2 + jp * 1280 + kwb);
            }
            #pragma unroll
            for (int i = 0; i < 2; i++)
                #pragma unroll
                for (int j = 0; j < 4; j++)
                    mma16816(acc[i][j], ah[i], bh[j]);
            #pragma unroll
            for (int i = 0; i < 2; i++)
                #pragma unroll
                for (int j = 0; j < 4; j++)
                    mma16816(acc[i][j], ah[i], bl[j]);
            #pragma unroll
            for (int i = 0; i < 2; i++)
                #pragma unroll
                for (int j = 0; j < 4; j++)
                    mma16816(acc[i][j], al[i], bh[j]);
        }
    }

    #pragma unroll
    for (int i = 0; i < 2; i++) {
        int row = row0 + wm + (i << 4) + g;
        #pragma unroll
        for (int j = 0; j < 4; j++) {
            int col = col0 + wn + (j << 3) + (tig << 1);
            float v0 = alpha * acc[i][j][0];
            float v1 = alpha * acc[i][j][1];
            float v2 = alpha * acc[i][j][2];
            float v3 = alpha * acc[i][j][3];
            if (mode == 0) {
                *(float2*)(C + (size_t)row * 1024 + col)       = make_float2(v0, v1);
                *(float2*)(C + (size_t)(row + 8) * 1024 + col) = make_float2(v2, v3);
            } else {
                uint32_t h0, l0, h1, l1;
                split2(v0, v1, h0, l0);
                split2(v2, v3, h1, l1);
                *(uint32_t*)(Ch + (size_t)row * 1024 + col)       = h0;
                *(uint32_t*)(Cl + (size_t)row * 1024 + col)       = l0;
                *(uint32_t*)(Ch + (size_t)(row + 8) * 1024 + col) = h1;
                *(uint32_t*)(Cl + (size_t)(row + 8) * 1024 + col) = l1;
            }
        }
    }
}

// ============================================================================
// Fused QK^T + bias + mask + softmax (32-row tile, 2 CTA/SM, __expf)
// ============================================================================
#define LSTRIDE 772
#define QK_SMEM 114176

__global__ __launch_bounds__(256, 2) void qk_softmax(const float* __restrict__ bias,
                                                  const int*   __restrict__ oidx,
                                                  const unsigned char* __restrict__ pmask,
                                                  const unsigned char* __restrict__ emask,
                                                  const __nv_bfloat16* __restrict__ qh_g,
                                                  const __nv_bfloat16* __restrict__ ql_g,
                                                  const __nv_bfloat16* __restrict__ kh_g,
                                                  const __nv_bfloat16* __restrict__ kl_g)
{
    extern __shared__ char sraw[];
    __nv_bfloat16* sqh = (__nv_bfloat16*)sraw;
    __nv_bfloat16* sql = sqh + 1280;
    __nv_bfloat16* skh = sqh + 2560;
    __nv_bfloat16* skl = sqh + 5120;
    float* logits = (float*)(sraw + 15360);

    const int tid  = threadIdx.x;
    const int wid  = tid >> 5;
    const int lane = tid & 31;
    const int g    = lane >> 2;
    const int tig  = lane & 3;
    const int bh   = blockIdx.y;
    const int b    = bh >> 5;
    const int h    = bh & 31;
    const int n0   = blockIdx.x << 5;

    if (tid < 128) {
        int r = tid >> 2, c = (tid & 3) << 3;
        size_t off = (size_t)(b * NN + n0 + r) * NE + h * ND + c;
        *(uint4*)(sqh + r * 40 + c) = *(const uint4*)(qh_g + off);
        *(uint4*)(sql + r * 40 + c) = *(const uint4*)(ql_g + off);
    }

    const int wn = (wid & 1) << 4;
    const int wm = (wid >> 1) << 4;

    for (int m0 = 0; m0 < NEXT; m0 += 64) {
        __syncthreads();
        {
            int r = tid >> 2, c = (tid & 3) << 3;
            int m = m0 + r;
            int row = (m < NN) ? m : oidx[b * NM + m - NN];
            size_t off = (size_t)(b * NN + row) * NE + h * ND + c;
            *(uint4*)(skh + r * 40 + c) = *(const uint4*)(kh_g + off);
            *(uint4*)(skl + r * 40 + c) = *(const uint4*)(kl_g + off);
        }
        __syncthreads();

        float acc[2][4];
        #pragma unroll
        for (int j = 0; j < 2; j++)
            #pragma unroll
            for (int q = 0; q < 4; q++) acc[j][q] = 0.f;

        #pragma unroll
        for (int kk = 0; kk < 2; kk++) {
            const int kw = kk << 3;
            uint32_t a_h[4], a_l[4], bhf[2][2], blf[2][2];
            {
                int rA = wn + g;
                a_h[0] = *(const uint32_t*)(sqh + (rA    ) * 40 + ((kw + tig    ) << 1));
                a_h[1] = *(const uint32_t*)(sqh + (rA + 8) * 40 + ((kw + tig    ) << 1));
                a_h[2] = *(const uint32_t*)(sqh + (rA    ) * 40 + ((kw + tig + 4) << 1));
                a_h[3] = *(const uint32_t*)(sqh + (rA + 8) * 40 + ((kw + tig + 4) << 1));
                a_l[0] = *(const uint32_t*)(sql + (rA    ) * 40 + ((kw + tig    ) << 1));
                a_l[1] = *(const uint32_t*)(sql + (rA + 8) * 40 + ((kw + tig    ) << 1));
                a_l[2] = *(const uint32_t*)(sql + (rA    ) * 40 + ((kw + tig + 4) << 1));
                a_l[3] = *(const uint32_t*)(sql + (rA + 8) * 40 + ((kw + tig + 4) << 1));
            }
            #pragma unroll
            for (int j = 0; j < 2; j++) {
                int rB = wm + (j << 3) + g;
                bhf[j][0] = *(const uint32_t*)(skh + rB * 40 + ((kw + tig    ) << 1));
                bhf[j][1] = *(const uint32_t*)(skh + rB * 40 + ((kw + tig + 4) << 1));
                blf[j][0] = *(const uint32_t*)(skl + rB * 40 + ((kw + tig    ) << 1));
                blf[j][1] = *(const uint32_t*)(skl + rB * 40 + ((kw + tig + 4) << 1));
            }
            #pragma unroll
            for (int j = 0; j < 2; j++) mma16816(acc[j], a_h, bhf[j]);
            #pragma unroll
            for (int j = 0; j < 2; j++) mma16816(acc[j], a_h, blf[j]);
            #pragma unroll
            for (int j = 0; j < 2; j++) mma16816(acc[j], a_l, bhf[j]);
        }

        #pragma unroll
        for (int j = 0; j < 2; j++) {
            int col = m0 + wm + (j << 3) + (tig << 1);
            int row = wn + g;
            *(float2*)&logits[row * LSTRIDE + col]       = make_float2(acc[j][0], acc[j][1]);
            *(float2*)&logits[(row + 8) * LSTRIDE + col] = make_float2(acc[j][2], acc[j][3]);
        }
    }
    __syncthreads();

    for (int rr = wid; rr < 32; rr += 8) {
        int n = n0 + rr;
        bool pn = pmask[b * NN + n] != 0;
        const float* lrow = logits + rr * LSTRIDE;
        long long goff = (((long long)(b * NH + h)) * NN + n) * NEXT;

        float val[24];
        float mx = -FLT_MAX;
        #pragma unroll
        for (int t = 0; t < 24; t++) {
            int m = lane + (t << 5);
            bool fm = (m < NN) ? (pmask[b * NN + m] != 0)
                               : (emask[b * NM + m - NN] != 0);
            float v = lrow[m] + bias[goff + m];
            if (pn || fm) v = -FLT_MAX;
            val[t] = v;
            mx = fmaxf(mx, v);
        }
        #pragma unroll
        for (int o = 16; o > 0; o >>= 1)
            mx = fmaxf(mx, __shfl_xor_sync(0xffffffffu, mx, o));
        float s = 0.f;
        #pragma unroll
        for (int t = 0; t < 24; t++) {
            val[t] = __expf(val[t] - mx);
            s += val[t];
        }
        #pragma unroll
        for (int o = 16; o > 0; o >>= 1)
            s += __shfl_xor_sync(0xffffffffu, s, o);
        float inv = 1.f / s;
        #pragma unroll
        for (int t = 0; t < 24; t++)
            g_attn[goff + lane + (t << 5)] = val[t] * inv;
    }
}

// ============================================================================
// Fused PV + vec (delta precomputed, vectorized gather, fast split2)
// ============================================================================
#define PV_A    4608
#define PV_VB   36864
#define PV_B    2304
#define PV_SMEM 92160

__global__ __launch_bounds__(256, 2) void pv_mma(const float* __restrict__ delta,
                                                 const int*   __restrict__ oidx,
                                                 const __nv_bfloat16* __restrict__ vh_g,
                                                 const __nv_bfloat16* __restrict__ vl_g,
                                                 const __nv_bfloat16* __restrict__ veh_g,
                                                 const __nv_bfloat16* __restrict__ vel_g,
                                                 __nv_bfloat16* __restrict__ outh,
                                                 __nv_bfloat16* __restrict__ outl)
{
    extern __shared__ __nv_bfloat16 sp[];

    const int tid  = threadIdx.x;
    const int wid  = tid >> 5;
    const int lane = tid & 31;
    const int g    = lane >> 2;
    const int tig  = lane & 3;
    const int b    = blockIdx.z;
    const int h    = blockIdx.y;
    const int n0   = blockIdx.x << 6;

    const int rowblk = (wid & 3) << 4;
    const int pair   = wid >> 2;

    __nv_bfloat16* VEh = sp + PV_VB;
    __nv_bfloat16* VEl = VEh + PV_B;
    __nv_bfloat16* Vh  = VEh + 2 * PV_B;
    __nv_bfloat16* Vl  = VEh + 3 * PV_B;

    const uint32_t spb = smem_u32(sp);
    const uint32_t a_offp = ((rowblk + (lane & 7) + (((lane >> 3) & 1) << 3)) * 72
                             + ((lane >> 4) << 3)) * 2;
    const uint32_t b_offp = (((lane & 7) + ((lane >> 4) << 3)) * 72
                             + (((lane >> 3) & 1) << 3)) * 2;
    const uint32_t A0u = spb + (((pair == 0) ? 0 : 4) * PV_A) * 2 + a_offp;
    const uint32_t A1u = spb + (((pair == 0) ? 2 : 6) * PV_A) * 2 + a_offp;
    const uint32_t Bvb = spb + PV_VB * 2;
    const uint32_t B0u = ((pair == 0) ? Bvb : Bvb + 2 * PV_B * 2) + b_offp;
    const uint32_t B1u = Bvb + 2 * PV_B * 2 + b_offp;

    float acc0[4][4], acc1[4][4];
    #pragma unroll
    for (int j = 0; j < 4; j++)
        #pragma unroll
        for (int q = 0; q < 4; q++) { acc0[j][q] = 0.f; acc1[j][q] = 0.f; }

    const int p_n  = tid >> 2;
    const int p_mb = (tid & 3) << 4;
    const size_t drow = ((size_t)(b * NN + n0 + p_n) * 3) * NEXT;

    for (int m0 = 0; m0 < NEXT; m0 += 64) {
        __syncthreads();
        // ---- phase 1a ----
        {
            const float* prow = g_attn +
                (((long long)(b * NH + h)) * NN + n0 + p_n) * NEXT + m0 + p_mb;
            float P[16], dxv[16], dyv[16], dzv[16];
            #pragma unroll
            for (int q4 = 0; q4 < 4; q4++) {
                *(float4*)(P   + q4*4) = *(const float4*)(prow + q4*4);
                *(float4*)(dxv + q4*4) = *(const float4*)(delta + drow            + m0 + p_mb + q4*4);
                *(float4*)(dyv + q4*4) = *(const float4*)(delta + drow +     NEXT + m0 + p_mb + q4*4);
                *(float4*)(dzv + q4*4) = *(const float4*)(delta + drow + 2 * NEXT + m0 + p_mb + q4*4);
            }
            int base = p_n * 72 + p_mb;
            #pragma unroll
            for (int qp = 0; qp < 8; qp++) {
                float p0 = P[2*qp], p1 = P[2*qp+1];
                uint32_t hi, lo;
                split2(p0, p1, hi, lo);
                *(uint32_t*)(sp + 0 * PV_A + base + 2*qp) = hi;
                *(uint32_t*)(sp + 1 * PV_A + base + 2*qp) = lo;
                split2(p0 * dxv[2*qp], p1 * dxv[2*qp+1], hi, lo);
                *(uint32_t*)(sp + 2 * PV_A + base + 2*qp) = hi;
                *(uint32_t*)(sp + 3 * PV_A + base + 2*qp) = lo;
                split2(p0 * dyv[2*qp], p1 * dyv[2*qp+1], hi, lo);
                *(uint32_t*)(sp + 4 * PV_A + base + 2*qp) = hi;
                *(uint32_t*)(sp + 5 * PV_A + base + 2*qp) = lo;
                split2(p0 * dzv[2*qp], p1 * dzv[2*qp+1], hi, lo);
                *(uint32_t*)(sp + 6 * PV_A + base + 2*qp) = hi;
                *(uint32_t*)(sp + 7 * PV_A + base + 2*qp) = lo;
            }
        }
        // ---- phase 1b ----
        {
            #pragma unroll
            for (int t = 0; t < 4; t++) {
                int u    = tid + (t << 8);
                int m    = u & 63;
                int rest = u >> 6;
                int dq   = rest & 3;
                int mat  = rest >> 2;
                int mg   = m0 + m;
                int row  = (mg < NN) ? mg : oidx[b * NM + mg - NN];
                const __nv_bfloat16* gsrc = (mat == 0) ? veh_g
                                          : (mat == 1) ? vel_g
                                          : (mat == 2) ? vh_g : vl_g;
                __nv_bfloat16* dst = (mat == 0) ? VEh
                                   : (mat == 1) ? VEl
                                   : (mat == 2) ? Vh : Vl;
                uint4 v = *(const uint4*)(gsrc + (size_t)(b * NN + row) * NE
                                          + h * ND + (dq << 3));
                __nv_bfloat16 tmp[8];
                *(uint4*)tmp = v;
                #pragma unroll
                for (int s = 0; s < 8; s++)
                    dst[((dq << 3) + s) * 72 + m] = tmp[s];
            }
        }
        __syncthreads();

        // ---- phase 2 ----
        #pragma unroll
        for (int o = 0; o < 2; o++) {
            const uint32_t Au = o ? A1u : A0u;
            const uint32_t Bu = o ? B1u : B0u;
            float (*acc)[4] = o ? acc1 : acc0;
            #pragma unroll
            for (int kk = 0; kk < 4; kk++) {
                const uint32_t kwb = kk << 5;
                uint32_t ah[4], al[4], bh[4][2], bl[4][2];
                ldsm4(ah[0], ah[1], ah[2], ah[3], Au + kwb);
                ldsm4(al[0], al[1], al[2], al[3], Au + PV_A * 2 + kwb);
                #pragma unroll
                for (int jp = 0; jp < 2; jp++) {
                    ldsm4(bh[2*jp][0], bh[2*jp][1], bh[2*jp+1][0], bh[2*jp+1][1],
                          Bu + jp * 2304 + kwb);
                    ldsm4(bl[2*jp][0], bl[2*jp][1], bl[2*jp+1][0], bl[2*jp+1][1],
                          Bu + PV_B * 2 + jp * 2304 + kwb);
                }
                #pragma unroll
                for (int j = 0; j < 4; j++) mma16816(acc[j], ah, bh[j]);
                #pragma unroll
                for (int j = 0; j < 4; j++) mma16816(acc[j], ah, bl[j]);
                #pragma unroll
                for (int j = 0; j < 4; j++) mma16816(acc[j], al, bh[j]);
            }
        }
    }

    // ---- epilogue ----
    const int r0g = n0 + rowblk + g;
    #pragma unroll
    for (int j = 0; j < 4; j++) {
        int col = h * ND + (j << 3) + (tig << 1);
        uint32_t hi, lo;
        if (pair == 0) {
            size_t ro0 = (size_t)(b * NN + r0g) * NE + col;
            size_t ro1 = (size_t)(b * NN + r0g + 8) * NE + col;
            split2(acc0[j][0], acc0[j][1], hi, lo);
            *(uint32_t*)(outh + ro0) = hi; *(uint32_t*)(outl + ro0) = lo;
            split2(acc0[j][2], acc0[j][3], hi, lo);
            *(uint32_t*)(outh + ro1) = hi; *(uint32_t*)(outl + ro1) = lo;
            size_t vo0 = VOFF + ((size_t)(b * NN + r0g) * 3 + 0) * NE + col;
            size_t vo1 = VOFF + ((size_t)(b * NN + r0g + 8) * 3 + 0) * NE + col;
            split2(acc1[j][0], acc1[j][1], hi, lo);
            *(uint32_t*)(outh + vo0) = hi; *(uint32_t*)(outl + vo0) = lo;
            split2(acc1[j][2], acc1[j][3], hi, lo);
            *(uint32_t*)(outh + vo1) = hi; *(uint32_t*)(outl + vo1) = lo;
        } else {
            size_t vo0 = VOFF + ((size_t)(b * NN + r0g) * 3 + 1) * NE + col;
            size_t vo1 = VOFF + ((size_t)(b * NN + r0g + 8) * 3 + 1) * NE + col;
            split2(acc0[j][0], acc0[j][1], hi, lo);
            *(uint32_t*)(outh + vo0) = hi; *(uint32_t*)(outl + vo0) = lo;
            split2(acc0[j][2], acc0[j][3], hi, lo);
            *(uint32_t*)(outh + vo1) = hi; *(uint32_t*)(outl + vo1) = lo;
            size_t wo0 = VOFF + ((size_t)(b * NN + r0g) * 3 + 2) * NE + col;
            size_t wo1 = VOFF + ((size_t)(b * NN + r0g + 8) * 3 + 2) * NE + col;
            split2(acc1[j][0], acc1[j][1], hi, lo);
            *(uint32_t*)(outh + wo0) = hi; *(uint32_t*)(outl + wo0) = lo;
            split2(acc1[j][2], acc1[j][3], hi, lo);
            *(uint32_t*)(outh + wo1) = hi; *(uint32_t*)(outl + wo1) = lo;
        }
    }
}

// ============================================================================
// launch
// ============================================================================
extern "C" void kernel_launch(void* const* d_in, const int* in_sizes, int n_in,
                              void* d_out, int out_size)
{
    const float* x    = (const float*)d_in[0];
    const float* pos  = (const float*)d_in[1];
    const float* epos = (const float*)d_in[2];
    const float* bias = (const float*)d_in[3];
    const unsigned char* pmask = (const unsigned char*)d_in[4];
    const unsigned char* emask = (const unsigned char*)d_in[5];
    const int*   oidx = (const int*)d_in[6];
    const float* Wq   = (const float*)d_in[7];
    const float* Wk   = (const float*)d_in[8];
    const float* Wv   = (const float*)d_in[9];
    const float* Wve  = (const float*)d_in[10];
    const float* Wo   = (const float*)d_in[11];
    const float* Woe  = (const float*)d_in[12];
    float* out = (float*)d_out;

    __nv_bfloat16 *ah, *al, *wh, *wl, *ph, *pl;
    float *dlt;
    cudaGetSymbolAddress((void**)&ah,  g_ah);
    cudaGetSymbolAddress((void**)&al,  g_al);
    cudaGetSymbolAddress((void**)&wh,  g_wh);
    cudaGetSymbolAddress((void**)&wl,  g_wl);
    cudaGetSymbolAddress((void**)&ph,  g_projh);
    cudaGetSymbolAddress((void**)&pl,  g_projl);
    cudaGetSymbolAddress((void**)&dlt, g_delta);

    cudaFuncSetAttribute(gemm_mma,   cudaFuncAttributeMaxDynamicSharedMemorySize, GSMEM_BYTES);
    cudaFuncSetAttribute(qk_softmax, cudaFuncAttributeMaxDynamicSharedMemorySize, QK_SMEM);
    cudaFuncSetAttribute(pv_mma,     cudaFuncAttributeMaxDynamicSharedMemorySize, PV_SMEM);

    const int WSZ = 1024 * 1024;

    // 1) converters + delta precompute
    cvt_split_x<<<2048, 256>>>(x, ah, al);
    cvt_split_w<<<dim3(1024, 6), 256>>>(Wq, Wk, Wv, Wve, Woe, Wo, wh, wl);
    delta_pre<<<6144, 256>>>(pos, epos, pmask, emask, dlt);

    // 2) projections -> bf16 hi/lo (mode 1), 64-row tiles
    gemm_mma<<<dim3(8, 32, 4), 256, GSMEM_BYTES>>>(ah, al, wh, wl,
                                                   nullptr, nullptr, 1024,
                                                   nullptr, ph, pl, SCALING_F, 1);

    // 3) fused QK + softmax
    qk_softmax<<<dim3(8, 256), 256, QK_SMEM>>>(bias, oidx, pmask, emask,
                                               ph, pl, ph + PSZ, pl + PSZ);

    // 4) fused PV + vec
    pv_mma<<<dim3(4, 32, 8), 256, PV_SMEM>>>(dlt, oidx,
                                             ph + 2*PSZ, pl + 2*PSZ,
                                             ph + 3*PSZ, pl + 3*PSZ,
                                             ah, al);

    // 5) fused output GEMMs: rows [0,2048)=xo @ Woe^T (y<32), rows [2048,8192)=vec @ Wo^T
    gemm_mma<<<dim3(8, 128, 1), 256, GSMEM_BYTES>>>(ah, al,
                                                    wh + 4*WSZ, wl + 4*WSZ,
                                                    wh + 5*WSZ, wl + 5*WSZ, 32,
                                                    out, nullptr, nullptr, 1.0f, 0);
}